// round 10
// baseline (speedup 1.0000x reference)
#include <cuda_runtime.h>
#include <cuda_fp16.h>
#include <cstdint>

#define NHIT 30000
#define NEDGE 90000
#define NSP 30000
#define HD 128
#define NCLASS 5
#define PSTRIDE (NHIT * HD)

// ---------------- device scratch ----------------
__device__ float g_h[2][3][NHIT * HD];          // fp32 state (residual path)
__device__ __half g_h16[2][3][NHIT * HD];       // fp16 shadow of h (GEMM A operand)
__device__ __half g_A[3][NHIT * HD];
__device__ __half g_B[3][NHIT * HD];
__device__ __half g_sp[NSP * HD];
__device__ float g_wcomb[HD * HD];              // W_msg2 @ W_upd_bottom
__device__ float g_b2c[HD];                     // b_msg2 @ W_upd_bottom

// prepped weights: 7 chunks x {hi,lo} x 2 k-stages x (128n x 64k fp16, swizzled)
__device__ uint4 g_wbuf[7][2][2][1024];

__device__ int g_deg[3][NHIT];
__device__ int g_cf[3][NSP];
__device__ int g_cb[3][NHIT];
__device__ int g_offE[3][NHIT + 1];
__device__ int g_offF[3][NSP + 1];
__device__ int g_offB[3][NHIT + 1];
__device__ int g_csrE[3][NEDGE];
__device__ int g_csrF[3][NSP];
__device__ int g_csrB[3][NSP];
__device__ int g_curE[3][NHIT];
__device__ int g_curF[3][NSP];
__device__ int g_curB[3][NHIT];

enum { EPI_RELU = 1, EPI_RESRELU = 2, EPI_RESRELU_DEG = 4 };
enum { GM_NONE = 0, GM_MR = 1, GM_BACK = 2, GM_SPSUM = 3 };

// ---------------- helpers ----------------
__device__ __forceinline__ uint32_t s2u(const void* p) {
    return (uint32_t)__cvta_generic_to_shared(p);
}
__device__ __forceinline__ uint32_t pack2h(float a, float b) {
    __half2 t = __floats2half2_rn(a, b);
    return *reinterpret_cast<uint32_t*>(&t);
}
__device__ __forceinline__ float lopart(float v) {
    return v - __half2float(__float2half(v));
}
__device__ __forceinline__ uint32_t swz(int row, int k) {
    return (uint32_t)(row * 128 + ((((k >> 3) ^ row) & 7) << 4) + (k & 7) * 2);
}
__device__ __forceinline__ void ldsm4(uint32_t* r, uint32_t addr) {
    asm volatile("ldmatrix.sync.aligned.m8n8.x4.shared.b16 {%0,%1,%2,%3}, [%4];"
                 : "=r"(r[0]), "=r"(r[1]), "=r"(r[2]), "=r"(r[3]) : "r"(addr));
}
__device__ __forceinline__ void mma16816(float* c, const uint32_t* a, uint32_t b0, uint32_t b1) {
    asm volatile(
        "mma.sync.aligned.m16n8k16.row.col.f32.f16.f16.f32 "
        "{%0,%1,%2,%3}, {%4,%5,%6,%7}, {%8,%9}, {%0,%1,%2,%3};"
        : "+f"(c[0]), "+f"(c[1]), "+f"(c[2]), "+f"(c[3])
        : "r"(a[0]), "r"(a[1]), "r"(a[2]), "r"(a[3]), "r"(b0), "r"(b1));
}
__device__ __forceinline__ void cpa8(uint32_t dst, const void* src) {
    asm volatile("cp.async.ca.shared.global [%0], [%1], 8;" :: "r"(dst), "l"(src));
}
__device__ __forceinline__ void cpa16(uint32_t dst, const void* src) {
    asm volatile("cp.async.cg.shared.global [%0], [%1], 16;" :: "r"(dst), "l"(src));
}
#define CP_COMMIT() asm volatile("cp.async.commit_group;")
#define CP_WAIT1()  asm volatile("cp.async.wait_group 1;")
#define CP_WAIT0()  asm volatile("cp.async.wait_group 0;")

// gemm_mma: 2 pipeline buffers x [A 16K | BHI 16K | BLO 16K]
#define PB_A 0
#define PB_BHI 16384
#define PB_BLO 32768
#define PB_SZ 49152
#define SM_TOTAL 98304
// gemm_dual: A (both halves) 32K + 2 B-buffers x [BHI 16K | BLO 16K]
#define DU_A 0
#define DU_B 32768
#define DU_BSZ 32768
#define DU_TOTAL 98304

// ---------------- weight combine ----------------
__global__ void combine_w(const float* __restrict__ W2, const float* __restrict__ Wub,
                          const float* __restrict__ b2) {
    int n = threadIdx.x;
    int k = blockIdx.x;
    if (k < 128) {
        float s = 0.f;
        #pragma unroll 8
        for (int j = 0; j < 128; j++) s = fmaf(W2[k * 128 + j], Wub[j * 128 + n], s);
        g_wcomb[k * 128 + n] = s;
    } else {
        float s = 0.f;
        #pragma unroll 8
        for (int j = 0; j < 128; j++) s = fmaf(b2[j], Wub[j * 128 + n], s);
        g_b2c[n] = s;
    }
}

// ---------------- weight prep ----------------
__global__ void prep_w(const float* w0, const float* w1, const float* w2,
                       const float* w3, const float* w4, const float* w5,
                       const float* w6) {
    int id = blockIdx.x * blockDim.x + threadIdx.x;
    if (id >= 7 * 8192) return;
    int c = id >> 13;
    int rem = id & 8191;
    int s = rem >> 12;
    int rem2 = rem & 4095;
    int n = rem2 >> 5;
    int kp = (rem2 & 31) * 2;
    const float* Wc = (c == 0) ? w0 : (c == 1) ? w1 : (c == 2) ? w2 : (c == 3) ? w3
                    : (c == 4) ? w4 : (c == 5) ? w5 : w6;
    float v0 = Wc[(s * 64 + kp) * 128 + n];
    float v1 = Wc[(s * 64 + kp + 1) * 128 + n];
    uint32_t o = swz(n, kp);
    *reinterpret_cast<uint32_t*>((char*)&g_wbuf[c][0][s][0] + o) = pack2h(v0, v1);
    *reinterpret_cast<uint32_t*>((char*)&g_wbuf[c][1][s][0] + o) = pack2h(lopart(v0), lopart(v1));
}

// ---------------- HMMA 2-pass GEMM with fused gather staging ----------------
__global__ __launch_bounds__(256, 2) void gemm_mma(
    const __half* __restrict__ A0, const __half* __restrict__ A1,
    int sA, int wc0, int nchunks, int gm0, int gm1,
    const float* __restrict__ gbias,
    const float* __restrict__ bias, const float* __restrict__ bias2,
    const int* __restrict__ mask, int sMask,
    const float* __restrict__ resid,
    float* __restrict__ outf, __half* __restrict__ outh, int M, int epi)
{
    extern __shared__ char smem[];
    uint32_t sb = s2u(smem);
    int tid = threadIdx.x;
    int wid = tid >> 5, lane = tid & 31;
    int mwarp = wid & 3, nwarp = wid >> 2;
    int row0 = blockIdx.x * 128;
    int pl = blockIdx.y;
    const __half* A0p = A0 ? (A0 + (size_t)pl * sA) : nullptr;
    const __half* A1p = A1 ? (A1 + (size_t)pl * sA) : nullptr;
    const float* residp = resid ? (resid + (size_t)pl * sA) : nullptr;
    const int* maskp = mask ? (mask + (size_t)pl * sMask) : nullptr;

    float C[2][8][4];
    #pragma unroll
    for (int mt = 0; mt < 2; mt++)
        #pragma unroll
        for (int nt = 0; nt < 8; nt++)
            #pragma unroll
            for (int q = 0; q < 4; q++) C[mt][nt][q] = 0.f;

    int a_row_in16 = (lane & 7) + ((lane >> 3) & 1) * 8;
    int a_kb = (lane >> 4) & 1;
    int b_row_in16 = (lane & 7) + ((lane >> 4) & 1) * 8;
    int b_kb = (lane >> 3) & 1;

    int nst = nchunks * 2;

    auto prefetch = [&](int s) {
        int ch = s >> 1, kh = s & 1;
        int gm = ch ? gm1 : gm0;
        uint32_t bb = sb + (uint32_t)((s & 1) * PB_SZ);
        char* bufp = smem + (size_t)((s & 1) * PB_SZ);
        if (gm == GM_NONE) {
            const __half* src = ch ? A1p : A0p;
            #pragma unroll
            for (int l = 0; l < 8; l++) {
                int i = l * 256 + tid;
                int r = i >> 4, c4 = (i & 15) * 4;
                int row = row0 + r; if (row >= M) row = M - 1;
                cpa8(bb + PB_A + swz(r, c4), &src[(size_t)row * 128 + kh * 64 + c4]);
            }
        } else {
            #pragma unroll 2
            for (int l = 0; l < 8; l++) {
                int i = l * 256 + tid;
                int r = i >> 4, c4 = (i & 15) * 4;
                int row = row0 + r; if (row >= M) row = M - 1;
                int kc = kh * 64 + c4;
                float4 acc = make_float4(0.f, 0.f, 0.f, 0.f);
                if (gm == GM_MR) {
                    uint2 av = *reinterpret_cast<const uint2*>(&g_A[pl][(size_t)row * 128 + kc]);
                    float2 a01 = __half22float2(*reinterpret_cast<__half2*>(&av.x));
                    float2 a23 = __half22float2(*reinterpret_cast<__half2*>(&av.y));
                    float4 bv4 = *reinterpret_cast<const float4*>(&gbias[kc]);
                    int st = g_offE[pl][row], en = g_offE[pl][row + 1];
                    for (int e = st; e < en; e++) {
                        int srcn = g_csrE[pl][e];
                        uint2 bv = *reinterpret_cast<const uint2*>(&g_B[pl][(size_t)srcn * 128 + kc]);
                        float2 b01 = __half22float2(*reinterpret_cast<__half2*>(&bv.x));
                        float2 b23 = __half22float2(*reinterpret_cast<__half2*>(&bv.y));
                        acc.x += fmaxf(a01.x + b01.x + bv4.x, 0.f);
                        acc.y += fmaxf(a01.y + b01.y + bv4.y, 0.f);
                        acc.z += fmaxf(a23.x + b23.x + bv4.z, 0.f);
                        acc.w += fmaxf(a23.y + b23.y + bv4.w, 0.f);
                    }
                    float inv = (en > st) ? 1.f / (float)(en - st) : 0.f;
                    acc.x *= inv; acc.y *= inv; acc.z *= inv; acc.w *= inv;
                } else if (gm == GM_BACK) {
                    int st = g_offB[pl][row], en = g_offB[pl][row + 1];
                    for (int e = st; e < en; e++) {
                        int spi = g_csrB[pl][e];
                        uint2 v = *reinterpret_cast<const uint2*>(&g_sp[(size_t)spi * 128 + kc]);
                        float2 v01 = __half22float2(*reinterpret_cast<__half2*>(&v.x));
                        float2 v23 = __half22float2(*reinterpret_cast<__half2*>(&v.y));
                        acc.x += v01.x; acc.y += v01.y; acc.z += v23.x; acc.w += v23.y;
                    }
                    float inv = (en > st) ? 1.f / (float)(en - st) : 0.f;
                    acc.x *= inv; acc.y *= inv; acc.z *= inv; acc.w *= inv;
                } else { // GM_SPSUM: row is a spacepoint index; A0 = h16 base
                    #pragma unroll
                    for (int p = 0; p < 3; p++) {
                        const __half* hh = A0 + (size_t)p * PSTRIDE;
                        int st = g_offF[p][row], en = g_offF[p][row + 1];
                        float4 pa = make_float4(0.f, 0.f, 0.f, 0.f);
                        for (int e = st; e < en; e++) {
                            int hit = g_csrF[p][e];
                            uint2 v = *reinterpret_cast<const uint2*>(&hh[(size_t)hit * 128 + kc]);
                            float2 v01 = __half22float2(*reinterpret_cast<__half2*>(&v.x));
                            float2 v23 = __half22float2(*reinterpret_cast<__half2*>(&v.y));
                            pa.x += v01.x; pa.y += v01.y; pa.z += v23.x; pa.w += v23.y;
                        }
                        if (en > st) {
                            float inv = 1.f / (float)(en - st);
                            acc.x += pa.x * inv; acc.y += pa.y * inv;
                            acc.z += pa.z * inv; acc.w += pa.w * inv;
                        }
                    }
                }
                uint2 o = make_uint2(pack2h(acc.x, acc.y), pack2h(acc.z, acc.w));
                *reinterpret_cast<uint2*>(bufp + PB_A + swz(r, c4)) = o;
            }
        }
        const uint4* bh = &g_wbuf[wc0 + ch][0][kh][0];
        const uint4* bl = &g_wbuf[wc0 + ch][1][kh][0];
        #pragma unroll
        for (int l = 0; l < 4; l++) {
            int i = l * 256 + tid;
            cpa16(bb + PB_BHI + (uint32_t)i * 16, bh + i);
            cpa16(bb + PB_BLO + (uint32_t)i * 16, bl + i);
        }
        CP_COMMIT();
    };

    prefetch(0);
    for (int s = 0; s < nst; s++) {
        if (s + 1 < nst) { prefetch(s + 1); CP_WAIT1(); }
        else             { CP_WAIT0(); }
        __syncthreads();
        uint32_t ab = sb + (uint32_t)((s & 1) * PB_SZ);

        #pragma unroll
        for (int k16 = 0; k16 < 4; k16++) {
            uint32_t a[2][4];
            #pragma unroll
            for (int mt = 0; mt < 2; mt++) {
                int row = mwarp * 32 + mt * 16 + a_row_in16;
                uint32_t o = (uint32_t)(row * 128 + ((((k16 * 2 + a_kb) ^ row) & 7) << 4));
                ldsm4(a[mt], ab + PB_A + o);
            }
            #pragma unroll
            for (int ntp = 0; ntp < 4; ntp++) {
                int nrow = nwarp * 64 + ntp * 16 + b_row_in16;
                uint32_t o = (uint32_t)(nrow * 128 + ((((k16 * 2 + b_kb) ^ nrow) & 7) << 4));
                uint32_t bhi[4], blo[4];
                ldsm4(bhi, ab + PB_BHI + o);
                ldsm4(blo, ab + PB_BLO + o);
                #pragma unroll
                for (int half = 0; half < 2; half++) {
                    int nt = ntp * 2 + half;
                    #pragma unroll
                    for (int mt = 0; mt < 2; mt++) {
                        mma16816(C[mt][nt], a[mt], bhi[half * 2], bhi[half * 2 + 1]);
                        mma16816(C[mt][nt], a[mt], blo[half * 2], blo[half * 2 + 1]);
                    }
                }
            }
        }
        __syncthreads();
    }

    int qrow = lane >> 2;
    int qcol = (lane & 3) * 2;
    #pragma unroll
    for (int mt = 0; mt < 2; mt++) {
        #pragma unroll
        for (int half = 0; half < 2; half++) {
            int row = row0 + mwarp * 32 + mt * 16 + qrow + half * 8;
            if (row >= M) continue;
            bool dg = (epi == EPI_RESRELU_DEG) ? (maskp[row] > 0) : false;
            #pragma unroll
            for (int nt = 0; nt < 8; nt++) {
                int col = nwarp * 64 + nt * 8 + qcol;
                float v0 = C[mt][nt][half * 2 + 0];
                float v1 = C[mt][nt][half * 2 + 1];
                float o0, o1;
                if (epi == EPI_RELU) {
                    o0 = fmaxf(v0 + bias[col], 0.f);
                    o1 = fmaxf(v1 + bias[col + 1], 0.f);
                } else {
                    float e0 = v0 + bias[col], e1 = v1 + bias[col + 1];
                    if (epi == EPI_RESRELU_DEG && dg) { e0 += bias2[col]; e1 += bias2[col + 1]; }
                    float2 rr = *reinterpret_cast<const float2*>(&residp[(size_t)row * 128 + col]);
                    o0 = rr.x + fmaxf(e0, 0.f);
                    o1 = rr.y + fmaxf(e1, 0.f);
                }
                if (outf)
                    *reinterpret_cast<float2*>(&outf[(size_t)pl * sA + (size_t)row * 128 + col]) =
                        make_float2(o0, o1);
                if (outh)
                    *reinterpret_cast<__half2*>(&outh[(size_t)pl * sA + (size_t)row * 128 + col]) =
                        __floats2half2_rn(o0, o1);
            }
        }
    }
}

// ---------------- dual-output GEMM, cp.async pipelined B ----------------
__global__ __launch_bounds__(256, 2) void gemm_dual(
    const __half* __restrict__ A, int sA, int wc0, int wc1,
    __half* __restrict__ out0, __half* __restrict__ out1, int M)
{
    extern __shared__ char smem[];
    uint32_t sb = s2u(smem);
    int tid = threadIdx.x;
    int wid = tid >> 5, lane = tid & 31;
    int mwarp = wid & 3, nwarp = wid >> 2;
    int row0 = blockIdx.x * 128;
    int pl = blockIdx.y;
    const __half* Ap = A + (size_t)pl * sA;
    __half* o0 = out0 + (size_t)pl * sA;
    __half* o1 = out1 + (size_t)pl * sA;

    int a_row_in16 = (lane & 7) + ((lane >> 3) & 1) * 8;
    int a_kb = (lane >> 4) & 1;
    int b_row_in16 = (lane & 7) + ((lane >> 4) & 1) * 8;
    int b_kb = (lane >> 3) & 1;
    int qrow = lane >> 2;
    int qcol = (lane & 3) * 2;

    auto prefetchB = [&](int s) {
        int w = s >> 1, kh = s & 1;
        int wc = w ? wc1 : wc0;
        uint32_t bb = sb + DU_B + (uint32_t)((s & 1) * DU_BSZ);
        const uint4* bh = &g_wbuf[wc][0][kh][0];
        const uint4* bl = &g_wbuf[wc][1][kh][0];
        #pragma unroll
        for (int l = 0; l < 4; l++) {
            int i = l * 256 + tid;
            cpa16(bb + (uint32_t)i * 16, bh + i);
            cpa16(bb + 16384 + (uint32_t)i * 16, bl + i);
        }
        CP_COMMIT();
    };

    #pragma unroll
    for (int l = 0; l < 16; l++) {
        int i = l * 256 + tid;
        int r = i >> 5, c4 = (i & 31) * 4;
        int sh = c4 >> 6, k = c4 & 63;
        int row = row0 + r; if (row >= M) row = M - 1;
        cpa8(sb + DU_A + sh * 16384 + swz(r, k), &Ap[(size_t)row * 128 + c4]);
    }
    prefetchB(0);

    float C[2][8][4];
    for (int s = 0; s < 4; s++) {
        if (s + 1 < 4) { prefetchB(s + 1); CP_WAIT1(); }
        else           { CP_WAIT0(); }
        __syncthreads();

        if ((s & 1) == 0) {
            #pragma unroll
            for (int mt = 0; mt < 2; mt++)
                #pragma unroll
                for (int nt = 0; nt < 8; nt++)
                    #pragma unroll
                    for (int q = 0; q < 4; q++) C[mt][nt][q] = 0.f;
        }

        uint32_t abase = sb + DU_A + (uint32_t)((s & 1) * 16384);
        uint32_t bbase = sb + DU_B + (uint32_t)((s & 1) * DU_BSZ);
        #pragma unroll
        for (int k16 = 0; k16 < 4; k16++) {
            uint32_t a[2][4];
            #pragma unroll
            for (int mt = 0; mt < 2; mt++) {
                int row = mwarp * 32 + mt * 16 + a_row_in16;
                uint32_t o = (uint32_t)(row * 128 + ((((k16 * 2 + a_kb) ^ row) & 7) << 4));
                ldsm4(a[mt], abase + o);
            }
            #pragma unroll
            for (int ntp = 0; ntp < 4; ntp++) {
                int nrow = nwarp * 64 + ntp * 16 + b_row_in16;
                uint32_t o = (uint32_t)(nrow * 128 + ((((k16 * 2 + b_kb) ^ nrow) & 7) << 4));
                uint32_t bhi[4], blo[4];
                ldsm4(bhi, bbase + o);
                ldsm4(blo, bbase + 16384 + o);
                #pragma unroll
                for (int half = 0; half < 2; half++) {
                    int nt = ntp * 2 + half;
                    #pragma unroll
                    for (int mt = 0; mt < 2; mt++) {
                        mma16816(C[mt][nt], a[mt], bhi[half * 2], bhi[half * 2 + 1]);
                        mma16816(C[mt][nt], a[mt], blo[half * 2], blo[half * 2 + 1]);
                    }
                }
            }
        }
        __syncthreads();

        if (s & 1) {
            __half* op = (s >> 1) ? o1 : o0;
            #pragma unroll
            for (int mt = 0; mt < 2; mt++) {
                #pragma unroll
                for (int half = 0; half < 2; half++) {
                    int row = row0 + mwarp * 32 + mt * 16 + qrow + half * 8;
                    if (row >= M) continue;
                    #pragma unroll
                    for (int nt = 0; nt < 8; nt++) {
                        int col = nwarp * 64 + nt * 8 + qcol;
                        *reinterpret_cast<__half2*>(&op[(size_t)row * 128 + col]) =
                            __floats2half2_rn(C[mt][nt][half * 2], C[mt][nt][half * 2 + 1]);
                    }
                }
            }
        }
    }
}

// ---------------- CSR build ----------------
__global__ void zero_counts() {
    int i = blockIdx.x * blockDim.x + threadIdx.x;
    if (i < NHIT) {
        #pragma unroll
        for (int p = 0; p < 3; p++) { g_deg[p][i] = 0; g_cb[p][i] = 0; }
    }
    if (i < NSP) {
        #pragma unroll
        for (int p = 0; p < 3; p++) g_cf[p][i] = 0;
    }
}

__global__ void count_all(const int* __restrict__ e0, const int* __restrict__ e1,
                          const int* __restrict__ e2, const int* __restrict__ n0,
                          const int* __restrict__ n1, const int* __restrict__ n2) {
    int p = blockIdx.y;
    const int* e = (p == 0) ? e0 : (p == 1) ? e1 : e2;
    const int* nx = (p == 0) ? n0 : (p == 1) ? n1 : n2;
    int i = blockIdx.x * blockDim.x + threadIdx.x;
    if (i < NEDGE) atomicAdd(&g_deg[p][e[NEDGE + i]], 1);
    if (i < NSP) {
        atomicAdd(&g_cf[p][nx[NSP + i]], 1);
        atomicAdd(&g_cb[p][nx[i]], 1);
    }
}

__global__ void scan_excl_all() {
    int sel = blockIdx.x / 3, p = blockIdx.x % 3;
    const int* in; int* out; int* cur; int n;
    if (sel == 0)      { in = g_deg[p]; out = g_offE[p]; cur = g_curE[p]; n = NHIT; }
    else if (sel == 1) { in = g_cf[p];  out = g_offF[p]; cur = g_curF[p]; n = NSP; }
    else               { in = g_cb[p];  out = g_offB[p]; cur = g_curB[p]; n = NHIT; }
    __shared__ int wsum[32];
    __shared__ int carry;
    int tid = threadIdx.x;
    if (tid == 0) carry = 0;
    __syncthreads();
    for (int base = 0; base < n; base += 1024) {
        int i = base + tid;
        int v = (i < n) ? in[i] : 0;
        int x = v;
        #pragma unroll
        for (int d = 1; d < 32; d <<= 1) {
            int y = __shfl_up_sync(0xffffffffu, x, d);
            if ((tid & 31) >= d) x += y;
        }
        if ((tid & 31) == 31) wsum[tid >> 5] = x;
        __syncthreads();
        if (tid < 32) {
            int s = wsum[tid];
            #pragma unroll
            for (int d = 1; d < 32; d <<= 1) {
                int y = __shfl_up_sync(0xffffffffu, s, d);
                if (tid >= d) s += y;
            }
            wsum[tid] = s;
        }
        __syncthreads();
        int woff = (tid >= 32) ? wsum[(tid >> 5) - 1] : 0;
        int incl = carry + woff + x;
        if (i < n) { out[i] = incl - v; cur[i] = incl - v; }
        __syncthreads();
        if (tid == 1023) carry = incl;
        __syncthreads();
    }
    if (tid == 0) out[n] = carry;
}

__global__ void fill_all(const int* __restrict__ e0, const int* __restrict__ e1,
                         const int* __restrict__ e2, const int* __restrict__ n0,
                         const int* __restrict__ n1, const int* __restrict__ n2) {
    int p = blockIdx.y;
    const int* e = (p == 0) ? e0 : (p == 1) ? e1 : e2;
    const int* nx = (p == 0) ? n0 : (p == 1) ? n1 : n2;
    int i = blockIdx.x * blockDim.x + threadIdx.x;
    if (i < NEDGE) {
        int dst = e[NEDGE + i];
        g_csrE[p][atomicAdd(&g_curE[p][dst], 1)] = e[i];
    }
    if (i < NSP) {
        int s = nx[NSP + i];
        g_csrF[p][atomicAdd(&g_curF[p][s], 1)] = nx[i];
        int h = nx[i];
        g_csrB[p][atomicAdd(&g_curB[p][h], 1)] = nx[NSP + i];
    }
}

// ---------------- encoder ----------------
__global__ void encoder_k(const float* __restrict__ x0, const float* __restrict__ x1,
                          const float* __restrict__ x2, const float* __restrict__ W,
                          const float* __restrict__ b, float* __restrict__ hbase,
                          __half* __restrict__ h16base) {
    int p = blockIdx.y;
    const float* x = (p == 0) ? x0 : (p == 1) ? x1 : x2;
    int idx = blockIdx.x * blockDim.x + threadIdx.x;
    if (idx >= NHIT * HD) return;
    int n = idx >> 7, j = idx & 127;
    float acc = b[j];
    #pragma unroll
    for (int k = 0; k < 4; k++) acc = fmaf(x[n * 4 + k], W[k * HD + j], acc);
    acc = fmaxf(acc, 0.f);
    hbase[(size_t)p * PSTRIDE + idx] = acc;
    h16base[(size_t)p * PSTRIDE + idx] = __float2half(acc);
}

// ---------------- decoder ----------------
__global__ void decoder_k(const float* __restrict__ hbase, const float* __restrict__ Wsem,
                          const float* __restrict__ bsem, float* __restrict__ out) {
    int p = blockIdx.y;
    const float* h = hbase + (size_t)p * PSTRIDE;
    float* o = out + (size_t)p * NHIT * NCLASS;
    int warp = (blockIdx.x * blockDim.x + threadIdx.x) >> 5;
    if (warp >= NHIT) return;
    int lane = threadIdx.x & 31;
    int n = warp;
    float hv[4];
    #pragma unroll
    for (int t = 0; t < 4; t++) hv[t] = h[(size_t)n * HD + lane + t * 32];
    #pragma unroll
    for (int c = 0; c < NCLASS; c++) {
        float s = 0.f;
        #pragma unroll
        for (int t = 0; t < 4; t++) s = fmaf(hv[t], Wsem[(lane + t * 32) * NCLASS + c], s);
        #pragma unroll
        for (int d = 16; d > 0; d >>= 1) s += __shfl_down_sync(0xffffffffu, s, d);
        if (lane == 0) o[n * NCLASS + c] = s + bsem[c];
    }
}

// ---------------- host ----------------
extern "C" void kernel_launch(void* const* d_in, const int* in_sizes, int n_in,
                              void* d_out, int out_size) {
    int xi[3], ei[3], ni[3];
    if (in_sizes[1] == 2 * NEDGE) {
        for (int p = 0; p < 3; p++) { xi[p] = 3 * p; ei[p] = 3 * p + 1; ni[p] = 3 * p + 2; }
    } else {
        for (int p = 0; p < 3; p++) { xi[p] = p; ei[p] = 3 + p; ni[p] = 6 + p; }
    }
    const float* x[3]; const int* edge[3]; const int* nexus[3];
    for (int p = 0; p < 3; p++) {
        x[p] = (const float*)d_in[xi[p]];
        edge[p] = (const int*)d_in[ei[p]];
        nexus[p] = (const int*)d_in[ni[p]];
    }
    const float* W_enc  = (const float*)d_in[9];
    const float* b_enc  = (const float*)d_in[10];
    const float* W_msg1 = (const float*)d_in[11];
    const float* b_msg1 = (const float*)d_in[12];
    const float* W_msg2 = (const float*)d_in[13];
    const float* b_msg2 = (const float*)d_in[14];
    const float* W_upd  = (const float*)d_in[15];
    const float* b_upd  = (const float*)d_in[16];
    const float* W_sp   = (const float*)d_in[17];
    const float* b_sp   = (const float*)d_in[18];
    const float* W_nx   = (const float*)d_in[19];
    const float* b_nx   = (const float*)d_in[20];
    const float* W_sem  = (const float*)d_in[21];
    const float* b_sem  = (const float*)d_in[22];

    float *ph, *pwcomb, *pb2c; int* pdeg;
    __half *ph16, *pA, *pB, *psp;
    cudaGetSymbolAddress((void**)&ph, g_h);
    cudaGetSymbolAddress((void**)&ph16, g_h16);
    cudaGetSymbolAddress((void**)&pA, g_A);
    cudaGetSymbolAddress((void**)&pB, g_B);
    cudaGetSymbolAddress((void**)&psp, g_sp);
    cudaGetSymbolAddress((void**)&pwcomb, g_wcomb);
    cudaGetSymbolAddress((void**)&pb2c, g_b2c);
    cudaGetSymbolAddress((void**)&pdeg, g_deg);

    cudaFuncSetAttribute(gemm_mma, cudaFuncAttributeMaxDynamicSharedMemorySize, SM_TOTAL);
    cudaFuncSetAttribute(gemm_dual, cudaFuncAttributeMaxDynamicSharedMemorySize, DU_TOTAL);

    float* h0 = ph;
    float* h1 = ph + (size_t)3 * PSTRIDE;
    __half* h16_0 = ph16;
    __half* h16_1 = ph16 + (size_t)3 * PSTRIDE;

    const int T = 256;
    dim3 gG3((NHIT + 127) / 128, 3);
    dim3 gG1((NSP + 127) / 128, 1);
    dim3 gW3((NHIT * 32 + T - 1) / T, 3);
    dim3 gE((NHIT * HD + T - 1) / T, 3);

    // --- CSR build ---
    zero_counts<<<(NHIT + T - 1) / T, T>>>();
    dim3 gCnt((NEDGE + T - 1) / T, 3);
    count_all<<<gCnt, T>>>(edge[0], edge[1], edge[2], nexus[0], nexus[1], nexus[2]);
    scan_excl_all<<<9, 1024>>>();
    fill_all<<<gCnt, T>>>(edge[0], edge[1], edge[2], nexus[0], nexus[1], nexus[2]);

    // --- weight combine + prep (0=W1top 1=W1bot 2=WupdT 3=comb 4=Wsp 5=WnxT 6=WnxB) ---
    combine_w<<<129, 128>>>(W_msg2, W_upd + 128 * 128, b_msg2);
    prep_w<<<224, 256>>>(W_msg1, W_msg1 + 128 * 128, W_upd, pwcomb,
                         W_sp, W_nx, W_nx + 128 * 128);

    // --- encoder ---
    encoder_k<<<gE, T>>>(x[0], x[1], x[2], W_enc, b_enc, h0, h16_0);

    for (int it = 0; it < 3; it++) {
        // planar: A/B projections
        gemm_dual<<<gG3, T, DU_TOTAL>>>(h16_0, PSTRIDE, 0, 1, pA, pB, NHIT);
        // upd: chunk0 = h16, chunk1 = fused planar-agg gather (mr)
        gemm_mma<<<gG3, T, SM_TOTAL>>>(h16_0, nullptr, PSTRIDE, 2, 2, GM_NONE, GM_MR,
                                       b_msg1, b_upd, pb2c, pdeg, NHIT,
                                       h0, h1, h16_1, NHIT, EPI_RESRELU_DEG);
        // sp: chunk0 = fused nexus-forward gather (spsum)
        gemm_mma<<<gG1, T, SM_TOTAL>>>(h16_1, nullptr, 0, 4, 1, GM_SPSUM, GM_NONE,
                                       nullptr, b_sp, nullptr, nullptr, 0,
                                       nullptr, nullptr, psp, NSP, EPI_RELU);
        // nx: chunk0 = h16, chunk1 = fused nexus-back gather
        gemm_mma<<<gG3, T, SM_TOTAL>>>(h16_1, nullptr, PSTRIDE, 5, 2, GM_NONE, GM_BACK,
                                       nullptr, b_nx, nullptr, nullptr, 0,
                                       h1, h0, h16_0, NHIT, EPI_RESRELU);
    }

    decoder_k<<<gW3, T>>>(h0, W_sem, b_sem, (float*)d_out);
}

// round 12
// speedup vs baseline: 1.4297x; 1.4297x over previous
#include <cuda_runtime.h>
#include <cuda_fp16.h>
#include <cstdint>

#define NHIT 30000
#define NEDGE 90000
#define NSP 30000
#define HD 128
#define NCLASS 5
#define PSTRIDE (NHIT * HD)

// ---------------- device scratch ----------------
__device__ float g_h[2][3][NHIT * HD];          // fp32 state (residual path)
__device__ __half g_h16[2][3][NHIT * HD];       // fp16 shadow of h (GEMM A operand)
__device__ __half g_A[3][NHIT * HD];
__device__ __half g_B[3][NHIT * HD];
__device__ __half g_mr[3][NHIT * HD];
__device__ __half g_spsum[NSP * HD];
__device__ __half g_sp[NSP * HD];
__device__ __half g_back[3][NHIT * HD];
__device__ float g_wcomb[HD * HD];              // W_msg2 @ W_upd_bottom
__device__ float g_b2c[HD];                     // b_msg2 @ W_upd_bottom

// prepped weights: 7 chunks x {hi,lo} x 2 k-stages x (128n x 64k fp16, swizzled)
__device__ uint4 g_wbuf[7][2][2][1024];

__device__ int g_deg[3][NHIT];
__device__ int g_cf[3][NSP];
__device__ int g_cb[3][NHIT];
__device__ int g_offE[3][NHIT + 1];
__device__ int g_offF[3][NSP + 1];
__device__ int g_offB[3][NHIT + 1];
__device__ int g_csrE[3][NEDGE];
__device__ int g_csrF[3][NSP];
__device__ int g_csrB[3][NSP];
__device__ int g_curE[3][NHIT];
__device__ int g_curF[3][NSP];
__device__ int g_curB[3][NHIT];

enum { EPI_RELU = 1, EPI_RESRELU = 2, EPI_RESRELU_DEG = 4 };

// ---------------- helpers ----------------
__device__ __forceinline__ uint32_t s2u(const void* p) {
    return (uint32_t)__cvta_generic_to_shared(p);
}
__device__ __forceinline__ uint32_t pack2h(float a, float b) {
    __half2 t = __floats2half2_rn(a, b);
    return *reinterpret_cast<uint32_t*>(&t);
}
__device__ __forceinline__ float lopart(float v) {
    return v - __half2float(__float2half(v));
}
__device__ __forceinline__ uint32_t swz(int row, int k) {
    return (uint32_t)(row * 128 + ((((k >> 3) ^ row) & 7) << 4) + (k & 7) * 2);
}
__device__ __forceinline__ void ldsm4(uint32_t* r, uint32_t addr) {
    asm volatile("ldmatrix.sync.aligned.m8n8.x4.shared.b16 {%0,%1,%2,%3}, [%4];"
                 : "=r"(r[0]), "=r"(r[1]), "=r"(r[2]), "=r"(r[3]) : "r"(addr));
}
__device__ __forceinline__ void mma16816(float* c, const uint32_t* a, uint32_t b0, uint32_t b1) {
    asm volatile(
        "mma.sync.aligned.m16n8k16.row.col.f32.f16.f16.f32 "
        "{%0,%1,%2,%3}, {%4,%5,%6,%7}, {%8,%9}, {%0,%1,%2,%3};"
        : "+f"(c[0]), "+f"(c[1]), "+f"(c[2]), "+f"(c[3])
        : "r"(a[0]), "r"(a[1]), "r"(a[2]), "r"(a[3]), "r"(b0), "r"(b1));
}
__device__ __forceinline__ void cpa8(uint32_t dst, const void* src) {
    asm volatile("cp.async.ca.shared.global [%0], [%1], 8;" :: "r"(dst), "l"(src));
}
__device__ __forceinline__ void cpa16(uint32_t dst, const void* src) {
    asm volatile("cp.async.cg.shared.global [%0], [%1], 16;" :: "r"(dst), "l"(src));
}
#define CP_COMMIT() asm volatile("cp.async.commit_group;")
#define CP_WAIT1()  asm volatile("cp.async.wait_group 1;")
#define CP_WAIT0()  asm volatile("cp.async.wait_group 0;")

// gemm_mma: 2 pipeline buffers x [A 16K | BHI 16K | BLO 16K]
#define PB_A 0
#define PB_BHI 16384
#define PB_BLO 32768
#define PB_SZ 49152
#define SM_TOTAL 98304
// gemm_dual: A (both halves) 32K + 2 B-buffers x [BHI 16K | BLO 16K]
#define DU_A 0
#define DU_B 32768
#define DU_BSZ 32768
#define DU_TOTAL 98304

// ---------------- weight combine ----------------
__global__ void combine_w(const float* __restrict__ W2, const float* __restrict__ Wub,
                          const float* __restrict__ b2) {
    int n = threadIdx.x;
    int k = blockIdx.x;
    if (k < 128) {
        float s = 0.f;
        #pragma unroll 8
        for (int j = 0; j < 128; j++) s = fmaf(W2[k * 128 + j], Wub[j * 128 + n], s);
        g_wcomb[k * 128 + n] = s;
    } else {
        float s = 0.f;
        #pragma unroll 8
        for (int j = 0; j < 128; j++) s = fmaf(b2[j], Wub[j * 128 + n], s);
        g_b2c[n] = s;
    }
}

// ---------------- weight prep ----------------
__global__ void prep_w(const float* w0, const float* w1, const float* w2,
                       const float* w3, const float* w4, const float* w5,
                       const float* w6) {
    int id = blockIdx.x * blockDim.x + threadIdx.x;
    if (id >= 7 * 8192) return;
    int c = id >> 13;
    int rem = id & 8191;
    int s = rem >> 12;
    int rem2 = rem & 4095;
    int n = rem2 >> 5;
    int kp = (rem2 & 31) * 2;
    const float* Wc = (c == 0) ? w0 : (c == 1) ? w1 : (c == 2) ? w2 : (c == 3) ? w3
                    : (c == 4) ? w4 : (c == 5) ? w5 : w6;
    float v0 = Wc[(s * 64 + kp) * 128 + n];
    float v1 = Wc[(s * 64 + kp + 1) * 128 + n];
    uint32_t o = swz(n, kp);
    *reinterpret_cast<uint32_t*>((char*)&g_wbuf[c][0][s][0] + o) = pack2h(v0, v1);
    *reinterpret_cast<uint32_t*>((char*)&g_wbuf[c][1][s][0] + o) = pack2h(lopart(v0), lopart(v1));
}

// ---------------- HMMA 2-pass GEMM, cp.async double-buffered ----------------
__global__ __launch_bounds__(256, 2) void gemm_mma(
    const __half* __restrict__ Ah0, const __half* __restrict__ Ah1,
    int sA, int wc0, int nchunks,
    const float* __restrict__ bias, const float* __restrict__ bias2,
    const int* __restrict__ mask, int sMask,
    const float* __restrict__ resid,
    float* __restrict__ outf, __half* __restrict__ outh, int M, int epi)
{
    extern __shared__ char smem[];
    uint32_t sb = s2u(smem);
    int tid = threadIdx.x;
    int wid = tid >> 5, lane = tid & 31;
    int mwarp = wid & 3, nwarp = wid >> 2;
    int row0 = blockIdx.x * 128;
    int pl = blockIdx.y;
    const __half* Ah0p = Ah0 + (size_t)pl * sA;
    const __half* Ah1p = Ah1 ? (Ah1 + (size_t)pl * sA) : nullptr;
    const float* residp = resid ? (resid + (size_t)pl * sA) : nullptr;
    const int* maskp = mask ? (mask + (size_t)pl * sMask) : nullptr;

    float C[2][8][4];
    #pragma unroll
    for (int mt = 0; mt < 2; mt++)
        #pragma unroll
        for (int nt = 0; nt < 8; nt++)
            #pragma unroll
            for (int q = 0; q < 4; q++) C[mt][nt][q] = 0.f;

    int a_row_in16 = (lane & 7) + ((lane >> 3) & 1) * 8;
    int a_kb = (lane >> 4) & 1;
    int b_row_in16 = (lane & 7) + ((lane >> 4) & 1) * 8;
    int b_kb = (lane >> 3) & 1;

    int nst = nchunks * 2;

    auto prefetch = [&](int s) {
        int ch = s >> 1, kh = s & 1;
        const __half* src = ch ? Ah1p : Ah0p;
        uint32_t bb = sb + (uint32_t)((s & 1) * PB_SZ);
        #pragma unroll
        for (int l = 0; l < 8; l++) {
            int i = l * 256 + tid;
            int r = i >> 4, c4 = (i & 15) * 4;
            int row = row0 + r; if (row >= M) row = M - 1;
            cpa8(bb + PB_A + swz(r, c4), &src[(size_t)row * 128 + kh * 64 + c4]);
        }
        const uint4* bh = &g_wbuf[wc0 + ch][0][kh][0];
        const uint4* bl = &g_wbuf[wc0 + ch][1][kh][0];
        #pragma unroll
        for (int l = 0; l < 4; l++) {
            int i = l * 256 + tid;
            cpa16(bb + PB_BHI + (uint32_t)i * 16, bh + i);
            cpa16(bb + PB_BLO + (uint32_t)i * 16, bl + i);
        }
        CP_COMMIT();
    };

    prefetch(0);
    for (int s = 0; s < nst; s++) {
        if (s + 1 < nst) { prefetch(s + 1); CP_WAIT1(); }
        else             { CP_WAIT0(); }
        __syncthreads();
        uint32_t ab = sb + (uint32_t)((s & 1) * PB_SZ);

        #pragma unroll
        for (int k16 = 0; k16 < 4; k16++) {
            uint32_t a[2][4];
            #pragma unroll
            for (int mt = 0; mt < 2; mt++) {
                int row = mwarp * 32 + mt * 16 + a_row_in16;
                uint32_t o = (uint32_t)(row * 128 + ((((k16 * 2 + a_kb) ^ row) & 7) << 4));
                ldsm4(a[mt], ab + PB_A + o);
            }
            #pragma unroll
            for (int ntp = 0; ntp < 4; ntp++) {
                int nrow = nwarp * 64 + ntp * 16 + b_row_in16;
                uint32_t o = (uint32_t)(nrow * 128 + ((((k16 * 2 + b_kb) ^ nrow) & 7) << 4));
                uint32_t bhi[4], blo[4];
                ldsm4(bhi, ab + PB_BHI + o);
                ldsm4(blo, ab + PB_BLO + o);
                #pragma unroll
                for (int half = 0; half < 2; half++) {
                    int nt = ntp * 2 + half;
                    #pragma unroll
                    for (int mt = 0; mt < 2; mt++) {
                        mma16816(C[mt][nt], a[mt], bhi[half * 2], bhi[half * 2 + 1]);
                        mma16816(C[mt][nt], a[mt], blo[half * 2], blo[half * 2 + 1]);
                    }
                }
            }
        }
        __syncthreads();
    }

    int qrow = lane >> 2;
    int qcol = (lane & 3) * 2;
    #pragma unroll
    for (int mt = 0; mt < 2; mt++) {
        #pragma unroll
        for (int half = 0; half < 2; half++) {
            int row = row0 + mwarp * 32 + mt * 16 + qrow + half * 8;
            if (row >= M) continue;
            bool dg = (epi == EPI_RESRELU_DEG) ? (maskp[row] > 0) : false;
            #pragma unroll
            for (int nt = 0; nt < 8; nt++) {
                int col = nwarp * 64 + nt * 8 + qcol;
                float v0 = C[mt][nt][half * 2 + 0];
                float v1 = C[mt][nt][half * 2 + 1];
                float o0, o1;
                if (epi == EPI_RELU) {
                    o0 = fmaxf(v0 + bias[col], 0.f);
                    o1 = fmaxf(v1 + bias[col + 1], 0.f);
                } else {
                    float e0 = v0 + bias[col], e1 = v1 + bias[col + 1];
                    if (epi == EPI_RESRELU_DEG && dg) { e0 += bias2[col]; e1 += bias2[col + 1]; }
                    float2 rr = *reinterpret_cast<const float2*>(&residp[(size_t)row * 128 + col]);
                    o0 = rr.x + fmaxf(e0, 0.f);
                    o1 = rr.y + fmaxf(e1, 0.f);
                }
                if (outf)
                    *reinterpret_cast<float2*>(&outf[(size_t)pl * sA + (size_t)row * 128 + col]) =
                        make_float2(o0, o1);
                if (outh)
                    *reinterpret_cast<__half2*>(&outh[(size_t)pl * sA + (size_t)row * 128 + col]) =
                        __floats2half2_rn(o0, o1);
            }
        }
    }
}

// ---------------- dual-output GEMM, cp.async pipelined B ----------------
__global__ __launch_bounds__(256, 2) void gemm_dual(
    const __half* __restrict__ A, int sA, int wc0, int wc1,
    __half* __restrict__ out0, __half* __restrict__ out1, int M)
{
    extern __shared__ char smem[];
    uint32_t sb = s2u(smem);
    int tid = threadIdx.x;
    int wid = tid >> 5, lane = tid & 31;
    int mwarp = wid & 3, nwarp = wid >> 2;
    int row0 = blockIdx.x * 128;
    int pl = blockIdx.y;
    const __half* Ap = A + (size_t)pl * sA;
    __half* o0 = out0 + (size_t)pl * sA;
    __half* o1 = out1 + (size_t)pl * sA;

    int a_row_in16 = (lane & 7) + ((lane >> 3) & 1) * 8;
    int a_kb = (lane >> 4) & 1;
    int b_row_in16 = (lane & 7) + ((lane >> 4) & 1) * 8;
    int b_kb = (lane >> 3) & 1;
    int qrow = lane >> 2;
    int qcol = (lane & 3) * 2;

    auto prefetchB = [&](int s) {
        int w = s >> 1, kh = s & 1;
        int wc = w ? wc1 : wc0;
        uint32_t bb = sb + DU_B + (uint32_t)((s & 1) * DU_BSZ);
        const uint4* bh = &g_wbuf[wc][0][kh][0];
        const uint4* bl = &g_wbuf[wc][1][kh][0];
        #pragma unroll
        for (int l = 0; l < 4; l++) {
            int i = l * 256 + tid;
            cpa16(bb + (uint32_t)i * 16, bh + i);
            cpa16(bb + 16384 + (uint32_t)i * 16, bl + i);
        }
        CP_COMMIT();
    };

    #pragma unroll
    for (int l = 0; l < 16; l++) {
        int i = l * 256 + tid;
        int r = i >> 5, c4 = (i & 31) * 4;
        int sh = c4 >> 6, k = c4 & 63;
        int row = row0 + r; if (row >= M) row = M - 1;
        cpa8(sb + DU_A + sh * 16384 + swz(r, k), &Ap[(size_t)row * 128 + c4]);
    }
    prefetchB(0);

    float C[2][8][4];
    for (int s = 0; s < 4; s++) {
        if (s + 1 < 4) { prefetchB(s + 1); CP_WAIT1(); }
        else           { CP_WAIT0(); }
        __syncthreads();

        if ((s & 1) == 0) {
            #pragma unroll
            for (int mt = 0; mt < 2; mt++)
                #pragma unroll
                for (int nt = 0; nt < 8; nt++)
                    #pragma unroll
                    for (int q = 0; q < 4; q++) C[mt][nt][q] = 0.f;
        }

        uint32_t abase = sb + DU_A + (uint32_t)((s & 1) * 16384);
        uint32_t bbase = sb + DU_B + (uint32_t)((s & 1) * DU_BSZ);
        #pragma unroll
        for (int k16 = 0; k16 < 4; k16++) {
            uint32_t a[2][4];
            #pragma unroll
            for (int mt = 0; mt < 2; mt++) {
                int row = mwarp * 32 + mt * 16 + a_row_in16;
                uint32_t o = (uint32_t)(row * 128 + ((((k16 * 2 + a_kb) ^ row) & 7) << 4));
                ldsm4(a[mt], abase + o);
            }
            #pragma unroll
            for (int ntp = 0; ntp < 4; ntp++) {
                int nrow = nwarp * 64 + ntp * 16 + b_row_in16;
                uint32_t o = (uint32_t)(nrow * 128 + ((((k16 * 2 + b_kb) ^ nrow) & 7) << 4));
                uint32_t bhi[4], blo[4];
                ldsm4(bhi, bbase + o);
                ldsm4(blo, bbase + 16384 + o);
                #pragma unroll
                for (int half = 0; half < 2; half++) {
                    int nt = ntp * 2 + half;
                    #pragma unroll
                    for (int mt = 0; mt < 2; mt++) {
                        mma16816(C[mt][nt], a[mt], bhi[half * 2], bhi[half * 2 + 1]);
                        mma16816(C[mt][nt], a[mt], blo[half * 2], blo[half * 2 + 1]);
                    }
                }
            }
        }
        __syncthreads();

        if (s & 1) {
            __half* op = (s >> 1) ? o1 : o0;
            #pragma unroll
            for (int mt = 0; mt < 2; mt++) {
                #pragma unroll
                for (int half = 0; half < 2; half++) {
                    int row = row0 + mwarp * 32 + mt * 16 + qrow + half * 8;
                    if (row >= M) continue;
                    #pragma unroll
                    for (int nt = 0; nt < 8; nt++) {
                        int col = nwarp * 64 + nt * 8 + qcol;
                        *reinterpret_cast<__half2*>(&op[(size_t)row * 128 + col]) =
                            __floats2half2_rn(C[mt][nt][half * 2], C[mt][nt][half * 2 + 1]);
                    }
                }
            }
        }
    }
}

// ---------------- CSR build ----------------
__global__ void zero_counts() {
    int i = blockIdx.x * blockDim.x + threadIdx.x;
    if (i < NHIT) {
        #pragma unroll
        for (int p = 0; p < 3; p++) { g_deg[p][i] = 0; g_cb[p][i] = 0; }
    }
    if (i < NSP) {
        #pragma unroll
        for (int p = 0; p < 3; p++) g_cf[p][i] = 0;
    }
}

__global__ void count_all(const int* __restrict__ e0, const int* __restrict__ e1,
                          const int* __restrict__ e2, const int* __restrict__ n0,
                          const int* __restrict__ n1, const int* __restrict__ n2) {
    int p = blockIdx.y;
    const int* e = (p == 0) ? e0 : (p == 1) ? e1 : e2;
    const int* nx = (p == 0) ? n0 : (p == 1) ? n1 : n2;
    int i = blockIdx.x * blockDim.x + threadIdx.x;
    if (i < NEDGE) atomicAdd(&g_deg[p][e[NEDGE + i]], 1);
    if (i < NSP) {
        atomicAdd(&g_cf[p][nx[NSP + i]], 1);
        atomicAdd(&g_cb[p][nx[i]], 1);
    }
}

__global__ void scan_excl_all() {
    int sel = blockIdx.x / 3, p = blockIdx.x % 3;
    const int* in; int* out; int* cur; int n;
    if (sel == 0)      { in = g_deg[p]; out = g_offE[p]; cur = g_curE[p]; n = NHIT; }
    else if (sel == 1) { in = g_cf[p];  out = g_offF[p]; cur = g_curF[p]; n = NSP; }
    else               { in = g_cb[p];  out = g_offB[p]; cur = g_curB[p]; n = NHIT; }
    __shared__ int wsum[32];
    __shared__ int carry;
    int tid = threadIdx.x;
    if (tid == 0) carry = 0;
    __syncthreads();
    for (int base = 0; base < n; base += 1024) {
        int i = base + tid;
        int v = (i < n) ? in[i] : 0;
        int x = v;
        #pragma unroll
        for (int d = 1; d < 32; d <<= 1) {
            int y = __shfl_up_sync(0xffffffffu, x, d);
            if ((tid & 31) >= d) x += y;
        }
        if ((tid & 31) == 31) wsum[tid >> 5] = x;
        __syncthreads();
        if (tid < 32) {
            int s = wsum[tid];
            #pragma unroll
            for (int d = 1; d < 32; d <<= 1) {
                int y = __shfl_up_sync(0xffffffffu, s, d);
                if (tid >= d) s += y;
            }
            wsum[tid] = s;
        }
        __syncthreads();
        int woff = (tid >= 32) ? wsum[(tid >> 5) - 1] : 0;
        int incl = carry + woff + x;
        if (i < n) { out[i] = incl - v; cur[i] = incl - v; }
        __syncthreads();
        if (tid == 1023) carry = incl;
        __syncthreads();
    }
    if (tid == 0) out[n] = carry;
}

__global__ void fill_all(const int* __restrict__ e0, const int* __restrict__ e1,
                         const int* __restrict__ e2, const int* __restrict__ n0,
                         const int* __restrict__ n1, const int* __restrict__ n2) {
    int p = blockIdx.y;
    const int* e = (p == 0) ? e0 : (p == 1) ? e1 : e2;
    const int* nx = (p == 0) ? n0 : (p == 1) ? n1 : n2;
    int i = blockIdx.x * blockDim.x + threadIdx.x;
    if (i < NEDGE) {
        int dst = e[NEDGE + i];
        g_csrE[p][atomicAdd(&g_curE[p][dst], 1)] = e[i];
    }
    if (i < NSP) {
        int s = nx[NSP + i];
        g_csrF[p][atomicAdd(&g_curF[p][s], 1)] = nx[i];
        int h = nx[i];
        g_csrB[p][atomicAdd(&g_curB[p][h], 1)] = nx[NSP + i];
    }
}

// ---------------- encoder ----------------
__global__ void encoder_k(const float* __restrict__ x0, const float* __restrict__ x1,
                          const float* __restrict__ x2, const float* __restrict__ W,
                          const float* __restrict__ b, float* __restrict__ hbase,
                          __half* __restrict__ h16base) {
    int p = blockIdx.y;
    const float* x = (p == 0) ? x0 : (p == 1) ? x1 : x2;
    int idx = blockIdx.x * blockDim.x + threadIdx.x;
    if (idx >= NHIT * HD) return;
    int n = idx >> 7, j = idx & 127;
    float acc = b[j];
    #pragma unroll
    for (int k = 0; k < 4; k++) acc = fmaf(x[n * 4 + k], W[k * HD + j], acc);
    acc = fmaxf(acc, 0.f);
    hbase[(size_t)p * PSTRIDE + idx] = acc;
    h16base[(size_t)p * PSTRIDE + idx] = __float2half(acc);
}

// ---------------- planar edge aggregation (2-way unrolled MLP) ----------------
__global__ void planar_agg(const float* __restrict__ b1) {
    int p = blockIdx.y;
    int warp = (blockIdx.x * blockDim.x + threadIdx.x) >> 5;
    if (warp >= NHIT) return;
    int lane = threadIdx.x & 31;
    int n = warp;
    uint2 ar = *reinterpret_cast<const uint2*>(&g_A[p][(size_t)n * HD + lane * 4]);
    float2 a01 = __half22float2(*reinterpret_cast<__half2*>(&ar.x));
    float2 a23 = __half22float2(*reinterpret_cast<__half2*>(&ar.y));
    float4 bb = *reinterpret_cast<const float4*>(&b1[lane * 4]);
    int s = g_offE[p][n], e = g_offE[p][n + 1];
    float4 acc0 = make_float4(0.f, 0.f, 0.f, 0.f);
    float4 acc1 = make_float4(0.f, 0.f, 0.f, 0.f);
    int i = s;
    for (; i + 2 <= e; i += 2) {
        int s0 = g_csrE[p][i], s1 = g_csrE[p][i + 1];
        uint2 br0 = *reinterpret_cast<const uint2*>(&g_B[p][(size_t)s0 * HD + lane * 4]);
        uint2 br1 = *reinterpret_cast<const uint2*>(&g_B[p][(size_t)s1 * HD + lane * 4]);
        float2 b001 = __half22float2(*reinterpret_cast<__half2*>(&br0.x));
        float2 b023 = __half22float2(*reinterpret_cast<__half2*>(&br0.y));
        float2 b101 = __half22float2(*reinterpret_cast<__half2*>(&br1.x));
        float2 b123 = __half22float2(*reinterpret_cast<__half2*>(&br1.y));
        acc0.x += fmaxf(a01.x + b001.x + bb.x, 0.f);
        acc0.y += fmaxf(a01.y + b001.y + bb.y, 0.f);
        acc0.z += fmaxf(a23.x + b023.x + bb.z, 0.f);
        acc0.w += fmaxf(a23.y + b023.y + bb.w, 0.f);
        acc1.x += fmaxf(a01.x + b101.x + bb.x, 0.f);
        acc1.y += fmaxf(a01.y + b101.y + bb.y, 0.f);
        acc1.z += fmaxf(a23.x + b123.x + bb.z, 0.f);
        acc1.w += fmaxf(a23.y + b123.y + bb.w, 0.f);
    }
    if (i < e) {
        int s0 = g_csrE[p][i];
        uint2 br0 = *reinterpret_cast<const uint2*>(&g_B[p][(size_t)s0 * HD + lane * 4]);
        float2 b001 = __half22float2(*reinterpret_cast<__half2*>(&br0.x));
        float2 b023 = __half22float2(*reinterpret_cast<__half2*>(&br0.y));
        acc0.x += fmaxf(a01.x + b001.x + bb.x, 0.f);
        acc0.y += fmaxf(a01.y + b001.y + bb.y, 0.f);
        acc0.z += fmaxf(a23.x + b023.x + bb.z, 0.f);
        acc0.w += fmaxf(a23.y + b023.y + bb.w, 0.f);
    }
    float4 acc = make_float4(acc0.x + acc1.x, acc0.y + acc1.y,
                             acc0.z + acc1.z, acc0.w + acc1.w);
    float inv = (e > s) ? 1.f / (float)(e - s) : 0.f;
    uint2 o;
    *reinterpret_cast<__half2*>(&o.x) = __floats2half2_rn(acc.x * inv, acc.y * inv);
    *reinterpret_cast<__half2*>(&o.y) = __floats2half2_rn(acc.z * inv, acc.w * inv);
    *reinterpret_cast<uint2*>(&g_mr[p][(size_t)n * HD + lane * 4]) = o;
}

// ---------------- nexus forward (2-way unrolled) ----------------
__global__ void nexus_fwd(const __half* __restrict__ h16base) {
    int warp = (blockIdx.x * blockDim.x + threadIdx.x) >> 5;
    if (warp >= NSP) return;
    int lane = threadIdx.x & 31;
    int s = warp;
    float4 tot = make_float4(0.f, 0.f, 0.f, 0.f);
    #pragma unroll
    for (int p = 0; p < 3; p++) {
        const __half* h = h16base + (size_t)p * PSTRIDE;
        int st = g_offF[p][s], en = g_offF[p][s + 1];
        float4 acc0 = make_float4(0.f, 0.f, 0.f, 0.f);
        float4 acc1 = make_float4(0.f, 0.f, 0.f, 0.f);
        int i = st;
        for (; i + 2 <= en; i += 2) {
            int h0i = g_csrF[p][i], h1i = g_csrF[p][i + 1];
            uint2 v0 = *reinterpret_cast<const uint2*>(&h[(size_t)h0i * HD + lane * 4]);
            uint2 v1 = *reinterpret_cast<const uint2*>(&h[(size_t)h1i * HD + lane * 4]);
            float2 a01 = __half22float2(*reinterpret_cast<__half2*>(&v0.x));
            float2 a23 = __half22float2(*reinterpret_cast<__half2*>(&v0.y));
            float2 c01 = __half22float2(*reinterpret_cast<__half2*>(&v1.x));
            float2 c23 = __half22float2(*reinterpret_cast<__half2*>(&v1.y));
            acc0.x += a01.x; acc0.y += a01.y; acc0.z += a23.x; acc0.w += a23.y;
            acc1.x += c01.x; acc1.y += c01.y; acc1.z += c23.x; acc1.w += c23.y;
        }
        if (i < en) {
            int h0i = g_csrF[p][i];
            uint2 v0 = *reinterpret_cast<const uint2*>(&h[(size_t)h0i * HD + lane * 4]);
            float2 a01 = __half22float2(*reinterpret_cast<__half2*>(&v0.x));
            float2 a23 = __half22float2(*reinterpret_cast<__half2*>(&v0.y));
            acc0.x += a01.x; acc0.y += a01.y; acc0.z += a23.x; acc0.w += a23.y;
        }
        if (en > st) {
            float inv = 1.f / (float)(en - st);
            tot.x += (acc0.x + acc1.x) * inv; tot.y += (acc0.y + acc1.y) * inv;
            tot.z += (acc0.z + acc1.z) * inv; tot.w += (acc0.w + acc1.w) * inv;
        }
    }
    uint2 o;
    *reinterpret_cast<__half2*>(&o.x) = __floats2half2_rn(tot.x, tot.y);
    *reinterpret_cast<__half2*>(&o.y) = __floats2half2_rn(tot.z, tot.w);
    *reinterpret_cast<uint2*>(&g_spsum[(size_t)s * HD + lane * 4]) = o;
}

// ---------------- nexus backward (2-way unrolled) ----------------
__global__ void nexus_back() {
    int p = blockIdx.y;
    int warp = (blockIdx.x * blockDim.x + threadIdx.x) >> 5;
    if (warp >= NHIT) return;
    int lane = threadIdx.x & 31;
    int n = warp;
    int st = g_offB[p][n], en = g_offB[p][n + 1];
    float4 acc0 = make_float4(0.f, 0.f, 0.f, 0.f);
    float4 acc1 = make_float4(0.f, 0.f, 0.f, 0.f);
    int i = st;
    for (; i + 2 <= en; i += 2) {
        int s0 = g_csrB[p][i], s1 = g_csrB[p][i + 1];
        uint2 v0 = *reinterpret_cast<const uint2*>(&g_sp[(size_t)s0 * HD + lane * 4]);
        uint2 v1 = *reinterpret_cast<const uint2*>(&g_sp[(size_t)s1 * HD + lane * 4]);
        float2 a01 = __half22float2(*reinterpret_cast<__half2*>(&v0.x));
        float2 a23 = __half22float2(*reinterpret_cast<__half2*>(&v0.y));
        float2 c01 = __half22float2(*reinterpret_cast<__half2*>(&v1.x));
        float2 c23 = __half22float2(*reinterpret_cast<__half2*>(&v1.y));
        acc0.x += a01.x; acc0.y += a01.y; acc0.z += a23.x; acc0.w += a23.y;
        acc1.x += c01.x; acc1.y += c01.y; acc1.z += c23.x; acc1.w += c23.y;
    }
    if (i < en) {
        int s0 = g_csrB[p][i];
        uint2 v0 = *reinterpret_cast<const uint2*>(&g_sp[(size_t)s0 * HD + lane * 4]);
        float2 a01 = __half22float2(*reinterpret_cast<__half2*>(&v0.x));
        float2 a23 = __half22float2(*reinterpret_cast<__half2*>(&v0.y));
        acc0.x += a01.x; acc0.y += a01.y; acc0.z += a23.x; acc0.w += a23.y;
    }
    float inv = (en > st) ? 1.f / (float)(en - st) : 0.f;
    uint2 o;
    *reinterpret_cast<__half2*>(&o.x) =
        __floats2half2_rn((acc0.x + acc1.x) * inv, (acc0.y + acc1.y) * inv);
    *reinterpret_cast<__half2*>(&o.y) =
        __floats2half2_rn((acc0.z + acc1.z) * inv, (acc0.w + acc1.w) * inv);
    *reinterpret_cast<uint2*>(&g_back[p][(size_t)n * HD + lane * 4]) = o;
}

// ---------------- decoder ----------------
__global__ void decoder_k(const float* __restrict__ hbase, const float* __restrict__ Wsem,
                          const float* __restrict__ bsem, float* __restrict__ out) {
    int p = blockIdx.y;
    const float* h = hbase + (size_t)p * PSTRIDE;
    float* o = out + (size_t)p * NHIT * NCLASS;
    int warp = (blockIdx.x * blockDim.x + threadIdx.x) >> 5;
    if (warp >= NHIT) return;
    int lane = threadIdx.x & 31;
    int n = warp;
    float hv[4];
    #pragma unroll
    for (int t = 0; t < 4; t++) hv[t] = h[(size_t)n * HD + lane + t * 32];
    #pragma unroll
    for (int c = 0; c < NCLASS; c++) {
        float s = 0.f;
        #pragma unroll
        for (int t = 0; t < 4; t++) s = fmaf(hv[t], Wsem[(lane + t * 32) * NCLASS + c], s);
        #pragma unroll
        for (int d = 16; d > 0; d >>= 1) s += __shfl_down_sync(0xffffffffu, s, d);
        if (lane == 0) o[n * NCLASS + c] = s + bsem[c];
    }
}

// ---------------- host ----------------
extern "C" void kernel_launch(void* const* d_in, const int* in_sizes, int n_in,
                              void* d_out, int out_size) {
    int xi[3], ei[3], ni[3];
    if (in_sizes[1] == 2 * NEDGE) {
        for (int p = 0; p < 3; p++) { xi[p] = 3 * p; ei[p] = 3 * p + 1; ni[p] = 3 * p + 2; }
    } else {
        for (int p = 0; p < 3; p++) { xi[p] = p; ei[p] = 3 + p; ni[p] = 6 + p; }
    }
    const float* x[3]; const int* edge[3]; const int* nexus[3];
    for (int p = 0; p < 3; p++) {
        x[p] = (const float*)d_in[xi[p]];
        edge[p] = (const int*)d_in[ei[p]];
        nexus[p] = (const int*)d_in[ni[p]];
    }
    const float* W_enc  = (const float*)d_in[9];
    const float* b_enc  = (const float*)d_in[10];
    const float* W_msg1 = (const float*)d_in[11];
    const float* b_msg1 = (const float*)d_in[12];
    const float* W_msg2 = (const float*)d_in[13];
    const float* b_msg2 = (const float*)d_in[14];
    const float* W_upd  = (const float*)d_in[15];
    const float* b_upd  = (const float*)d_in[16];
    const float* W_sp   = (const float*)d_in[17];
    const float* b_sp   = (const float*)d_in[18];
    const float* W_nx   = (const float*)d_in[19];
    const float* b_nx   = (const float*)d_in[20];
    const float* W_sem  = (const float*)d_in[21];
    const float* b_sem  = (const float*)d_in[22];

    float *ph, *pwcomb, *pb2c; int* pdeg;
    __half *ph16, *pA, *pB, *pmr, *pspsum, *psp, *pback;
    cudaGetSymbolAddress((void**)&ph, g_h);
    cudaGetSymbolAddress((void**)&ph16, g_h16);
    cudaGetSymbolAddress((void**)&pA, g_A);
    cudaGetSymbolAddress((void**)&pB, g_B);
    cudaGetSymbolAddress((void**)&pmr, g_mr);
    cudaGetSymbolAddress((void**)&pspsum, g_spsum);
    cudaGetSymbolAddress((void**)&psp, g_sp);
    cudaGetSymbolAddress((void**)&pback, g_back);
    cudaGetSymbolAddress((void**)&pwcomb, g_wcomb);
    cudaGetSymbolAddress((void**)&pb2c, g_b2c);
    cudaGetSymbolAddress((void**)&pdeg, g_deg);

    cudaFuncSetAttribute(gemm_mma, cudaFuncAttributeMaxDynamicSharedMemorySize, SM_TOTAL);
    cudaFuncSetAttribute(gemm_dual, cudaFuncAttributeMaxDynamicSharedMemorySize, DU_TOTAL);

    float* h0 = ph;
    float* h1 = ph + (size_t)3 * PSTRIDE;
    __half* h16_0 = ph16;
    __half* h16_1 = ph16 + (size_t)3 * PSTRIDE;

    const int T = 256;
    dim3 gG3((NHIT + 127) / 128, 3);
    dim3 gG1((NSP + 127) / 128, 1);
    dim3 gW3((NHIT * 32 + T - 1) / T, 3);
    int gW1 = (NSP * 32 + T - 1) / T;
    dim3 gE((NHIT * HD + T - 1) / T, 3);

    // --- CSR build ---
    zero_counts<<<(NHIT + T - 1) / T, T>>>();
    dim3 gCnt((NEDGE + T - 1) / T, 3);
    count_all<<<gCnt, T>>>(edge[0], edge[1], edge[2], nexus[0], nexus[1], nexus[2]);
    scan_excl_all<<<9, 1024>>>();
    fill_all<<<gCnt, T>>>(edge[0], edge[1], edge[2], nexus[0], nexus[1], nexus[2]);

    // --- weight combine + prep (0=W1top 1=W1bot 2=WupdT 3=comb 4=Wsp 5=WnxT 6=WnxB) ---
    combine_w<<<129, 128>>>(W_msg2, W_upd + 128 * 128, b_msg2);
    prep_w<<<224, 256>>>(W_msg1, W_msg1 + 128 * 128, W_upd, pwcomb,
                         W_sp, W_nx, W_nx + 128 * 128);

    // --- encoder ---
    encoder_k<<<gE, T>>>(x[0], x[1], x[2], W_enc, b_enc, h0, h16_0);

    for (int it = 0; it < 3; it++) {
        gemm_dual<<<gG3, T, DU_TOTAL>>>(h16_0, PSTRIDE, 0, 1, pA, pB, NHIT);
        planar_agg<<<gW3, T>>>(b_msg1);
        gemm_mma<<<gG3, T, SM_TOTAL>>>(h16_0, pmr, PSTRIDE, 2, 2, b_upd, pb2c,
                                       pdeg, NHIT, h0, h1, h16_1, NHIT, EPI_RESRELU_DEG);
        nexus_fwd<<<gW1, T>>>(h16_1);
        gemm_mma<<<gG1, T, SM_TOTAL>>>(pspsum, nullptr, 0, 4, 1, b_sp, nullptr,
                                       nullptr, 0, nullptr, nullptr, psp, NSP, EPI_RELU);
        nexus_back<<<gW3, T>>>();
        gemm_mma<<<gG3, T, SM_TOTAL>>>(h16_1, pback, PSTRIDE, 5, 2, b_nx, nullptr,
                                       nullptr, 0, h1, h0, h16_0, NHIT, EPI_RESRELU);
    }

    decoder_k<<<gW3, T>>>(h0, W_sem, b_sem, (float*)d_out);
}

// round 13
// speedup vs baseline: 1.5473x; 1.0822x over previous
#include <cuda_runtime.h>
#include <cuda_fp16.h>
#include <cstdint>

#define NHIT 30000
#define NEDGE 90000
#define NSP 30000
#define HD 128
#define NCLASS 5
#define PSTRIDE (NHIT * HD)

// ---------------- device scratch ----------------
__device__ __half g_h16[2][3][NHIT * HD];       // fp16 hidden state (ping-pong)
__device__ __half g_A[3][NHIT * HD];
__device__ __half g_B[3][NHIT * HD];
__device__ __half g_mr[3][NHIT * HD];
__device__ __half g_spsum[NSP * HD];
__device__ __half g_sp[NSP * HD];
__device__ __half g_back[3][NHIT * HD];
__device__ float g_wcomb[HD * HD];              // W_msg2 @ W_upd_bottom
__device__ float g_b2c[HD];                     // b_msg2 @ W_upd_bottom

// prepped weights: 7 chunks x {hi,lo} x 2 k-stages x (128n x 64k fp16, swizzled)
__device__ uint4 g_wbuf[7][2][2][1024];

__device__ int g_deg[3][NHIT];
__device__ int g_cf[3][NSP];
__device__ int g_cb[3][NHIT];
__device__ int g_offE[3][NHIT + 1];
__device__ int g_offF[3][NSP + 1];
__device__ int g_offB[3][NHIT + 1];
__device__ int g_csrE[3][NEDGE];
__device__ int g_csrF[3][NSP];
__device__ int g_csrB[3][NSP];
__device__ int g_curE[3][NHIT];
__device__ int g_curF[3][NSP];
__device__ int g_curB[3][NHIT];

enum { EPI_RELU = 1, EPI_RESRELU = 2, EPI_RESRELU_DEG = 4 };

// ---------------- helpers ----------------
__device__ __forceinline__ uint32_t s2u(const void* p) {
    return (uint32_t)__cvta_generic_to_shared(p);
}
__device__ __forceinline__ uint32_t pack2h(float a, float b) {
    __half2 t = __floats2half2_rn(a, b);
    return *reinterpret_cast<uint32_t*>(&t);
}
__device__ __forceinline__ float lopart(float v) {
    return v - __half2float(__float2half(v));
}
__device__ __forceinline__ uint32_t swz(int row, int k) {
    return (uint32_t)(row * 128 + ((((k >> 3) ^ row) & 7) << 4) + (k & 7) * 2);
}
__device__ __forceinline__ void ldsm4(uint32_t* r, uint32_t addr) {
    asm volatile("ldmatrix.sync.aligned.m8n8.x4.shared.b16 {%0,%1,%2,%3}, [%4];"
                 : "=r"(r[0]), "=r"(r[1]), "=r"(r[2]), "=r"(r[3]) : "r"(addr));
}
__device__ __forceinline__ void mma16816(float* c, const uint32_t* a, uint32_t b0, uint32_t b1) {
    asm volatile(
        "mma.sync.aligned.m16n8k16.row.col.f32.f16.f16.f32 "
        "{%0,%1,%2,%3}, {%4,%5,%6,%7}, {%8,%9}, {%0,%1,%2,%3};"
        : "+f"(c[0]), "+f"(c[1]), "+f"(c[2]), "+f"(c[3])
        : "r"(a[0]), "r"(a[1]), "r"(a[2]), "r"(a[3]), "r"(b0), "r"(b1));
}
__device__ __forceinline__ void cpa8(uint32_t dst, const void* src) {
    asm volatile("cp.async.ca.shared.global [%0], [%1], 8;" :: "r"(dst), "l"(src));
}
__device__ __forceinline__ void cpa16(uint32_t dst, const void* src) {
    asm volatile("cp.async.cg.shared.global [%0], [%1], 16;" :: "r"(dst), "l"(src));
}
#define CP_COMMIT() asm volatile("cp.async.commit_group;")
#define CP_WAIT1()  asm volatile("cp.async.wait_group 1;")
#define CP_WAIT0()  asm volatile("cp.async.wait_group 0;")

// gemm_mma: 2 pipeline buffers x [A 16K | BHI 16K | BLO 16K]
#define PB_A 0
#define PB_BHI 16384
#define PB_BLO 32768
#define PB_SZ 49152
#define SM_TOTAL 98304
// gemm_dual: A (both halves) 32K + 2 B-buffers x [BHI 16K | BLO 16K]
#define DU_A 0
#define DU_B 32768
#define DU_BSZ 32768
#define DU_TOTAL 98304

// ---------------- weight combine ----------------
__global__ void combine_w(const float* __restrict__ W2, const float* __restrict__ Wub,
                          const float* __restrict__ b2) {
    int n = threadIdx.x;
    int k = blockIdx.x;
    if (k < 128) {
        float s = 0.f;
        #pragma unroll 8
        for (int j = 0; j < 128; j++) s = fmaf(W2[k * 128 + j], Wub[j * 128 + n], s);
        g_wcomb[k * 128 + n] = s;
    } else {
        float s = 0.f;
        #pragma unroll 8
        for (int j = 0; j < 128; j++) s = fmaf(b2[j], Wub[j * 128 + n], s);
        g_b2c[n] = s;
    }
}

// ---------------- weight prep ----------------
__global__ void prep_w(const float* w0, const float* w1, const float* w2,
                       const float* w3, const float* w4, const float* w5,
                       const float* w6) {
    int id = blockIdx.x * blockDim.x + threadIdx.x;
    if (id >= 7 * 8192) return;
    int c = id >> 13;
    int rem = id & 8191;
    int s = rem >> 12;
    int rem2 = rem & 4095;
    int n = rem2 >> 5;
    int kp = (rem2 & 31) * 2;
    const float* Wc = (c == 0) ? w0 : (c == 1) ? w1 : (c == 2) ? w2 : (c == 3) ? w3
                    : (c == 4) ? w4 : (c == 5) ? w5 : w6;
    float v0 = Wc[(s * 64 + kp) * 128 + n];
    float v1 = Wc[(s * 64 + kp + 1) * 128 + n];
    uint32_t o = swz(n, kp);
    *reinterpret_cast<uint32_t*>((char*)&g_wbuf[c][0][s][0] + o) = pack2h(v0, v1);
    *reinterpret_cast<uint32_t*>((char*)&g_wbuf[c][1][s][0] + o) = pack2h(lopart(v0), lopart(v1));
}

// ---------------- HMMA 2-pass GEMM, cp.async double-buffered ----------------
__global__ __launch_bounds__(256, 2) void gemm_mma(
    const __half* __restrict__ Ah0, const __half* __restrict__ Ah1,
    int sA, int wc0, int nchunks,
    const float* __restrict__ bias, const float* __restrict__ bias2,
    const int* __restrict__ mask, int sMask,
    const __half* __restrict__ resid,
    __half* __restrict__ outh, int M, int epi)
{
    extern __shared__ char smem[];
    uint32_t sb = s2u(smem);
    int tid = threadIdx.x;
    int wid = tid >> 5, lane = tid & 31;
    int mwarp = wid & 3, nwarp = wid >> 2;
    int row0 = blockIdx.x * 128;
    int pl = blockIdx.y;
    const __half* Ah0p = Ah0 + (size_t)pl * sA;
    const __half* Ah1p = Ah1 ? (Ah1 + (size_t)pl * sA) : nullptr;
    const __half* residp = resid ? (resid + (size_t)pl * sA) : nullptr;
    const int* maskp = mask ? (mask + (size_t)pl * sMask) : nullptr;

    float C[2][8][4];
    #pragma unroll
    for (int mt = 0; mt < 2; mt++)
        #pragma unroll
        for (int nt = 0; nt < 8; nt++)
            #pragma unroll
            for (int q = 0; q < 4; q++) C[mt][nt][q] = 0.f;

    int a_row_in16 = (lane & 7) + ((lane >> 3) & 1) * 8;
    int a_kb = (lane >> 4) & 1;
    int b_row_in16 = (lane & 7) + ((lane >> 4) & 1) * 8;
    int b_kb = (lane >> 3) & 1;

    int nst = nchunks * 2;

    auto prefetch = [&](int s) {
        int ch = s >> 1, kh = s & 1;
        const __half* src = ch ? Ah1p : Ah0p;
        uint32_t bb = sb + (uint32_t)((s & 1) * PB_SZ);
        #pragma unroll
        for (int l = 0; l < 8; l++) {
            int i = l * 256 + tid;
            int r = i >> 4, c4 = (i & 15) * 4;
            int row = row0 + r; if (row >= M) row = M - 1;
            cpa8(bb + PB_A + swz(r, c4), &src[(size_t)row * 128 + kh * 64 + c4]);
        }
        const uint4* bh = &g_wbuf[wc0 + ch][0][kh][0];
        const uint4* bl = &g_wbuf[wc0 + ch][1][kh][0];
        #pragma unroll
        for (int l = 0; l < 4; l++) {
            int i = l * 256 + tid;
            cpa16(bb + PB_BHI + (uint32_t)i * 16, bh + i);
            cpa16(bb + PB_BLO + (uint32_t)i * 16, bl + i);
        }
        CP_COMMIT();
    };

    prefetch(0);
    for (int s = 0; s < nst; s++) {
        if (s + 1 < nst) { prefetch(s + 1); CP_WAIT1(); }
        else             { CP_WAIT0(); }
        __syncthreads();
        uint32_t ab = sb + (uint32_t)((s & 1) * PB_SZ);

        #pragma unroll
        for (int k16 = 0; k16 < 4; k16++) {
            uint32_t a[2][4];
            #pragma unroll
            for (int mt = 0; mt < 2; mt++) {
                int row = mwarp * 32 + mt * 16 + a_row_in16;
                uint32_t o = (uint32_t)(row * 128 + ((((k16 * 2 + a_kb) ^ row) & 7) << 4));
                ldsm4(a[mt], ab + PB_A + o);
            }
            #pragma unroll
            for (int ntp = 0; ntp < 4; ntp++) {
                int nrow = nwarp * 64 + ntp * 16 + b_row_in16;
                uint32_t o = (uint32_t)(nrow * 128 + ((((k16 * 2 + b_kb) ^ nrow) & 7) << 4));
                uint32_t bhi[4], blo[4];
                ldsm4(bhi, ab + PB_BHI + o);
                ldsm4(blo, ab + PB_BLO + o);
                #pragma unroll
                for (int half = 0; half < 2; half++) {
                    int nt = ntp * 2 + half;
                    #pragma unroll
                    for (int mt = 0; mt < 2; mt++) {
                        mma16816(C[mt][nt], a[mt], bhi[half * 2], bhi[half * 2 + 1]);
                        mma16816(C[mt][nt], a[mt], blo[half * 2], blo[half * 2 + 1]);
                    }
                }
            }
        }
        __syncthreads();
    }

    int qrow = lane >> 2;
    int qcol = (lane & 3) * 2;
    #pragma unroll
    for (int mt = 0; mt < 2; mt++) {
        #pragma unroll
        for (int half = 0; half < 2; half++) {
            int row = row0 + mwarp * 32 + mt * 16 + qrow + half * 8;
            if (row >= M) continue;
            bool dg = (epi == EPI_RESRELU_DEG) ? (maskp[row] > 0) : false;
            #pragma unroll
            for (int nt = 0; nt < 8; nt++) {
                int col = nwarp * 64 + nt * 8 + qcol;
                float v0 = C[mt][nt][half * 2 + 0];
                float v1 = C[mt][nt][half * 2 + 1];
                float o0, o1;
                if (epi == EPI_RELU) {
                    o0 = fmaxf(v0 + bias[col], 0.f);
                    o1 = fmaxf(v1 + bias[col + 1], 0.f);
                } else {
                    float e0 = v0 + bias[col], e1 = v1 + bias[col + 1];
                    if (epi == EPI_RESRELU_DEG && dg) { e0 += bias2[col]; e1 += bias2[col + 1]; }
                    float2 rr = __half22float2(
                        *reinterpret_cast<const __half2*>(&residp[(size_t)row * 128 + col]));
                    o0 = rr.x + fmaxf(e0, 0.f);
                    o1 = rr.y + fmaxf(e1, 0.f);
                }
                *reinterpret_cast<__half2*>(&outh[(size_t)pl * sA + (size_t)row * 128 + col]) =
                    __floats2half2_rn(o0, o1);
            }
        }
    }
}

// ---------------- dual-output GEMM, cp.async pipelined B ----------------
__global__ __launch_bounds__(256, 2) void gemm_dual(
    const __half* __restrict__ A, int sA, int wc0, int wc1,
    __half* __restrict__ out0, __half* __restrict__ out1, int M)
{
    extern __shared__ char smem[];
    uint32_t sb = s2u(smem);
    int tid = threadIdx.x;
    int wid = tid >> 5, lane = tid & 31;
    int mwarp = wid & 3, nwarp = wid >> 2;
    int row0 = blockIdx.x * 128;
    int pl = blockIdx.y;
    const __half* Ap = A + (size_t)pl * sA;
    __half* o0 = out0 + (size_t)pl * sA;
    __half* o1 = out1 + (size_t)pl * sA;

    int a_row_in16 = (lane & 7) + ((lane >> 3) & 1) * 8;
    int a_kb = (lane >> 4) & 1;
    int b_row_in16 = (lane & 7) + ((lane >> 4) & 1) * 8;
    int b_kb = (lane >> 3) & 1;
    int qrow = lane >> 2;
    int qcol = (lane & 3) * 2;

    auto prefetchB = [&](int s) {
        int w = s >> 1, kh = s & 1;
        int wc = w ? wc1 : wc0;
        uint32_t bb = sb + DU_B + (uint32_t)((s & 1) * DU_BSZ);
        const uint4* bh = &g_wbuf[wc][0][kh][0];
        const uint4* bl = &g_wbuf[wc][1][kh][0];
        #pragma unroll
        for (int l = 0; l < 4; l++) {
            int i = l * 256 + tid;
            cpa16(bb + (uint32_t)i * 16, bh + i);
            cpa16(bb + 16384 + (uint32_t)i * 16, bl + i);
        }
        CP_COMMIT();
    };

    #pragma unroll
    for (int l = 0; l < 16; l++) {
        int i = l * 256 + tid;
        int r = i >> 5, c4 = (i & 31) * 4;
        int sh = c4 >> 6, k = c4 & 63;
        int row = row0 + r; if (row >= M) row = M - 1;
        cpa8(sb + DU_A + sh * 16384 + swz(r, k), &Ap[(size_t)row * 128 + c4]);
    }
    prefetchB(0);

    float C[2][8][4];
    for (int s = 0; s < 4; s++) {
        if (s + 1 < 4) { prefetchB(s + 1); CP_WAIT1(); }
        else           { CP_WAIT0(); }
        __syncthreads();

        if ((s & 1) == 0) {
            #pragma unroll
            for (int mt = 0; mt < 2; mt++)
                #pragma unroll
                for (int nt = 0; nt < 8; nt++)
                    #pragma unroll
                    for (int q = 0; q < 4; q++) C[mt][nt][q] = 0.f;
        }

        uint32_t abase = sb + DU_A + (uint32_t)((s & 1) * 16384);
        uint32_t bbase = sb + DU_B + (uint32_t)((s & 1) * DU_BSZ);
        #pragma unroll
        for (int k16 = 0; k16 < 4; k16++) {
            uint32_t a[2][4];
            #pragma unroll
            for (int mt = 0; mt < 2; mt++) {
                int row = mwarp * 32 + mt * 16 + a_row_in16;
                uint32_t o = (uint32_t)(row * 128 + ((((k16 * 2 + a_kb) ^ row) & 7) << 4));
                ldsm4(a[mt], abase + o);
            }
            #pragma unroll
            for (int ntp = 0; ntp < 4; ntp++) {
                int nrow = nwarp * 64 + ntp * 16 + b_row_in16;
                uint32_t o = (uint32_t)(nrow * 128 + ((((k16 * 2 + b_kb) ^ nrow) & 7) << 4));
                uint32_t bhi[4], blo[4];
                ldsm4(bhi, bbase + o);
                ldsm4(blo, bbase + 16384 + o);
                #pragma unroll
                for (int half = 0; half < 2; half++) {
                    int nt = ntp * 2 + half;
                    #pragma unroll
                    for (int mt = 0; mt < 2; mt++) {
                        mma16816(C[mt][nt], a[mt], bhi[half * 2], bhi[half * 2 + 1]);
                        mma16816(C[mt][nt], a[mt], blo[half * 2], blo[half * 2 + 1]);
                    }
                }
            }
        }
        __syncthreads();

        if (s & 1) {
            __half* op = (s >> 1) ? o1 : o0;
            #pragma unroll
            for (int mt = 0; mt < 2; mt++) {
                #pragma unroll
                for (int half = 0; half < 2; half++) {
                    int row = row0 + mwarp * 32 + mt * 16 + qrow + half * 8;
                    if (row >= M) continue;
                    #pragma unroll
                    for (int nt = 0; nt < 8; nt++) {
                        int col = nwarp * 64 + nt * 8 + qcol;
                        *reinterpret_cast<__half2*>(&op[(size_t)row * 128 + col]) =
                            __floats2half2_rn(C[mt][nt][half * 2], C[mt][nt][half * 2 + 1]);
                    }
                }
            }
        }
    }
}

// ---------------- CSR build ----------------
__global__ void zero_counts() {
    int i = blockIdx.x * blockDim.x + threadIdx.x;
    if (i < NHIT) {
        #pragma unroll
        for (int p = 0; p < 3; p++) { g_deg[p][i] = 0; g_cb[p][i] = 0; }
    }
    if (i < NSP) {
        #pragma unroll
        for (int p = 0; p < 3; p++) g_cf[p][i] = 0;
    }
}

__global__ void count_all(const int* __restrict__ e0, const int* __restrict__ e1,
                          const int* __restrict__ e2, const int* __restrict__ n0,
                          const int* __restrict__ n1, const int* __restrict__ n2) {
    int p = blockIdx.y;
    const int* e = (p == 0) ? e0 : (p == 1) ? e1 : e2;
    const int* nx = (p == 0) ? n0 : (p == 1) ? n1 : n2;
    int i = blockIdx.x * blockDim.x + threadIdx.x;
    if (i < NEDGE) atomicAdd(&g_deg[p][e[NEDGE + i]], 1);
    if (i < NSP) {
        atomicAdd(&g_cf[p][nx[NSP + i]], 1);
        atomicAdd(&g_cb[p][nx[i]], 1);
    }
}

__global__ void scan_excl_all() {
    int sel = blockIdx.x / 3, p = blockIdx.x % 3;
    const int* in; int* out; int* cur; int n;
    if (sel == 0)      { in = g_deg[p]; out = g_offE[p]; cur = g_curE[p]; n = NHIT; }
    else if (sel == 1) { in = g_cf[p];  out = g_offF[p]; cur = g_curF[p]; n = NSP; }
    else               { in = g_cb[p];  out = g_offB[p]; cur = g_curB[p]; n = NHIT; }
    __shared__ int wsum[32];
    __shared__ int carry;
    int tid = threadIdx.x;
    if (tid == 0) carry = 0;
    __syncthreads();
    for (int base = 0; base < n; base += 1024) {
        int i = base + tid;
        int v = (i < n) ? in[i] : 0;
        int x = v;
        #pragma unroll
        for (int d = 1; d < 32; d <<= 1) {
            int y = __shfl_up_sync(0xffffffffu, x, d);
            if ((tid & 31) >= d) x += y;
        }
        if ((tid & 31) == 31) wsum[tid >> 5] = x;
        __syncthreads();
        if (tid < 32) {
            int s = wsum[tid];
            #pragma unroll
            for (int d = 1; d < 32; d <<= 1) {
                int y = __shfl_up_sync(0xffffffffu, s, d);
                if (tid >= d) s += y;
            }
            wsum[tid] = s;
        }
        __syncthreads();
        int woff = (tid >= 32) ? wsum[(tid >> 5) - 1] : 0;
        int incl = carry + woff + x;
        if (i < n) { out[i] = incl - v; cur[i] = incl - v; }
        __syncthreads();
        if (tid == 1023) carry = incl;
        __syncthreads();
    }
    if (tid == 0) out[n] = carry;
}

__global__ void fill_all(const int* __restrict__ e0, const int* __restrict__ e1,
                         const int* __restrict__ e2, const int* __restrict__ n0,
                         const int* __restrict__ n1, const int* __restrict__ n2) {
    int p = blockIdx.y;
    const int* e = (p == 0) ? e0 : (p == 1) ? e1 : e2;
    const int* nx = (p == 0) ? n0 : (p == 1) ? n1 : n2;
    int i = blockIdx.x * blockDim.x + threadIdx.x;
    if (i < NEDGE) {
        int dst = e[NEDGE + i];
        g_csrE[p][atomicAdd(&g_curE[p][dst], 1)] = e[i];
    }
    if (i < NSP) {
        int s = nx[NSP + i];
        g_csrF[p][atomicAdd(&g_curF[p][s], 1)] = nx[i];
        int h = nx[i];
        g_csrB[p][atomicAdd(&g_curB[p][h], 1)] = nx[NSP + i];
    }
}

// ---------------- encoder (fp16 state) ----------------
__global__ void encoder_k(const float* __restrict__ x0, const float* __restrict__ x1,
                          const float* __restrict__ x2, const float* __restrict__ W,
                          const float* __restrict__ b, __half* __restrict__ h16base) {
    int p = blockIdx.y;
    const float* x = (p == 0) ? x0 : (p == 1) ? x1 : x2;
    int idx = blockIdx.x * blockDim.x + threadIdx.x;
    if (idx >= NHIT * HD) return;
    int n = idx >> 7, j = idx & 127;
    float acc = b[j];
    #pragma unroll
    for (int k = 0; k < 4; k++) acc = fmaf(x[n * 4 + k], W[k * HD + j], acc);
    acc = fmaxf(acc, 0.f);
    h16base[(size_t)p * PSTRIDE + idx] = __float2half(acc);
}

// ---------------- planar edge aggregation (2-way unrolled MLP) ----------------
__global__ void planar_agg(const float* __restrict__ b1) {
    int p = blockIdx.y;
    int warp = (blockIdx.x * blockDim.x + threadIdx.x) >> 5;
    if (warp >= NHIT) return;
    int lane = threadIdx.x & 31;
    int n = warp;
    uint2 ar = *reinterpret_cast<const uint2*>(&g_A[p][(size_t)n * HD + lane * 4]);
    float2 a01 = __half22float2(*reinterpret_cast<__half2*>(&ar.x));
    float2 a23 = __half22float2(*reinterpret_cast<__half2*>(&ar.y));
    float4 bb = *reinterpret_cast<const float4*>(&b1[lane * 4]);
    int s = g_offE[p][n], e = g_offE[p][n + 1];
    float4 acc0 = make_float4(0.f, 0.f, 0.f, 0.f);
    float4 acc1 = make_float4(0.f, 0.f, 0.f, 0.f);
    int i = s;
    for (; i + 2 <= e; i += 2) {
        int s0 = g_csrE[p][i], s1 = g_csrE[p][i + 1];
        uint2 br0 = *reinterpret_cast<const uint2*>(&g_B[p][(size_t)s0 * HD + lane * 4]);
        uint2 br1 = *reinterpret_cast<const uint2*>(&g_B[p][(size_t)s1 * HD + lane * 4]);
        float2 b001 = __half22float2(*reinterpret_cast<__half2*>(&br0.x));
        float2 b023 = __half22float2(*reinterpret_cast<__half2*>(&br0.y));
        float2 b101 = __half22float2(*reinterpret_cast<__half2*>(&br1.x));
        float2 b123 = __half22float2(*reinterpret_cast<__half2*>(&br1.y));
        acc0.x += fmaxf(a01.x + b001.x + bb.x, 0.f);
        acc0.y += fmaxf(a01.y + b001.y + bb.y, 0.f);
        acc0.z += fmaxf(a23.x + b023.x + bb.z, 0.f);
        acc0.w += fmaxf(a23.y + b023.y + bb.w, 0.f);
        acc1.x += fmaxf(a01.x + b101.x + bb.x, 0.f);
        acc1.y += fmaxf(a01.y + b101.y + bb.y, 0.f);
        acc1.z += fmaxf(a23.x + b123.x + bb.z, 0.f);
        acc1.w += fmaxf(a23.y + b123.y + bb.w, 0.f);
    }
    if (i < e) {
        int s0 = g_csrE[p][i];
        uint2 br0 = *reinterpret_cast<const uint2*>(&g_B[p][(size_t)s0 * HD + lane * 4]);
        float2 b001 = __half22float2(*reinterpret_cast<__half2*>(&br0.x));
        float2 b023 = __half22float2(*reinterpret_cast<__half2*>(&br0.y));
        acc0.x += fmaxf(a01.x + b001.x + bb.x, 0.f);
        acc0.y += fmaxf(a01.y + b001.y + bb.y, 0.f);
        acc0.z += fmaxf(a23.x + b023.x + bb.z, 0.f);
        acc0.w += fmaxf(a23.y + b023.y + bb.w, 0.f);
    }
    float4 acc = make_float4(acc0.x + acc1.x, acc0.y + acc1.y,
                             acc0.z + acc1.z, acc0.w + acc1.w);
    float inv = (e > s) ? 1.f / (float)(e - s) : 0.f;
    uint2 o;
    *reinterpret_cast<__half2*>(&o.x) = __floats2half2_rn(acc.x * inv, acc.y * inv);
    *reinterpret_cast<__half2*>(&o.y) = __floats2half2_rn(acc.z * inv, acc.w * inv);
    *reinterpret_cast<uint2*>(&g_mr[p][(size_t)n * HD + lane * 4]) = o;
}

// ---------------- nexus forward (2-way unrolled) ----------------
__global__ void nexus_fwd(const __half* __restrict__ h16base) {
    int warp = (blockIdx.x * blockDim.x + threadIdx.x) >> 5;
    if (warp >= NSP) return;
    int lane = threadIdx.x & 31;
    int s = warp;
    float4 tot = make_float4(0.f, 0.f, 0.f, 0.f);
    #pragma unroll
    for (int p = 0; p < 3; p++) {
        const __half* h = h16base + (size_t)p * PSTRIDE;
        int st = g_offF[p][s], en = g_offF[p][s + 1];
        float4 acc0 = make_float4(0.f, 0.f, 0.f, 0.f);
        float4 acc1 = make_float4(0.f, 0.f, 0.f, 0.f);
        int i = st;
        for (; i + 2 <= en; i += 2) {
            int h0i = g_csrF[p][i], h1i = g_csrF[p][i + 1];
            uint2 v0 = *reinterpret_cast<const uint2*>(&h[(size_t)h0i * HD + lane * 4]);
            uint2 v1 = *reinterpret_cast<const uint2*>(&h[(size_t)h1i * HD + lane * 4]);
            float2 a01 = __half22float2(*reinterpret_cast<__half2*>(&v0.x));
            float2 a23 = __half22float2(*reinterpret_cast<__half2*>(&v0.y));
            float2 c01 = __half22float2(*reinterpret_cast<__half2*>(&v1.x));
            float2 c23 = __half22float2(*reinterpret_cast<__half2*>(&v1.y));
            acc0.x += a01.x; acc0.y += a01.y; acc0.z += a23.x; acc0.w += a23.y;
            acc1.x += c01.x; acc1.y += c01.y; acc1.z += c23.x; acc1.w += c23.y;
        }
        if (i < en) {
            int h0i = g_csrF[p][i];
            uint2 v0 = *reinterpret_cast<const uint2*>(&h[(size_t)h0i * HD + lane * 4]);
            float2 a01 = __half22float2(*reinterpret_cast<__half2*>(&v0.x));
            float2 a23 = __half22float2(*reinterpret_cast<__half2*>(&v0.y));
            acc0.x += a01.x; acc0.y += a01.y; acc0.z += a23.x; acc0.w += a23.y;
        }
        if (en > st) {
            float inv = 1.f / (float)(en - st);
            tot.x += (acc0.x + acc1.x) * inv; tot.y += (acc0.y + acc1.y) * inv;
            tot.z += (acc0.z + acc1.z) * inv; tot.w += (acc0.w + acc1.w) * inv;
        }
    }
    uint2 o;
    *reinterpret_cast<__half2*>(&o.x) = __floats2half2_rn(tot.x, tot.y);
    *reinterpret_cast<__half2*>(&o.y) = __floats2half2_rn(tot.z, tot.w);
    *reinterpret_cast<uint2*>(&g_spsum[(size_t)s * HD + lane * 4]) = o;
}

// ---------------- nexus backward (2-way unrolled) ----------------
__global__ void nexus_back() {
    int p = blockIdx.y;
    int warp = (blockIdx.x * blockDim.x + threadIdx.x) >> 5;
    if (warp >= NHIT) return;
    int lane = threadIdx.x & 31;
    int n = warp;
    int st = g_offB[p][n], en = g_offB[p][n + 1];
    float4 acc0 = make_float4(0.f, 0.f, 0.f, 0.f);
    float4 acc1 = make_float4(0.f, 0.f, 0.f, 0.f);
    int i = st;
    for (; i + 2 <= en; i += 2) {
        int s0 = g_csrB[p][i], s1 = g_csrB[p][i + 1];
        uint2 v0 = *reinterpret_cast<const uint2*>(&g_sp[(size_t)s0 * HD + lane * 4]);
        uint2 v1 = *reinterpret_cast<const uint2*>(&g_sp[(size_t)s1 * HD + lane * 4]);
        float2 a01 = __half22float2(*reinterpret_cast<__half2*>(&v0.x));
        float2 a23 = __half22float2(*reinterpret_cast<__half2*>(&v0.y));
        float2 c01 = __half22float2(*reinterpret_cast<__half2*>(&v1.x));
        float2 c23 = __half22float2(*reinterpret_cast<__half2*>(&v1.y));
        acc0.x += a01.x; acc0.y += a01.y; acc0.z += a23.x; acc0.w += a23.y;
        acc1.x += c01.x; acc1.y += c01.y; acc1.z += c23.x; acc1.w += c23.y;
    }
    if (i < en) {
        int s0 = g_csrB[p][i];
        uint2 v0 = *reinterpret_cast<const uint2*>(&g_sp[(size_t)s0 * HD + lane * 4]);
        float2 a01 = __half22float2(*reinterpret_cast<__half2*>(&v0.x));
        float2 a23 = __half22float2(*reinterpret_cast<__half2*>(&v0.y));
        acc0.x += a01.x; acc0.y += a01.y; acc0.z += a23.x; acc0.w += a23.y;
    }
    float inv = (en > st) ? 1.f / (float)(en - st) : 0.f;
    uint2 o;
    *reinterpret_cast<__half2*>(&o.x) =
        __floats2half2_rn((acc0.x + acc1.x) * inv, (acc0.y + acc1.y) * inv);
    *reinterpret_cast<__half2*>(&o.y) =
        __floats2half2_rn((acc0.z + acc1.z) * inv, (acc0.w + acc1.w) * inv);
    *reinterpret_cast<uint2*>(&g_back[p][(size_t)n * HD + lane * 4]) = o;
}

// ---------------- decoder (fp16 state in, fp32 out) ----------------
__global__ void decoder_k(const __half* __restrict__ hbase, const float* __restrict__ Wsem,
                          const float* __restrict__ bsem, float* __restrict__ out) {
    int p = blockIdx.y;
    const __half* h = hbase + (size_t)p * PSTRIDE;
    float* o = out + (size_t)p * NHIT * NCLASS;
    int warp = (blockIdx.x * blockDim.x + threadIdx.x) >> 5;
    if (warp >= NHIT) return;
    int lane = threadIdx.x & 31;
    int n = warp;
    float hv[4];
    #pragma unroll
    for (int t = 0; t < 4; t++) hv[t] = __half2float(h[(size_t)n * HD + lane + t * 32]);
    #pragma unroll
    for (int c = 0; c < NCLASS; c++) {
        float s = 0.f;
        #pragma unroll
        for (int t = 0; t < 4; t++) s = fmaf(hv[t], Wsem[(lane + t * 32) * NCLASS + c], s);
        #pragma unroll
        for (int d = 16; d > 0; d >>= 1) s += __shfl_down_sync(0xffffffffu, s, d);
        if (lane == 0) o[n * NCLASS + c] = s + bsem[c];
    }
}

// ---------------- host ----------------
extern "C" void kernel_launch(void* const* d_in, const int* in_sizes, int n_in,
                              void* d_out, int out_size) {
    int xi[3], ei[3], ni[3];
    if (in_sizes[1] == 2 * NEDGE) {
        for (int p = 0; p < 3; p++) { xi[p] = 3 * p; ei[p] = 3 * p + 1; ni[p] = 3 * p + 2; }
    } else {
        for (int p = 0; p < 3; p++) { xi[p] = p; ei[p] = 3 + p; ni[p] = 6 + p; }
    }
    const float* x[3]; const int* edge[3]; const int* nexus[3];
    for (int p = 0; p < 3; p++) {
        x[p] = (const float*)d_in[xi[p]];
        edge[p] = (const int*)d_in[ei[p]];
        nexus[p] = (const int*)d_in[ni[p]];
    }
    const float* W_enc  = (const float*)d_in[9];
    const float* b_enc  = (const float*)d_in[10];
    const float* W_msg1 = (const float*)d_in[11];
    const float* b_msg1 = (const float*)d_in[12];
    const float* W_msg2 = (const float*)d_in[13];
    const float* b_msg2 = (const float*)d_in[14];
    const float* W_upd  = (const float*)d_in[15];
    const float* b_upd  = (const float*)d_in[16];
    const float* W_sp   = (const float*)d_in[17];
    const float* b_sp   = (const float*)d_in[18];
    const float* W_nx   = (const float*)d_in[19];
    const float* b_nx   = (const float*)d_in[20];
    const float* W_sem  = (const float*)d_in[21];
    const float* b_sem  = (const float*)d_in[22];

    float *pwcomb, *pb2c; int* pdeg;
    __half *ph16, *pA, *pB, *pmr, *pspsum, *psp, *pback;
    cudaGetSymbolAddress((void**)&ph16, g_h16);
    cudaGetSymbolAddress((void**)&pA, g_A);
    cudaGetSymbolAddress((void**)&pB, g_B);
    cudaGetSymbolAddress((void**)&pmr, g_mr);
    cudaGetSymbolAddress((void**)&pspsum, g_spsum);
    cudaGetSymbolAddress((void**)&psp, g_sp);
    cudaGetSymbolAddress((void**)&pback, g_back);
    cudaGetSymbolAddress((void**)&pwcomb, g_wcomb);
    cudaGetSymbolAddress((void**)&pb2c, g_b2c);
    cudaGetSymbolAddress((void**)&pdeg, g_deg);

    cudaFuncSetAttribute(gemm_mma, cudaFuncAttributeMaxDynamicSharedMemorySize, SM_TOTAL);
    cudaFuncSetAttribute(gemm_dual, cudaFuncAttributeMaxDynamicSharedMemorySize, DU_TOTAL);

    __half* h16_0 = ph16;
    __half* h16_1 = ph16 + (size_t)3 * PSTRIDE;

    const int T = 256;
    dim3 gG3((NHIT + 127) / 128, 3);
    dim3 gG1((NSP + 127) / 128, 1);
    dim3 gW3((NHIT * 32 + T - 1) / T, 3);
    int gW1 = (NSP * 32 + T - 1) / T;
    dim3 gE((NHIT * HD + T - 1) / T, 3);

    // --- CSR build ---
    zero_counts<<<(NHIT + T - 1) / T, T>>>();
    dim3 gCnt((NEDGE + T - 1) / T, 3);
    count_all<<<gCnt, T>>>(edge[0], edge[1], edge[2], nexus[0], nexus[1], nexus[2]);
    scan_excl_all<<<9, 1024>>>();
    fill_all<<<gCnt, T>>>(edge[0], edge[1], edge[2], nexus[0], nexus[1], nexus[2]);

    // --- weight combine + prep (0=W1top 1=W1bot 2=WupdT 3=comb 4=Wsp 5=WnxT 6=WnxB) ---
    combine_w<<<129, 128>>>(W_msg2, W_upd + 128 * 128, b_msg2);
    prep_w<<<224, 256>>>(W_msg1, W_msg1 + 128 * 128, W_upd, pwcomb,
                         W_sp, W_nx, W_nx + 128 * 128);

    // --- encoder ---
    encoder_k<<<gE, T>>>(x[0], x[1], x[2], W_enc, b_enc, h16_0);

    for (int it = 0; it < 3; it++) {
        gemm_dual<<<gG3, T, DU_TOTAL>>>(h16_0, PSTRIDE, 0, 1, pA, pB, NHIT);
        planar_agg<<<gW3, T>>>(b_msg1);
        gemm_mma<<<gG3, T, SM_TOTAL>>>(h16_0, pmr, PSTRIDE, 2, 2, b_upd, pb2c,
                                       pdeg, NHIT, h16_0, h16_1, NHIT, EPI_RESRELU_DEG);
        nexus_fwd<<<gW1, T>>>(h16_1);
        gemm_mma<<<gG1, T, SM_TOTAL>>>(pspsum, nullptr, 0, 4, 1, b_sp, nullptr,
                                       nullptr, 0, nullptr, psp, NSP, EPI_RELU);
        nexus_back<<<gW3, T>>>();
        gemm_mma<<<gG3, T, SM_TOTAL>>>(h16_1, pback, PSTRIDE, 5, 2, b_nx, nullptr,
                                       nullptr, 0, h16_1, h16_0, NHIT, EPI_RESRELU);
    }

    decoder_k<<<gW3, T>>>(h16_0, W_sem, b_sem, (float*)d_out);
}

// round 14
// speedup vs baseline: 1.6082x; 1.0394x over previous
#include <cuda_runtime.h>
#include <cuda_fp16.h>
#include <cstdint>

#define NHIT 30000
#define NEDGE 90000
#define NSP 30000
#define HD 128
#define NCLASS 5
#define PSTRIDE (NHIT * HD)

// ---------------- device scratch ----------------
__device__ __half g_h16[2][3][NHIT * HD];       // fp16 hidden state (ping-pong)
__device__ __half g_A[3][NHIT * HD];
__device__ __half g_B[3][NHIT * HD];
__device__ __half g_mr[3][NHIT * HD];
__device__ __half g_spsum[NSP * HD];
__device__ __half g_sp[NSP * HD];
__device__ __half g_back[3][NHIT * HD];
__device__ float g_wcomb[HD * HD];              // W_msg2 @ W_upd_bottom
__device__ float g_b2c[HD];                     // b_msg2 @ W_upd_bottom

// prepped weights: 7 chunks x {hi,lo} x 2 k-stages x (128n x 64k fp16, swizzled)
__device__ uint4 g_wbuf[7][2][2][1024];

__device__ int g_deg[3][NHIT];
__device__ int g_cf[3][NSP];
__device__ int g_cb[3][NHIT];
__device__ int g_offE[3][NHIT + 1];
__device__ int g_offF[3][NSP + 1];
__device__ int g_offB[3][NHIT + 1];
__device__ int g_csrE[3][NEDGE];
__device__ int g_csrF[3][NSP];
__device__ int g_csrB[3][NSP];
__device__ int g_curE[3][NHIT];
__device__ int g_curF[3][NSP];
__device__ int g_curB[3][NHIT];

enum { EPI_RELU = 1, EPI_RESRELU = 2, EPI_RESRELU_DEG = 4 };

// ---------------- helpers ----------------
__device__ __forceinline__ uint32_t s2u(const void* p) {
    return (uint32_t)__cvta_generic_to_shared(p);
}
__device__ __forceinline__ uint32_t pack2h(float a, float b) {
    __half2 t = __floats2half2_rn(a, b);
    return *reinterpret_cast<uint32_t*>(&t);
}
__device__ __forceinline__ float lopart(float v) {
    return v - __half2float(__float2half(v));
}
__device__ __forceinline__ uint32_t swz(int row, int k) {
    return (uint32_t)(row * 128 + ((((k >> 3) ^ row) & 7) << 4) + (k & 7) * 2);
}
__device__ __forceinline__ void ldsm4(uint32_t* r, uint32_t addr) {
    asm volatile("ldmatrix.sync.aligned.m8n8.x4.shared.b16 {%0,%1,%2,%3}, [%4];"
                 : "=r"(r[0]), "=r"(r[1]), "=r"(r[2]), "=r"(r[3]) : "r"(addr));
}
__device__ __forceinline__ void mma16816(float* c, const uint32_t* a, uint32_t b0, uint32_t b1) {
    asm volatile(
        "mma.sync.aligned.m16n8k16.row.col.f32.f16.f16.f32 "
        "{%0,%1,%2,%3}, {%4,%5,%6,%7}, {%8,%9}, {%0,%1,%2,%3};"
        : "+f"(c[0]), "+f"(c[1]), "+f"(c[2]), "+f"(c[3])
        : "r"(a[0]), "r"(a[1]), "r"(a[2]), "r"(a[3]), "r"(b0), "r"(b1));
}
__device__ __forceinline__ void cpa8(uint32_t dst, const void* src) {
    asm volatile("cp.async.ca.shared.global [%0], [%1], 8;" :: "r"(dst), "l"(src));
}
__device__ __forceinline__ void cpa16(uint32_t dst, const void* src) {
    asm volatile("cp.async.cg.shared.global [%0], [%1], 16;" :: "r"(dst), "l"(src));
}
#define CP_COMMIT() asm volatile("cp.async.commit_group;")
#define CP_WAIT1()  asm volatile("cp.async.wait_group 1;")
#define CP_WAIT0()  asm volatile("cp.async.wait_group 0;")

// gemm_mma: 2 pipeline buffers x [A 16K | BHI 16K | BLO 16K]
#define PB_A 0
#define PB_BHI 16384
#define PB_BLO 32768
#define PB_SZ 49152
#define SM_TOTAL 98304
// gemm_dual: A (both halves) 32K + 2 B-buffers x [BHI 16K | (BLO unused)]
#define DU_A 0
#define DU_B 32768
#define DU_BSZ 32768
#define DU_TOTAL 98304

// ---------------- weight combine ----------------
__global__ void combine_w(const float* __restrict__ W2, const float* __restrict__ Wub,
                          const float* __restrict__ b2) {
    int n = threadIdx.x;
    int k = blockIdx.x;
    if (k < 128) {
        float s = 0.f;
        #pragma unroll 8
        for (int j = 0; j < 128; j++) s = fmaf(W2[k * 128 + j], Wub[j * 128 + n], s);
        g_wcomb[k * 128 + n] = s;
    } else {
        float s = 0.f;
        #pragma unroll 8
        for (int j = 0; j < 128; j++) s = fmaf(b2[j], Wub[j * 128 + n], s);
        g_b2c[n] = s;
    }
}

// ---------------- weight prep ----------------
__global__ void prep_w(const float* w0, const float* w1, const float* w2,
                       const float* w3, const float* w4, const float* w5,
                       const float* w6) {
    int id = blockIdx.x * blockDim.x + threadIdx.x;
    if (id >= 7 * 8192) return;
    int c = id >> 13;
    int rem = id & 8191;
    int s = rem >> 12;
    int rem2 = rem & 4095;
    int n = rem2 >> 5;
    int kp = (rem2 & 31) * 2;
    const float* Wc = (c == 0) ? w0 : (c == 1) ? w1 : (c == 2) ? w2 : (c == 3) ? w3
                    : (c == 4) ? w4 : (c == 5) ? w5 : w6;
    float v0 = Wc[(s * 64 + kp) * 128 + n];
    float v1 = Wc[(s * 64 + kp + 1) * 128 + n];
    uint32_t o = swz(n, kp);
    *reinterpret_cast<uint32_t*>((char*)&g_wbuf[c][0][s][0] + o) = pack2h(v0, v1);
    *reinterpret_cast<uint32_t*>((char*)&g_wbuf[c][1][s][0] + o) = pack2h(lopart(v0), lopart(v1));
}

// ---------------- HMMA GEMM, cp.async double-buffered; optional B_lo pass ----------------
__global__ __launch_bounds__(256, 2) void gemm_mma(
    const __half* __restrict__ Ah0, const __half* __restrict__ Ah1,
    int sA, int wc0, int nchunks, int uselo,
    const float* __restrict__ bias, const float* __restrict__ bias2,
    const int* __restrict__ mask, int sMask,
    const __half* __restrict__ resid,
    __half* __restrict__ outh, int M, int epi)
{
    extern __shared__ char smem[];
    uint32_t sb = s2u(smem);
    int tid = threadIdx.x;
    int wid = tid >> 5, lane = tid & 31;
    int mwarp = wid & 3, nwarp = wid >> 2;
    int row0 = blockIdx.x * 128;
    int pl = blockIdx.y;
    const __half* Ah0p = Ah0 + (size_t)pl * sA;
    const __half* Ah1p = Ah1 ? (Ah1 + (size_t)pl * sA) : nullptr;
    const __half* residp = resid ? (resid + (size_t)pl * sA) : nullptr;
    const int* maskp = mask ? (mask + (size_t)pl * sMask) : nullptr;

    float C[2][8][4];
    #pragma unroll
    for (int mt = 0; mt < 2; mt++)
        #pragma unroll
        for (int nt = 0; nt < 8; nt++)
            #pragma unroll
            for (int q = 0; q < 4; q++) C[mt][nt][q] = 0.f;

    int a_row_in16 = (lane & 7) + ((lane >> 3) & 1) * 8;
    int a_kb = (lane >> 4) & 1;
    int b_row_in16 = (lane & 7) + ((lane >> 4) & 1) * 8;
    int b_kb = (lane >> 3) & 1;

    int nst = nchunks * 2;

    auto prefetch = [&](int s) {
        int ch = s >> 1, kh = s & 1;
        const __half* src = ch ? Ah1p : Ah0p;
        uint32_t bb = sb + (uint32_t)((s & 1) * PB_SZ);
        #pragma unroll
        for (int l = 0; l < 8; l++) {
            int i = l * 256 + tid;
            int r = i >> 4, c4 = (i & 15) * 4;
            int row = row0 + r; if (row >= M) row = M - 1;
            cpa8(bb + PB_A + swz(r, c4), &src[(size_t)row * 128 + kh * 64 + c4]);
        }
        const uint4* bh = &g_wbuf[wc0 + ch][0][kh][0];
        const uint4* bl = &g_wbuf[wc0 + ch][1][kh][0];
        #pragma unroll
        for (int l = 0; l < 4; l++) {
            int i = l * 256 + tid;
            cpa16(bb + PB_BHI + (uint32_t)i * 16, bh + i);
            if (uselo) cpa16(bb + PB_BLO + (uint32_t)i * 16, bl + i);
        }
        CP_COMMIT();
    };

    prefetch(0);
    for (int s = 0; s < nst; s++) {
        if (s + 1 < nst) { prefetch(s + 1); CP_WAIT1(); }
        else             { CP_WAIT0(); }
        __syncthreads();
        uint32_t ab = sb + (uint32_t)((s & 1) * PB_SZ);

        #pragma unroll
        for (int k16 = 0; k16 < 4; k16++) {
            uint32_t a[2][4];
            #pragma unroll
            for (int mt = 0; mt < 2; mt++) {
                int row = mwarp * 32 + mt * 16 + a_row_in16;
                uint32_t o = (uint32_t)(row * 128 + ((((k16 * 2 + a_kb) ^ row) & 7) << 4));
                ldsm4(a[mt], ab + PB_A + o);
            }
            #pragma unroll
            for (int ntp = 0; ntp < 4; ntp++) {
                int nrow = nwarp * 64 + ntp * 16 + b_row_in16;
                uint32_t o = (uint32_t)(nrow * 128 + ((((k16 * 2 + b_kb) ^ nrow) & 7) << 4));
                uint32_t bhi[4], blo[4];
                ldsm4(bhi, ab + PB_BHI + o);
                if (uselo) ldsm4(blo, ab + PB_BLO + o);
                #pragma unroll
                for (int half = 0; half < 2; half++) {
                    int nt = ntp * 2 + half;
                    #pragma unroll
                    for (int mt = 0; mt < 2; mt++) {
                        mma16816(C[mt][nt], a[mt], bhi[half * 2], bhi[half * 2 + 1]);
                        if (uselo)
                            mma16816(C[mt][nt], a[mt], blo[half * 2], blo[half * 2 + 1]);
                    }
                }
            }
        }
        __syncthreads();
    }

    int qrow = lane >> 2;
    int qcol = (lane & 3) * 2;
    #pragma unroll
    for (int mt = 0; mt < 2; mt++) {
        #pragma unroll
        for (int half = 0; half < 2; half++) {
            int row = row0 + mwarp * 32 + mt * 16 + qrow + half * 8;
            if (row >= M) continue;
            bool dg = (epi == EPI_RESRELU_DEG) ? (maskp[row] > 0) : false;
            #pragma unroll
            for (int nt = 0; nt < 8; nt++) {
                int col = nwarp * 64 + nt * 8 + qcol;
                float v0 = C[mt][nt][half * 2 + 0];
                float v1 = C[mt][nt][half * 2 + 1];
                float o0, o1;
                if (epi == EPI_RELU) {
                    o0 = fmaxf(v0 + bias[col], 0.f);
                    o1 = fmaxf(v1 + bias[col + 1], 0.f);
                } else {
                    float e0 = v0 + bias[col], e1 = v1 + bias[col + 1];
                    if (epi == EPI_RESRELU_DEG && dg) { e0 += bias2[col]; e1 += bias2[col + 1]; }
                    float2 rr = __half22float2(
                        *reinterpret_cast<const __half2*>(&residp[(size_t)row * 128 + col]));
                    o0 = rr.x + fmaxf(e0, 0.f);
                    o1 = rr.y + fmaxf(e1, 0.f);
                }
                *reinterpret_cast<__half2*>(&outh[(size_t)pl * sA + (size_t)row * 128 + col]) =
                    __floats2half2_rn(o0, o1);
            }
        }
    }
}

// ---------------- dual-output GEMM, 1-pass (B_hi only), cp.async pipelined B ----------------
__global__ __launch_bounds__(256, 2) void gemm_dual(
    const __half* __restrict__ A, int sA, int wc0, int wc1,
    __half* __restrict__ out0, __half* __restrict__ out1, int M)
{
    extern __shared__ char smem[];
    uint32_t sb = s2u(smem);
    int tid = threadIdx.x;
    int wid = tid >> 5, lane = tid & 31;
    int mwarp = wid & 3, nwarp = wid >> 2;
    int row0 = blockIdx.x * 128;
    int pl = blockIdx.y;
    const __half* Ap = A + (size_t)pl * sA;
    __half* o0 = out0 + (size_t)pl * sA;
    __half* o1 = out1 + (size_t)pl * sA;

    int a_row_in16 = (lane & 7) + ((lane >> 3) & 1) * 8;
    int a_kb = (lane >> 4) & 1;
    int b_row_in16 = (lane & 7) + ((lane >> 4) & 1) * 8;
    int b_kb = (lane >> 3) & 1;
    int qrow = lane >> 2;
    int qcol = (lane & 3) * 2;

    auto prefetchB = [&](int s) {
        int w = s >> 1, kh = s & 1;
        int wc = w ? wc1 : wc0;
        uint32_t bb = sb + DU_B + (uint32_t)((s & 1) * DU_BSZ);
        const uint4* bh = &g_wbuf[wc][0][kh][0];
        #pragma unroll
        for (int l = 0; l < 4; l++) {
            int i = l * 256 + tid;
            cpa16(bb + (uint32_t)i * 16, bh + i);
        }
        CP_COMMIT();
    };

    #pragma unroll
    for (int l = 0; l < 16; l++) {
        int i = l * 256 + tid;
        int r = i >> 5, c4 = (i & 31) * 4;
        int sh = c4 >> 6, k = c4 & 63;
        int row = row0 + r; if (row >= M) row = M - 1;
        cpa8(sb + DU_A + sh * 16384 + swz(r, k), &Ap[(size_t)row * 128 + c4]);
    }
    prefetchB(0);

    float C[2][8][4];
    for (int s = 0; s < 4; s++) {
        if (s + 1 < 4) { prefetchB(s + 1); CP_WAIT1(); }
        else           { CP_WAIT0(); }
        __syncthreads();

        if ((s & 1) == 0) {
            #pragma unroll
            for (int mt = 0; mt < 2; mt++)
                #pragma unroll
                for (int nt = 0; nt < 8; nt++)
                    #pragma unroll
                    for (int q = 0; q < 4; q++) C[mt][nt][q] = 0.f;
        }

        uint32_t abase = sb + DU_A + (uint32_t)((s & 1) * 16384);
        uint32_t bbase = sb + DU_B + (uint32_t)((s & 1) * DU_BSZ);
        #pragma unroll
        for (int k16 = 0; k16 < 4; k16++) {
            uint32_t a[2][4];
            #pragma unroll
            for (int mt = 0; mt < 2; mt++) {
                int row = mwarp * 32 + mt * 16 + a_row_in16;
                uint32_t o = (uint32_t)(row * 128 + ((((k16 * 2 + a_kb) ^ row) & 7) << 4));
                ldsm4(a[mt], abase + o);
            }
            #pragma unroll
            for (int ntp = 0; ntp < 4; ntp++) {
                int nrow = nwarp * 64 + ntp * 16 + b_row_in16;
                uint32_t o = (uint32_t)(nrow * 128 + ((((k16 * 2 + b_kb) ^ nrow) & 7) << 4));
                uint32_t bhi[4];
                ldsm4(bhi, bbase + o);
                #pragma unroll
                for (int half = 0; half < 2; half++) {
                    int nt = ntp * 2 + half;
                    #pragma unroll
                    for (int mt = 0; mt < 2; mt++)
                        mma16816(C[mt][nt], a[mt], bhi[half * 2], bhi[half * 2 + 1]);
                }
            }
        }
        __syncthreads();

        if (s & 1) {
            __half* op = (s >> 1) ? o1 : o0;
            #pragma unroll
            for (int mt = 0; mt < 2; mt++) {
                #pragma unroll
                for (int half = 0; half < 2; half++) {
                    int row = row0 + mwarp * 32 + mt * 16 + qrow + half * 8;
                    if (row >= M) continue;
                    #pragma unroll
                    for (int nt = 0; nt < 8; nt++) {
                        int col = nwarp * 64 + nt * 8 + qcol;
                        *reinterpret_cast<__half2*>(&op[(size_t)row * 128 + col]) =
                            __floats2half2_rn(C[mt][nt][half * 2], C[mt][nt][half * 2 + 1]);
                    }
                }
            }
        }
    }
}

// ---------------- CSR build ----------------
__global__ void zero_counts() {
    int i = blockIdx.x * blockDim.x + threadIdx.x;
    if (i < NHIT) {
        #pragma unroll
        for (int p = 0; p < 3; p++) { g_deg[p][i] = 0; g_cb[p][i] = 0; }
    }
    if (i < NSP) {
        #pragma unroll
        for (int p = 0; p < 3; p++) g_cf[p][i] = 0;
    }
}

__global__ void count_all(const int* __restrict__ e0, const int* __restrict__ e1,
                          const int* __restrict__ e2, const int* __restrict__ n0,
                          const int* __restrict__ n1, const int* __restrict__ n2) {
    int p = blockIdx.y;
    const int* e = (p == 0) ? e0 : (p == 1) ? e1 : e2;
    const int* nx = (p == 0) ? n0 : (p == 1) ? n1 : n2;
    int i = blockIdx.x * blockDim.x + threadIdx.x;
    if (i < NEDGE) atomicAdd(&g_deg[p][e[NEDGE + i]], 1);
    if (i < NSP) {
        atomicAdd(&g_cf[p][nx[NSP + i]], 1);
        atomicAdd(&g_cb[p][nx[i]], 1);
    }
}

__global__ void scan_excl_all() {
    int sel = blockIdx.x / 3, p = blockIdx.x % 3;
    const int* in; int* out; int* cur; int n;
    if (sel == 0)      { in = g_deg[p]; out = g_offE[p]; cur = g_curE[p]; n = NHIT; }
    else if (sel == 1) { in = g_cf[p];  out = g_offF[p]; cur = g_curF[p]; n = NSP; }
    else               { in = g_cb[p];  out = g_offB[p]; cur = g_curB[p]; n = NHIT; }
    __shared__ int wsum[32];
    __shared__ int carry;
    int tid = threadIdx.x;
    if (tid == 0) carry = 0;
    __syncthreads();
    for (int base = 0; base < n; base += 1024) {
        int i = base + tid;
        int v = (i < n) ? in[i] : 0;
        int x = v;
        #pragma unroll
        for (int d = 1; d < 32; d <<= 1) {
            int y = __shfl_up_sync(0xffffffffu, x, d);
            if ((tid & 31) >= d) x += y;
        }
        if ((tid & 31) == 31) wsum[tid >> 5] = x;
        __syncthreads();
        if (tid < 32) {
            int s = wsum[tid];
            #pragma unroll
            for (int d = 1; d < 32; d <<= 1) {
                int y = __shfl_up_sync(0xffffffffu, s, d);
                if (tid >= d) s += y;
            }
            wsum[tid] = s;
        }
        __syncthreads();
        int woff = (tid >= 32) ? wsum[(tid >> 5) - 1] : 0;
        int incl = carry + woff + x;
        if (i < n) { out[i] = incl - v; cur[i] = incl - v; }
        __syncthreads();
        if (tid == 1023) carry = incl;
        __syncthreads();
    }
    if (tid == 0) out[n] = carry;
}

__global__ void fill_all(const int* __restrict__ e0, const int* __restrict__ e1,
                         const int* __restrict__ e2, const int* __restrict__ n0,
                         const int* __restrict__ n1, const int* __restrict__ n2) {
    int p = blockIdx.y;
    const int* e = (p == 0) ? e0 : (p == 1) ? e1 : e2;
    const int* nx = (p == 0) ? n0 : (p == 1) ? n1 : n2;
    int i = blockIdx.x * blockDim.x + threadIdx.x;
    if (i < NEDGE) {
        int dst = e[NEDGE + i];
        g_csrE[p][atomicAdd(&g_curE[p][dst], 1)] = e[i];
    }
    if (i < NSP) {
        int s = nx[NSP + i];
        g_csrF[p][atomicAdd(&g_curF[p][s], 1)] = nx[i];
        int h = nx[i];
        g_csrB[p][atomicAdd(&g_curB[p][h], 1)] = nx[NSP + i];
    }
}

// ---------------- encoder (fp16 state) ----------------
__global__ void encoder_k(const float* __restrict__ x0, const float* __restrict__ x1,
                          const float* __restrict__ x2, const float* __restrict__ W,
                          const float* __restrict__ b, __half* __restrict__ h16base) {
    int p = blockIdx.y;
    const float* x = (p == 0) ? x0 : (p == 1) ? x1 : x2;
    int idx = blockIdx.x * blockDim.x + threadIdx.x;
    if (idx >= NHIT * HD) return;
    int n = idx >> 7, j = idx & 127;
    float acc = b[j];
    #pragma unroll
    for (int k = 0; k < 4; k++) acc = fmaf(x[n * 4 + k], W[k * HD + j], acc);
    acc = fmaxf(acc, 0.f);
    h16base[(size_t)p * PSTRIDE + idx] = __float2half(acc);
}

// ---------------- planar edge aggregation (2-way unrolled MLP) ----------------
__global__ void planar_agg(const float* __restrict__ b1) {
    int p = blockIdx.y;
    int warp = (blockIdx.x * blockDim.x + threadIdx.x) >> 5;
    if (warp >= NHIT) return;
    int lane = threadIdx.x & 31;
    int n = warp;
    uint2 ar = *reinterpret_cast<const uint2*>(&g_A[p][(size_t)n * HD + lane * 4]);
    float2 a01 = __half22float2(*reinterpret_cast<__half2*>(&ar.x));
    float2 a23 = __half22float2(*reinterpret_cast<__half2*>(&ar.y));
    float4 bb = *reinterpret_cast<const float4*>(&b1[lane * 4]);
    int s = g_offE[p][n], e = g_offE[p][n + 1];
    float4 acc0 = make_float4(0.f, 0.f, 0.f, 0.f);
    float4 acc1 = make_float4(0.f, 0.f, 0.f, 0.f);
    int i = s;
    for (; i + 2 <= e; i += 2) {
        int s0 = g_csrE[p][i], s1 = g_csrE[p][i + 1];
        uint2 br0 = *reinterpret_cast<const uint2*>(&g_B[p][(size_t)s0 * HD + lane * 4]);
        uint2 br1 = *reinterpret_cast<const uint2*>(&g_B[p][(size_t)s1 * HD + lane * 4]);
        float2 b001 = __half22float2(*reinterpret_cast<__half2*>(&br0.x));
        float2 b023 = __half22float2(*reinterpret_cast<__half2*>(&br0.y));
        float2 b101 = __half22float2(*reinterpret_cast<__half2*>(&br1.x));
        float2 b123 = __half22float2(*reinterpret_cast<__half2*>(&br1.y));
        acc0.x += fmaxf(a01.x + b001.x + bb.x, 0.f);
        acc0.y += fmaxf(a01.y + b001.y + bb.y, 0.f);
        acc0.z += fmaxf(a23.x + b023.x + bb.z, 0.f);
        acc0.w += fmaxf(a23.y + b023.y + bb.w, 0.f);
        acc1.x += fmaxf(a01.x + b101.x + bb.x, 0.f);
        acc1.y += fmaxf(a01.y + b101.y + bb.y, 0.f);
        acc1.z += fmaxf(a23.x + b123.x + bb.z, 0.f);
        acc1.w += fmaxf(a23.y + b123.y + bb.w, 0.f);
    }
    if (i < e) {
        int s0 = g_csrE[p][i];
        uint2 br0 = *reinterpret_cast<const uint2*>(&g_B[p][(size_t)s0 * HD + lane * 4]);
        float2 b001 = __half22float2(*reinterpret_cast<__half2*>(&br0.x));
        float2 b023 = __half22float2(*reinterpret_cast<__half2*>(&br0.y));
        acc0.x += fmaxf(a01.x + b001.x + bb.x, 0.f);
        acc0.y += fmaxf(a01.y + b001.y + bb.y, 0.f);
        acc0.z += fmaxf(a23.x + b023.x + bb.z, 0.f);
        acc0.w += fmaxf(a23.y + b023.y + bb.w, 0.f);
    }
    float4 acc = make_float4(acc0.x + acc1.x, acc0.y + acc1.y,
                             acc0.z + acc1.z, acc0.w + acc1.w);
    float inv = (e > s) ? 1.f / (float)(e - s) : 0.f;
    uint2 o;
    *reinterpret_cast<__half2*>(&o.x) = __floats2half2_rn(acc.x * inv, acc.y * inv);
    *reinterpret_cast<__half2*>(&o.y) = __floats2half2_rn(acc.z * inv, acc.w * inv);
    *reinterpret_cast<uint2*>(&g_mr[p][(size_t)n * HD + lane * 4]) = o;
}

// ---------------- nexus forward (2-way unrolled) ----------------
__global__ void nexus_fwd(const __half* __restrict__ h16base) {
    int warp = (blockIdx.x * blockDim.x + threadIdx.x) >> 5;
    if (warp >= NSP) return;
    int lane = threadIdx.x & 31;
    int s = warp;
    float4 tot = make_float4(0.f, 0.f, 0.f, 0.f);
    #pragma unroll
    for (int p = 0; p < 3; p++) {
        const __half* h = h16base + (size_t)p * PSTRIDE;
        int st = g_offF[p][s], en = g_offF[p][s + 1];
        float4 acc0 = make_float4(0.f, 0.f, 0.f, 0.f);
        float4 acc1 = make_float4(0.f, 0.f, 0.f, 0.f);
        int i = st;
        for (; i + 2 <= en; i += 2) {
            int h0i = g_csrF[p][i], h1i = g_csrF[p][i + 1];
            uint2 v0 = *reinterpret_cast<const uint2*>(&h[(size_t)h0i * HD + lane * 4]);
            uint2 v1 = *reinterpret_cast<const uint2*>(&h[(size_t)h1i * HD + lane * 4]);
            float2 a01 = __half22float2(*reinterpret_cast<__half2*>(&v0.x));
            float2 a23 = __half22float2(*reinterpret_cast<__half2*>(&v0.y));
            float2 c01 = __half22float2(*reinterpret_cast<__half2*>(&v1.x));
            float2 c23 = __half22float2(*reinterpret_cast<__half2*>(&v1.y));
            acc0.x += a01.x; acc0.y += a01.y; acc0.z += a23.x; acc0.w += a23.y;
            acc1.x += c01.x; acc1.y += c01.y; acc1.z += c23.x; acc1.w += c23.y;
        }
        if (i < en) {
            int h0i = g_csrF[p][i];
            uint2 v0 = *reinterpret_cast<const uint2*>(&h[(size_t)h0i * HD + lane * 4]);
            float2 a01 = __half22float2(*reinterpret_cast<__half2*>(&v0.x));
            float2 a23 = __half22float2(*reinterpret_cast<__half2*>(&v0.y));
            acc0.x += a01.x; acc0.y += a01.y; acc0.z += a23.x; acc0.w += a23.y;
        }
        if (en > st) {
            float inv = 1.f / (float)(en - st);
            tot.x += (acc0.x + acc1.x) * inv; tot.y += (acc0.y + acc1.y) * inv;
            tot.z += (acc0.z + acc1.z) * inv; tot.w += (acc0.w + acc1.w) * inv;
        }
    }
    uint2 o;
    *reinterpret_cast<__half2*>(&o.x) = __floats2half2_rn(tot.x, tot.y);
    *reinterpret_cast<__half2*>(&o.y) = __floats2half2_rn(tot.z, tot.w);
    *reinterpret_cast<uint2*>(&g_spsum[(size_t)s * HD + lane * 4]) = o;
}

// ---------------- nexus backward (2-way unrolled) ----------------
__global__ void nexus_back() {
    int p = blockIdx.y;
    int warp = (blockIdx.x * blockDim.x + threadIdx.x) >> 5;
    if (warp >= NHIT) return;
    int lane = threadIdx.x & 31;
    int n = warp;
    int st = g_offB[p][n], en = g_offB[p][n + 1];
    float4 acc0 = make_float4(0.f, 0.f, 0.f, 0.f);
    float4 acc1 = make_float4(0.f, 0.f, 0.f, 0.f);
    int i = st;
    for (; i + 2 <= en; i += 2) {
        int s0 = g_csrB[p][i], s1 = g_csrB[p][i + 1];
        uint2 v0 = *reinterpret_cast<const uint2*>(&g_sp[(size_t)s0 * HD + lane * 4]);
        uint2 v1 = *reinterpret_cast<const uint2*>(&g_sp[(size_t)s1 * HD + lane * 4]);
        float2 a01 = __half22float2(*reinterpret_cast<__half2*>(&v0.x));
        float2 a23 = __half22float2(*reinterpret_cast<__half2*>(&v0.y));
        float2 c01 = __half22float2(*reinterpret_cast<__half2*>(&v1.x));
        float2 c23 = __half22float2(*reinterpret_cast<__half2*>(&v1.y));
        acc0.x += a01.x; acc0.y += a01.y; acc0.z += a23.x; acc0.w += a23.y;
        acc1.x += c01.x; acc1.y += c01.y; acc1.z += c23.x; acc1.w += c23.y;
    }
    if (i < en) {
        int s0 = g_csrB[p][i];
        uint2 v0 = *reinterpret_cast<const uint2*>(&g_sp[(size_t)s0 * HD + lane * 4]);
        float2 a01 = __half22float2(*reinterpret_cast<__half2*>(&v0.x));
        float2 a23 = __half22float2(*reinterpret_cast<__half2*>(&v0.y));
        acc0.x += a01.x; acc0.y += a01.y; acc0.z += a23.x; acc0.w += a23.y;
    }
    float inv = (en > st) ? 1.f / (float)(en - st) : 0.f;
    uint2 o;
    *reinterpret_cast<__half2*>(&o.x) =
        __floats2half2_rn((acc0.x + acc1.x) * inv, (acc0.y + acc1.y) * inv);
    *reinterpret_cast<__half2*>(&o.y) =
        __floats2half2_rn((acc0.z + acc1.z) * inv, (acc0.w + acc1.w) * inv);
    *reinterpret_cast<uint2*>(&g_back[p][(size_t)n * HD + lane * 4]) = o;
}

// ---------------- decoder (fp16 state in, fp32 out) ----------------
__global__ void decoder_k(const __half* __restrict__ hbase, const float* __restrict__ Wsem,
                          const float* __restrict__ bsem, float* __restrict__ out) {
    int p = blockIdx.y;
    const __half* h = hbase + (size_t)p * PSTRIDE;
    float* o = out + (size_t)p * NHIT * NCLASS;
    int warp = (blockIdx.x * blockDim.x + threadIdx.x) >> 5;
    if (warp >= NHIT) return;
    int lane = threadIdx.x & 31;
    int n = warp;
    float hv[4];
    #pragma unroll
    for (int t = 0; t < 4; t++) hv[t] = __half2float(h[(size_t)n * HD + lane + t * 32]);
    #pragma unroll
    for (int c = 0; c < NCLASS; c++) {
        float s = 0.f;
        #pragma unroll
        for (int t = 0; t < 4; t++) s = fmaf(hv[t], Wsem[(lane + t * 32) * NCLASS + c], s);
        #pragma unroll
        for (int d = 16; d > 0; d >>= 1) s += __shfl_down_sync(0xffffffffu, s, d);
        if (lane == 0) o[n * NCLASS + c] = s + bsem[c];
    }
}

// ---------------- host ----------------
extern "C" void kernel_launch(void* const* d_in, const int* in_sizes, int n_in,
                              void* d_out, int out_size) {
    int xi[3], ei[3], ni[3];
    if (in_sizes[1] == 2 * NEDGE) {
        for (int p = 0; p < 3; p++) { xi[p] = 3 * p; ei[p] = 3 * p + 1; ni[p] = 3 * p + 2; }
    } else {
        for (int p = 0; p < 3; p++) { xi[p] = p; ei[p] = 3 + p; ni[p] = 6 + p; }
    }
    const float* x[3]; const int* edge[3]; const int* nexus[3];
    for (int p = 0; p < 3; p++) {
        x[p] = (const float*)d_in[xi[p]];
        edge[p] = (const int*)d_in[ei[p]];
        nexus[p] = (const int*)d_in[ni[p]];
    }
    const float* W_enc  = (const float*)d_in[9];
    const float* b_enc  = (const float*)d_in[10];
    const float* W_msg1 = (const float*)d_in[11];
    const float* b_msg1 = (const float*)d_in[12];
    const float* W_msg2 = (const float*)d_in[13];
    const float* b_msg2 = (const float*)d_in[14];
    const float* W_upd  = (const float*)d_in[15];
    const float* b_upd  = (const float*)d_in[16];
    const float* W_sp   = (const float*)d_in[17];
    const float* b_sp   = (const float*)d_in[18];
    const float* W_nx   = (const float*)d_in[19];
    const float* b_nx   = (const float*)d_in[20];
    const float* W_sem  = (const float*)d_in[21];
    const float* b_sem  = (const float*)d_in[22];

    float *pwcomb, *pb2c; int* pdeg;
    __half *ph16, *pA, *pB, *pmr, *pspsum, *psp, *pback;
    cudaGetSymbolAddress((void**)&ph16, g_h16);
    cudaGetSymbolAddress((void**)&pA, g_A);
    cudaGetSymbolAddress((void**)&pB, g_B);
    cudaGetSymbolAddress((void**)&pmr, g_mr);
    cudaGetSymbolAddress((void**)&pspsum, g_spsum);
    cudaGetSymbolAddress((void**)&psp, g_sp);
    cudaGetSymbolAddress((void**)&pback, g_back);
    cudaGetSymbolAddress((void**)&pwcomb, g_wcomb);
    cudaGetSymbolAddress((void**)&pb2c, g_b2c);
    cudaGetSymbolAddress((void**)&pdeg, g_deg);

    cudaFuncSetAttribute(gemm_mma, cudaFuncAttributeMaxDynamicSharedMemorySize, SM_TOTAL);
    cudaFuncSetAttribute(gemm_dual, cudaFuncAttributeMaxDynamicSharedMemorySize, DU_TOTAL);

    __half* h16_0 = ph16;
    __half* h16_1 = ph16 + (size_t)3 * PSTRIDE;

    const int T = 256;
    dim3 gG3((NHIT + 127) / 128, 3);
    dim3 gG1((NSP + 127) / 128, 1);
    dim3 gW3((NHIT * 32 + T - 1) / T, 3);
    int gW1 = (NSP * 32 + T - 1) / T;
    dim3 gE((NHIT * HD + T - 1) / T, 3);

    // --- CSR build ---
    zero_counts<<<(NHIT + T - 1) / T, T>>>();
    dim3 gCnt((NEDGE + T - 1) / T, 3);
    count_all<<<gCnt, T>>>(edge[0], edge[1], edge[2], nexus[0], nexus[1], nexus[2]);
    scan_excl_all<<<9, 1024>>>();
    fill_all<<<gCnt, T>>>(edge[0], edge[1], edge[2], nexus[0], nexus[1], nexus[2]);

    // --- weight combine + prep (0=W1top 1=W1bot 2=WupdT 3=comb 4=Wsp 5=WnxT 6=WnxB) ---
    combine_w<<<129, 128>>>(W_msg2, W_upd + 128 * 128, b_msg2);
    prep_w<<<224, 256>>>(W_msg1, W_msg1 + 128 * 128, W_upd, pwcomb,
                         W_sp, W_nx, W_nx + 128 * 128);

    // --- encoder ---
    encoder_k<<<gE, T>>>(x[0], x[1], x[2], W_enc, b_enc, h16_0);

    for (int it = 0; it < 3; it++) {
        gemm_dual<<<gG3, T, DU_TOTAL>>>(h16_0, PSTRIDE, 0, 1, pA, pB, NHIT);
        planar_agg<<<gW3, T>>>(b_msg1);
        gemm_mma<<<gG3, T, SM_TOTAL>>>(h16_0, pmr, PSTRIDE, 2, 2, 1, b_upd, pb2c,
                                       pdeg, NHIT, h16_0, h16_1, NHIT, EPI_RESRELU_DEG);
        nexus_fwd<<<gW1, T>>>(h16_1);
        gemm_mma<<<gG1, T, SM_TOTAL>>>(pspsum, nullptr, 0, 4, 1, 0, b_sp, nullptr,
                                       nullptr, 0, nullptr, psp, NSP, EPI_RELU);
        nexus_back<<<gW3, T>>>();
        gemm_mma<<<gG3, T, SM_TOTAL>>>(h16_1, pback, PSTRIDE, 5, 2, 1, b_nx, nullptr,
                                       nullptr, 0, h16_1, h16_0, NHIT, EPI_RESRELU);
    }

    decoder_k<<<gW3, T>>>(h16_0, W_sem, b_sem, (float*)d_out);
}

// round 15
// speedup vs baseline: 1.6421x; 1.0211x over previous
#include <cuda_runtime.h>
#include <cuda_fp16.h>
#include <cstdint>

#define NHIT 30000
#define NEDGE 90000
#define NSP 30000
#define HD 128
#define NCLASS 5
#define PSTRIDE (NHIT * HD)

// ---------------- device scratch ----------------
__device__ __half g_h16[2][3][NHIT * HD];       // fp16 hidden state (ping-pong)
__device__ __half g_A[3][NHIT * HD];
__device__ __half g_B[3][NHIT * HD];
__device__ __half g_mr[3][NHIT * HD];
__device__ __half g_spsum[NSP * HD];
__device__ __half g_sp[NSP * HD];
__device__ __half g_back[3][NHIT * HD];
__device__ float g_wcomb[HD * HD];              // W_msg2 @ W_upd_bottom
__device__ float g_b2c[HD];                     // b_msg2 @ W_upd_bottom

// prepped weights: 7 chunks x {hi,lo} x 2 k-stages x (128n x 64k fp16, swizzled)
__device__ uint4 g_wbuf[7][2][2][1024];

__device__ int g_deg[3][NHIT];
__device__ int g_cf[3][NSP];
__device__ int g_cb[3][NHIT];
__device__ int g_offE[3][NHIT + 1];
__device__ int g_offF[3][NSP + 1];
__device__ int g_offB[3][NHIT + 1];
__device__ int g_csrE[3][NEDGE];
__device__ int g_csrF[3][NSP];
__device__ int g_csrB[3][NSP];
__device__ int g_curE[3][NHIT];
__device__ int g_curF[3][NSP];
__device__ int g_curB[3][NHIT];

enum { EPI_RELU = 1, EPI_RESRELU = 2, EPI_RESRELU_DEG = 4 };

// ---------------- helpers ----------------
__device__ __forceinline__ uint32_t s2u(const void* p) {
    return (uint32_t)__cvta_generic_to_shared(p);
}
__device__ __forceinline__ uint32_t pack2h(float a, float b) {
    __half2 t = __floats2half2_rn(a, b);
    return *reinterpret_cast<uint32_t*>(&t);
}
__device__ __forceinline__ float lopart(float v) {
    return v - __half2float(__float2half(v));
}
__device__ __forceinline__ uint32_t swz(int row, int k) {
    return (uint32_t)(row * 128 + ((((k >> 3) ^ row) & 7) << 4) + (k & 7) * 2);
}
__device__ __forceinline__ void ldsm4(uint32_t* r, uint32_t addr) {
    asm volatile("ldmatrix.sync.aligned.m8n8.x4.shared.b16 {%0,%1,%2,%3}, [%4];"
                 : "=r"(r[0]), "=r"(r[1]), "=r"(r[2]), "=r"(r[3]) : "r"(addr));
}
__device__ __forceinline__ void mma16816(float* c, const uint32_t* a, uint32_t b0, uint32_t b1) {
    asm volatile(
        "mma.sync.aligned.m16n8k16.row.col.f32.f16.f16.f32 "
        "{%0,%1,%2,%3}, {%4,%5,%6,%7}, {%8,%9}, {%0,%1,%2,%3};"
        : "+f"(c[0]), "+f"(c[1]), "+f"(c[2]), "+f"(c[3])
        : "r"(a[0]), "r"(a[1]), "r"(a[2]), "r"(a[3]), "r"(b0), "r"(b1));
}
__device__ __forceinline__ void cpa8(uint32_t dst, const void* src) {
    asm volatile("cp.async.ca.shared.global [%0], [%1], 8;" :: "r"(dst), "l"(src));
}
__device__ __forceinline__ void cpa16(uint32_t dst, const void* src) {
    asm volatile("cp.async.cg.shared.global [%0], [%1], 16;" :: "r"(dst), "l"(src));
}
#define CP_COMMIT() asm volatile("cp.async.commit_group;")
#define CP_WAIT1()  asm volatile("cp.async.wait_group 1;")
#define CP_WAIT0()  asm volatile("cp.async.wait_group 0;")

// gemm_mma: 2 pipeline buffers x [A 16K | BHI 16K | BLO 16K]
#define PB_A 0
#define PB_BHI 16384
#define PB_BLO 32768
#define PB_SZ 49152
#define SM_TOTAL 98304
// gemm_dual: A (both halves) 32K + 2 B-buffers x [BHI 16K]
#define DU_A 0
#define DU_B 32768
#define DU_BSZ 32768
#define DU_TOTAL 98304

// ---------------- weight combine ----------------
__global__ void combine_w(const float* __restrict__ W2, const float* __restrict__ Wub,
                          const float* __restrict__ b2) {
    int n = threadIdx.x;
    int k = blockIdx.x;
    if (k < 128) {
        float s = 0.f;
        #pragma unroll 8
        for (int j = 0; j < 128; j++) s = fmaf(W2[k * 128 + j], Wub[j * 128 + n], s);
        g_wcomb[k * 128 + n] = s;
    } else {
        float s = 0.f;
        #pragma unroll 8
        for (int j = 0; j < 128; j++) s = fmaf(b2[j], Wub[j * 128 + n], s);
        g_b2c[n] = s;
    }
}

// ---------------- weight prep ----------------
__global__ void prep_w(const float* w0, const float* w1, const float* w2,
                       const float* w3, const float* w4, const float* w5,
                       const float* w6) {
    int id = blockIdx.x * blockDim.x + threadIdx.x;
    if (id >= 7 * 8192) return;
    int c = id >> 13;
    int rem = id & 8191;
    int s = rem >> 12;
    int rem2 = rem & 4095;
    int n = rem2 >> 5;
    int kp = (rem2 & 31) * 2;
    const float* Wc = (c == 0) ? w0 : (c == 1) ? w1 : (c == 2) ? w2 : (c == 3) ? w3
                    : (c == 4) ? w4 : (c == 5) ? w5 : w6;
    float v0 = Wc[(s * 64 + kp) * 128 + n];
    float v1 = Wc[(s * 64 + kp + 1) * 128 + n];
    uint32_t o = swz(n, kp);
    *reinterpret_cast<uint32_t*>((char*)&g_wbuf[c][0][s][0] + o) = pack2h(v0, v1);
    *reinterpret_cast<uint32_t*>((char*)&g_wbuf[c][1][s][0] + o) = pack2h(lopart(v0), lopart(v1));
}

// ---------------- HMMA GEMM, cp.async double-buffered; optional B_lo pass ----------------
__global__ __launch_bounds__(256, 2) void gemm_mma(
    const __half* __restrict__ Ah0, const __half* __restrict__ Ah1,
    int sA, int wc0, int nchunks, int uselo,
    const float* __restrict__ bias, const float* __restrict__ bias2,
    const int* __restrict__ mask, int sMask,
    const __half* __restrict__ resid,
    __half* __restrict__ outh, int M, int epi)
{
    extern __shared__ char smem[];
    uint32_t sb = s2u(smem);
    int tid = threadIdx.x;
    int wid = tid >> 5, lane = tid & 31;
    int mwarp = wid & 3, nwarp = wid >> 2;
    int row0 = blockIdx.x * 128;
    int pl = blockIdx.y;
    const __half* Ah0p = Ah0 + (size_t)pl * sA;
    const __half* Ah1p = Ah1 ? (Ah1 + (size_t)pl * sA) : nullptr;
    const __half* residp = resid ? (resid + (size_t)pl * sA) : nullptr;
    const int* maskp = mask ? (mask + (size_t)pl * sMask) : nullptr;

    float C[2][8][4];
    #pragma unroll
    for (int mt = 0; mt < 2; mt++)
        #pragma unroll
        for (int nt = 0; nt < 8; nt++)
            #pragma unroll
            for (int q = 0; q < 4; q++) C[mt][nt][q] = 0.f;

    int a_row_in16 = (lane & 7) + ((lane >> 3) & 1) * 8;
    int a_kb = (lane >> 4) & 1;
    int b_row_in16 = (lane & 7) + ((lane >> 4) & 1) * 8;
    int b_kb = (lane >> 3) & 1;

    int nst = nchunks * 2;

    auto prefetch = [&](int s) {
        int ch = s >> 1, kh = s & 1;
        const __half* src = ch ? Ah1p : Ah0p;
        uint32_t bb = sb + (uint32_t)((s & 1) * PB_SZ);
        #pragma unroll
        for (int l = 0; l < 8; l++) {
            int i = l * 256 + tid;
            int r = i >> 4, c4 = (i & 15) * 4;
            int row = row0 + r; if (row >= M) row = M - 1;
            cpa8(bb + PB_A + swz(r, c4), &src[(size_t)row * 128 + kh * 64 + c4]);
        }
        const uint4* bh = &g_wbuf[wc0 + ch][0][kh][0];
        const uint4* bl = &g_wbuf[wc0 + ch][1][kh][0];
        #pragma unroll
        for (int l = 0; l < 4; l++) {
            int i = l * 256 + tid;
            cpa16(bb + PB_BHI + (uint32_t)i * 16, bh + i);
            if (uselo) cpa16(bb + PB_BLO + (uint32_t)i * 16, bl + i);
        }
        CP_COMMIT();
    };

    prefetch(0);
    for (int s = 0; s < nst; s++) {
        if (s + 1 < nst) { prefetch(s + 1); CP_WAIT1(); }
        else             { CP_WAIT0(); }
        __syncthreads();
        uint32_t ab = sb + (uint32_t)((s & 1) * PB_SZ);

        #pragma unroll
        for (int k16 = 0; k16 < 4; k16++) {
            uint32_t a[2][4];
            #pragma unroll
            for (int mt = 0; mt < 2; mt++) {
                int row = mwarp * 32 + mt * 16 + a_row_in16;
                uint32_t o = (uint32_t)(row * 128 + ((((k16 * 2 + a_kb) ^ row) & 7) << 4));
                ldsm4(a[mt], ab + PB_A + o);
            }
            #pragma unroll
            for (int ntp = 0; ntp < 4; ntp++) {
                int nrow = nwarp * 64 + ntp * 16 + b_row_in16;
                uint32_t o = (uint32_t)(nrow * 128 + ((((k16 * 2 + b_kb) ^ nrow) & 7) << 4));
                uint32_t bhi[4], blo[4];
                ldsm4(bhi, ab + PB_BHI + o);
                if (uselo) ldsm4(blo, ab + PB_BLO + o);
                #pragma unroll
                for (int half = 0; half < 2; half++) {
                    int nt = ntp * 2 + half;
                    #pragma unroll
                    for (int mt = 0; mt < 2; mt++) {
                        mma16816(C[mt][nt], a[mt], bhi[half * 2], bhi[half * 2 + 1]);
                        if (uselo)
                            mma16816(C[mt][nt], a[mt], blo[half * 2], blo[half * 2 + 1]);
                    }
                }
            }
        }
        __syncthreads();
    }

    int qrow = lane >> 2;
    int qcol = (lane & 3) * 2;
    #pragma unroll
    for (int mt = 0; mt < 2; mt++) {
        #pragma unroll
        for (int half = 0; half < 2; half++) {
            int row = row0 + mwarp * 32 + mt * 16 + qrow + half * 8;
            if (row >= M) continue;
            bool dg = (epi == EPI_RESRELU_DEG) ? (maskp[row] > 0) : false;
            #pragma unroll
            for (int nt = 0; nt < 8; nt++) {
                int col = nwarp * 64 + nt * 8 + qcol;
                float v0 = C[mt][nt][half * 2 + 0];
                float v1 = C[mt][nt][half * 2 + 1];
                float o0, o1;
                if (epi == EPI_RELU) {
                    o0 = fmaxf(v0 + bias[col], 0.f);
                    o1 = fmaxf(v1 + bias[col + 1], 0.f);
                } else {
                    float e0 = v0 + bias[col], e1 = v1 + bias[col + 1];
                    if (epi == EPI_RESRELU_DEG && dg) { e0 += bias2[col]; e1 += bias2[col + 1]; }
                    float2 rr = __half22float2(
                        *reinterpret_cast<const __half2*>(&residp[(size_t)row * 128 + col]));
                    o0 = rr.x + fmaxf(e0, 0.f);
                    o1 = rr.y + fmaxf(e1, 0.f);
                }
                *reinterpret_cast<__half2*>(&outh[(size_t)pl * sA + (size_t)row * 128 + col]) =
                    __floats2half2_rn(o0, o1);
            }
        }
    }
}

// ---------------- dual-output GEMM, 1-pass (B_hi only), cp.async pipelined B ----------------
__global__ __launch_bounds__(256, 2) void gemm_dual(
    const __half* __restrict__ A, int sA, int wc0, int wc1,
    __half* __restrict__ out0, __half* __restrict__ out1, int M)
{
    extern __shared__ char smem[];
    uint32_t sb = s2u(smem);
    int tid = threadIdx.x;
    int wid = tid >> 5, lane = tid & 31;
    int mwarp = wid & 3, nwarp = wid >> 2;
    int row0 = blockIdx.x * 128;
    int pl = blockIdx.y;
    const __half* Ap = A + (size_t)pl * sA;
    __half* o0 = out0 + (size_t)pl * sA;
    __half* o1 = out1 + (size_t)pl * sA;

    int a_row_in16 = (lane & 7) + ((lane >> 3) & 1) * 8;
    int a_kb = (lane >> 4) & 1;
    int b_row_in16 = (lane & 7) + ((lane >> 4) & 1) * 8;
    int b_kb = (lane >> 3) & 1;
    int qrow = lane >> 2;
    int qcol = (lane & 3) * 2;

    auto prefetchB = [&](int s) {
        int w = s >> 1, kh = s & 1;
        int wc = w ? wc1 : wc0;
        uint32_t bb = sb + DU_B + (uint32_t)((s & 1) * DU_BSZ);
        const uint4* bh = &g_wbuf[wc][0][kh][0];
        #pragma unroll
        for (int l = 0; l < 4; l++) {
            int i = l * 256 + tid;
            cpa16(bb + (uint32_t)i * 16, bh + i);
        }
        CP_COMMIT();
    };

    #pragma unroll
    for (int l = 0; l < 16; l++) {
        int i = l * 256 + tid;
        int r = i >> 5, c4 = (i & 31) * 4;
        int sh = c4 >> 6, k = c4 & 63;
        int row = row0 + r; if (row >= M) row = M - 1;
        cpa8(sb + DU_A + sh * 16384 + swz(r, k), &Ap[(size_t)row * 128 + c4]);
    }
    prefetchB(0);

    float C[2][8][4];
    for (int s = 0; s < 4; s++) {
        if (s + 1 < 4) { prefetchB(s + 1); CP_WAIT1(); }
        else           { CP_WAIT0(); }
        __syncthreads();

        if ((s & 1) == 0) {
            #pragma unroll
            for (int mt = 0; mt < 2; mt++)
                #pragma unroll
                for (int nt = 0; nt < 8; nt++)
                    #pragma unroll
                    for (int q = 0; q < 4; q++) C[mt][nt][q] = 0.f;
        }

        uint32_t abase = sb + DU_A + (uint32_t)((s & 1) * 16384);
        uint32_t bbase = sb + DU_B + (uint32_t)((s & 1) * DU_BSZ);
        #pragma unroll
        for (int k16 = 0; k16 < 4; k16++) {
            uint32_t a[2][4];
            #pragma unroll
            for (int mt = 0; mt < 2; mt++) {
                int row = mwarp * 32 + mt * 16 + a_row_in16;
                uint32_t o = (uint32_t)(row * 128 + ((((k16 * 2 + a_kb) ^ row) & 7) << 4));
                ldsm4(a[mt], abase + o);
            }
            #pragma unroll
            for (int ntp = 0; ntp < 4; ntp++) {
                int nrow = nwarp * 64 + ntp * 16 + b_row_in16;
                uint32_t o = (uint32_t)(nrow * 128 + ((((k16 * 2 + b_kb) ^ nrow) & 7) << 4));
                uint32_t bhi[4];
                ldsm4(bhi, bbase + o);
                #pragma unroll
                for (int half = 0; half < 2; half++) {
                    int nt = ntp * 2 + half;
                    #pragma unroll
                    for (int mt = 0; mt < 2; mt++)
                        mma16816(C[mt][nt], a[mt], bhi[half * 2], bhi[half * 2 + 1]);
                }
            }
        }
        __syncthreads();

        if (s & 1) {
            __half* op = (s >> 1) ? o1 : o0;
            #pragma unroll
            for (int mt = 0; mt < 2; mt++) {
                #pragma unroll
                for (int half = 0; half < 2; half++) {
                    int row = row0 + mwarp * 32 + mt * 16 + qrow + half * 8;
                    if (row >= M) continue;
                    #pragma unroll
                    for (int nt = 0; nt < 8; nt++) {
                        int col = nwarp * 64 + nt * 8 + qcol;
                        *reinterpret_cast<__half2*>(&op[(size_t)row * 128 + col]) =
                            __floats2half2_rn(C[mt][nt][half * 2], C[mt][nt][half * 2 + 1]);
                    }
                }
            }
        }
    }
}

// ---------------- CSR build ----------------
__global__ void zero_counts() {
    int i = blockIdx.x * blockDim.x + threadIdx.x;
    if (i < NHIT) {
        #pragma unroll
        for (int p = 0; p < 3; p++) { g_deg[p][i] = 0; g_cb[p][i] = 0; }
    }
    if (i < NSP) {
        #pragma unroll
        for (int p = 0; p < 3; p++) g_cf[p][i] = 0;
    }
}

__global__ void count_all(const int* __restrict__ e0, const int* __restrict__ e1,
                          const int* __restrict__ e2, const int* __restrict__ n0,
                          const int* __restrict__ n1, const int* __restrict__ n2) {
    int p = blockIdx.y;
    const int* e = (p == 0) ? e0 : (p == 1) ? e1 : e2;
    const int* nx = (p == 0) ? n0 : (p == 1) ? n1 : n2;
    int i = blockIdx.x * blockDim.x + threadIdx.x;
    if (i < NEDGE) atomicAdd(&g_deg[p][e[NEDGE + i]], 1);
    if (i < NSP) {
        atomicAdd(&g_cf[p][nx[NSP + i]], 1);
        atomicAdd(&g_cb[p][nx[i]], 1);
    }
}

__global__ void scan_excl_all() {
    int sel = blockIdx.x / 3, p = blockIdx.x % 3;
    const int* in; int* out; int* cur; int n;
    if (sel == 0)      { in = g_deg[p]; out = g_offE[p]; cur = g_curE[p]; n = NHIT; }
    else if (sel == 1) { in = g_cf[p];  out = g_offF[p]; cur = g_curF[p]; n = NSP; }
    else               { in = g_cb[p];  out = g_offB[p]; cur = g_curB[p]; n = NHIT; }
    __shared__ int wsum[32];
    __shared__ int carry;
    int tid = threadIdx.x;
    if (tid == 0) carry = 0;
    __syncthreads();
    for (int base = 0; base < n; base += 1024) {
        int i = base + tid;
        int v = (i < n) ? in[i] : 0;
        int x = v;
        #pragma unroll
        for (int d = 1; d < 32; d <<= 1) {
            int y = __shfl_up_sync(0xffffffffu, x, d);
            if ((tid & 31) >= d) x += y;
        }
        if ((tid & 31) == 31) wsum[tid >> 5] = x;
        __syncthreads();
        if (tid < 32) {
            int s = wsum[tid];
            #pragma unroll
            for (int d = 1; d < 32; d <<= 1) {
                int y = __shfl_up_sync(0xffffffffu, s, d);
                if (tid >= d) s += y;
            }
            wsum[tid] = s;
        }
        __syncthreads();
        int woff = (tid >= 32) ? wsum[(tid >> 5) - 1] : 0;
        int incl = carry + woff + x;
        if (i < n) { out[i] = incl - v; cur[i] = incl - v; }
        __syncthreads();
        if (tid == 1023) carry = incl;
        __syncthreads();
    }
    if (tid == 0) out[n] = carry;
}

__global__ void fill_all(const int* __restrict__ e0, const int* __restrict__ e1,
                         const int* __restrict__ e2, const int* __restrict__ n0,
                         const int* __restrict__ n1, const int* __restrict__ n2) {
    int p = blockIdx.y;
    const int* e = (p == 0) ? e0 : (p == 1) ? e1 : e2;
    const int* nx = (p == 0) ? n0 : (p == 1) ? n1 : n2;
    int i = blockIdx.x * blockDim.x + threadIdx.x;
    if (i < NEDGE) {
        int dst = e[NEDGE + i];
        g_csrE[p][atomicAdd(&g_curE[p][dst], 1)] = e[i];
    }
    if (i < NSP) {
        int s = nx[NSP + i];
        g_csrF[p][atomicAdd(&g_curF[p][s], 1)] = nx[i];
        int h = nx[i];
        g_csrB[p][atomicAdd(&g_curB[p][h], 1)] = nx[NSP + i];
    }
}

// ---------------- encoder (fp16 state) ----------------
__global__ void encoder_k(const float* __restrict__ x0, const float* __restrict__ x1,
                          const float* __restrict__ x2, const float* __restrict__ W,
                          const float* __restrict__ b, __half* __restrict__ h16base) {
    int p = blockIdx.y;
    const float* x = (p == 0) ? x0 : (p == 1) ? x1 : x2;
    int idx = blockIdx.x * blockDim.x + threadIdx.x;
    if (idx >= NHIT * HD) return;
    int n = idx >> 7, j = idx & 127;
    float acc = b[j];
    #pragma unroll
    for (int k = 0; k < 4; k++) acc = fmaf(x[n * 4 + k], W[k * HD + j], acc);
    acc = fmaxf(acc, 0.f);
    h16base[(size_t)p * PSTRIDE + idx] = __float2half(acc);
}

// ---------------- planar edge aggregation (2-way unrolled MLP) ----------------
__global__ void planar_agg(const float* __restrict__ b1) {
    int p = blockIdx.y;
    int warp = (blockIdx.x * blockDim.x + threadIdx.x) >> 5;
    if (warp >= NHIT) return;
    int lane = threadIdx.x & 31;
    int n = warp;
    uint2 ar = *reinterpret_cast<const uint2*>(&g_A[p][(size_t)n * HD + lane * 4]);
    float2 a01 = __half22float2(*reinterpret_cast<__half2*>(&ar.x));
    float2 a23 = __half22float2(*reinterpret_cast<__half2*>(&ar.y));
    float4 bb = *reinterpret_cast<const float4*>(&b1[lane * 4]);
    int s = g_offE[p][n], e = g_offE[p][n + 1];
    float4 acc0 = make_float4(0.f, 0.f, 0.f, 0.f);
    float4 acc1 = make_float4(0.f, 0.f, 0.f, 0.f);
    int i = s;
    for (; i + 2 <= e; i += 2) {
        int s0 = g_csrE[p][i], s1 = g_csrE[p][i + 1];
        uint2 br0 = *reinterpret_cast<const uint2*>(&g_B[p][(size_t)s0 * HD + lane * 4]);
        uint2 br1 = *reinterpret_cast<const uint2*>(&g_B[p][(size_t)s1 * HD + lane * 4]);
        float2 b001 = __half22float2(*reinterpret_cast<__half2*>(&br0.x));
        float2 b023 = __half22float2(*reinterpret_cast<__half2*>(&br0.y));
        float2 b101 = __half22float2(*reinterpret_cast<__half2*>(&br1.x));
        float2 b123 = __half22float2(*reinterpret_cast<__half2*>(&br1.y));
        acc0.x += fmaxf(a01.x + b001.x + bb.x, 0.f);
        acc0.y += fmaxf(a01.y + b001.y + bb.y, 0.f);
        acc0.z += fmaxf(a23.x + b023.x + bb.z, 0.f);
        acc0.w += fmaxf(a23.y + b023.y + bb.w, 0.f);
        acc1.x += fmaxf(a01.x + b101.x + bb.x, 0.f);
        acc1.y += fmaxf(a01.y + b101.y + bb.y, 0.f);
        acc1.z += fmaxf(a23.x + b123.x + bb.z, 0.f);
        acc1.w += fmaxf(a23.y + b123.y + bb.w, 0.f);
    }
    if (i < e) {
        int s0 = g_csrE[p][i];
        uint2 br0 = *reinterpret_cast<const uint2*>(&g_B[p][(size_t)s0 * HD + lane * 4]);
        float2 b001 = __half22float2(*reinterpret_cast<__half2*>(&br0.x));
        float2 b023 = __half22float2(*reinterpret_cast<__half2*>(&br0.y));
        acc0.x += fmaxf(a01.x + b001.x + bb.x, 0.f);
        acc0.y += fmaxf(a01.y + b001.y + bb.y, 0.f);
        acc0.z += fmaxf(a23.x + b023.x + bb.z, 0.f);
        acc0.w += fmaxf(a23.y + b023.y + bb.w, 0.f);
    }
    float4 acc = make_float4(acc0.x + acc1.x, acc0.y + acc1.y,
                             acc0.z + acc1.z, acc0.w + acc1.w);
    float inv = (e > s) ? 1.f / (float)(e - s) : 0.f;
    uint2 o;
    *reinterpret_cast<__half2*>(&o.x) = __floats2half2_rn(acc.x * inv, acc.y * inv);
    *reinterpret_cast<__half2*>(&o.y) = __floats2half2_rn(acc.z * inv, acc.w * inv);
    *reinterpret_cast<uint2*>(&g_mr[p][(size_t)n * HD + lane * 4]) = o;
}

// ---------------- nexus forward (2-way unrolled) ----------------
__global__ void nexus_fwd(const __half* __restrict__ h16base) {
    int warp = (blockIdx.x * blockDim.x + threadIdx.x) >> 5;
    if (warp >= NSP) return;
    int lane = threadIdx.x & 31;
    int s = warp;
    float4 tot = make_float4(0.f, 0.f, 0.f, 0.f);
    #pragma unroll
    for (int p = 0; p < 3; p++) {
        const __half* h = h16base + (size_t)p * PSTRIDE;
        int st = g_offF[p][s], en = g_offF[p][s + 1];
        float4 acc0 = make_float4(0.f, 0.f, 0.f, 0.f);
        float4 acc1 = make_float4(0.f, 0.f, 0.f, 0.f);
        int i = st;
        for (; i + 2 <= en; i += 2) {
            int h0i = g_csrF[p][i], h1i = g_csrF[p][i + 1];
            uint2 v0 = *reinterpret_cast<const uint2*>(&h[(size_t)h0i * HD + lane * 4]);
            uint2 v1 = *reinterpret_cast<const uint2*>(&h[(size_t)h1i * HD + lane * 4]);
            float2 a01 = __half22float2(*reinterpret_cast<__half2*>(&v0.x));
            float2 a23 = __half22float2(*reinterpret_cast<__half2*>(&v0.y));
            float2 c01 = __half22float2(*reinterpret_cast<__half2*>(&v1.x));
            float2 c23 = __half22float2(*reinterpret_cast<__half2*>(&v1.y));
            acc0.x += a01.x; acc0.y += a01.y; acc0.z += a23.x; acc0.w += a23.y;
            acc1.x += c01.x; acc1.y += c01.y; acc1.z += c23.x; acc1.w += c23.y;
        }
        if (i < en) {
            int h0i = g_csrF[p][i];
            uint2 v0 = *reinterpret_cast<const uint2*>(&h[(size_t)h0i * HD + lane * 4]);
            float2 a01 = __half22float2(*reinterpret_cast<__half2*>(&v0.x));
            float2 a23 = __half22float2(*reinterpret_cast<__half2*>(&v0.y));
            acc0.x += a01.x; acc0.y += a01.y; acc0.z += a23.x; acc0.w += a23.y;
        }
        if (en > st) {
            float inv = 1.f / (float)(en - st);
            tot.x += (acc0.x + acc1.x) * inv; tot.y += (acc0.y + acc1.y) * inv;
            tot.z += (acc0.z + acc1.z) * inv; tot.w += (acc0.w + acc1.w) * inv;
        }
    }
    uint2 o;
    *reinterpret_cast<__half2*>(&o.x) = __floats2half2_rn(tot.x, tot.y);
    *reinterpret_cast<__half2*>(&o.y) = __floats2half2_rn(tot.z, tot.w);
    *reinterpret_cast<uint2*>(&g_spsum[(size_t)s * HD + lane * 4]) = o;
}

// ---------------- nexus backward (2-way unrolled) ----------------
__global__ void nexus_back() {
    int p = blockIdx.y;
    int warp = (blockIdx.x * blockDim.x + threadIdx.x) >> 5;
    if (warp >= NHIT) return;
    int lane = threadIdx.x & 31;
    int n = warp;
    int st = g_offB[p][n], en = g_offB[p][n + 1];
    float4 acc0 = make_float4(0.f, 0.f, 0.f, 0.f);
    float4 acc1 = make_float4(0.f, 0.f, 0.f, 0.f);
    int i = st;
    for (; i + 2 <= en; i += 2) {
        int s0 = g_csrB[p][i], s1 = g_csrB[p][i + 1];
        uint2 v0 = *reinterpret_cast<const uint2*>(&g_sp[(size_t)s0 * HD + lane * 4]);
        uint2 v1 = *reinterpret_cast<const uint2*>(&g_sp[(size_t)s1 * HD + lane * 4]);
        float2 a01 = __half22float2(*reinterpret_cast<__half2*>(&v0.x));
        float2 a23 = __half22float2(*reinterpret_cast<__half2*>(&v0.y));
        float2 c01 = __half22float2(*reinterpret_cast<__half2*>(&v1.x));
        float2 c23 = __half22float2(*reinterpret_cast<__half2*>(&v1.y));
        acc0.x += a01.x; acc0.y += a01.y; acc0.z += a23.x; acc0.w += a23.y;
        acc1.x += c01.x; acc1.y += c01.y; acc1.z += c23.x; acc1.w += c23.y;
    }
    if (i < en) {
        int s0 = g_csrB[p][i];
        uint2 v0 = *reinterpret_cast<const uint2*>(&g_sp[(size_t)s0 * HD + lane * 4]);
        float2 a01 = __half22float2(*reinterpret_cast<__half2*>(&v0.x));
        float2 a23 = __half22float2(*reinterpret_cast<__half2*>(&v0.y));
        acc0.x += a01.x; acc0.y += a01.y; acc0.z += a23.x; acc0.w += a23.y;
    }
    float inv = (en > st) ? 1.f / (float)(en - st) : 0.f;
    uint2 o;
    *reinterpret_cast<__half2*>(&o.x) =
        __floats2half2_rn((acc0.x + acc1.x) * inv, (acc0.y + acc1.y) * inv);
    *reinterpret_cast<__half2*>(&o.y) =
        __floats2half2_rn((acc0.z + acc1.z) * inv, (acc0.w + acc1.w) * inv);
    *reinterpret_cast<uint2*>(&g_back[p][(size_t)n * HD + lane * 4]) = o;
}

// ---------------- decoder (fp16 state in, fp32 out) ----------------
__global__ void decoder_k(const __half* __restrict__ hbase, const float* __restrict__ Wsem,
                          const float* __restrict__ bsem, float* __restrict__ out) {
    int p = blockIdx.y;
    const __half* h = hbase + (size_t)p * PSTRIDE;
    float* o = out + (size_t)p * NHIT * NCLASS;
    int warp = (blockIdx.x * blockDim.x + threadIdx.x) >> 5;
    if (warp >= NHIT) return;
    int lane = threadIdx.x & 31;
    int n = warp;
    float hv[4];
    #pragma unroll
    for (int t = 0; t < 4; t++) hv[t] = __half2float(h[(size_t)n * HD + lane + t * 32]);
    #pragma unroll
    for (int c = 0; c < NCLASS; c++) {
        float s = 0.f;
        #pragma unroll
        for (int t = 0; t < 4; t++) s = fmaf(hv[t], Wsem[(lane + t * 32) * NCLASS + c], s);
        #pragma unroll
        for (int d = 16; d > 0; d >>= 1) s += __shfl_down_sync(0xffffffffu, s, d);
        if (lane == 0) o[n * NCLASS + c] = s + bsem[c];
    }
}

// ---------------- host ----------------
extern "C" void kernel_launch(void* const* d_in, const int* in_sizes, int n_in,
                              void* d_out, int out_size) {
    int xi[3], ei[3], ni[3];
    if (in_sizes[1] == 2 * NEDGE) {
        for (int p = 0; p < 3; p++) { xi[p] = 3 * p; ei[p] = 3 * p + 1; ni[p] = 3 * p + 2; }
    } else {
        for (int p = 0; p < 3; p++) { xi[p] = p; ei[p] = 3 + p; ni[p] = 6 + p; }
    }
    const float* x[3]; const int* edge[3]; const int* nexus[3];
    for (int p = 0; p < 3; p++) {
        x[p] = (const float*)d_in[xi[p]];
        edge[p] = (const int*)d_in[ei[p]];
        nexus[p] = (const int*)d_in[ni[p]];
    }
    const float* W_enc  = (const float*)d_in[9];
    const float* b_enc  = (const float*)d_in[10];
    const float* W_msg1 = (const float*)d_in[11];
    const float* b_msg1 = (const float*)d_in[12];
    const float* W_msg2 = (const float*)d_in[13];
    const float* b_msg2 = (const float*)d_in[14];
    const float* W_upd  = (const float*)d_in[15];
    const float* b_upd  = (const float*)d_in[16];
    const float* W_sp   = (const float*)d_in[17];
    const float* b_sp   = (const float*)d_in[18];
    const float* W_nx   = (const float*)d_in[19];
    const float* b_nx   = (const float*)d_in[20];
    const float* W_sem  = (const float*)d_in[21];
    const float* b_sem  = (const float*)d_in[22];

    float *pwcomb, *pb2c; int* pdeg;
    __half *ph16, *pA, *pB, *pmr, *pspsum, *psp, *pback;
    cudaGetSymbolAddress((void**)&ph16, g_h16);
    cudaGetSymbolAddress((void**)&pA, g_A);
    cudaGetSymbolAddress((void**)&pB, g_B);
    cudaGetSymbolAddress((void**)&pmr, g_mr);
    cudaGetSymbolAddress((void**)&pspsum, g_spsum);
    cudaGetSymbolAddress((void**)&psp, g_sp);
    cudaGetSymbolAddress((void**)&pback, g_back);
    cudaGetSymbolAddress((void**)&pwcomb, g_wcomb);
    cudaGetSymbolAddress((void**)&pb2c, g_b2c);
    cudaGetSymbolAddress((void**)&pdeg, g_deg);

    cudaFuncSetAttribute(gemm_mma, cudaFuncAttributeMaxDynamicSharedMemorySize, SM_TOTAL);
    cudaFuncSetAttribute(gemm_dual, cudaFuncAttributeMaxDynamicSharedMemorySize, DU_TOTAL);

    __half* h16_0 = ph16;
    __half* h16_1 = ph16 + (size_t)3 * PSTRIDE;

    const int T = 256;
    dim3 gG3((NHIT + 127) / 128, 3);
    dim3 gG1((NSP + 127) / 128, 1);
    dim3 gW3((NHIT * 32 + T - 1) / T, 3);
    int gW1 = (NSP * 32 + T - 1) / T;
    dim3 gE((NHIT * HD + T - 1) / T, 3);

    // --- CSR build ---
    zero_counts<<<(NHIT + T - 1) / T, T>>>();
    dim3 gCnt((NEDGE + T - 1) / T, 3);
    count_all<<<gCnt, T>>>(edge[0], edge[1], edge[2], nexus[0], nexus[1], nexus[2]);
    scan_excl_all<<<9, 1024>>>();
    fill_all<<<gCnt, T>>>(edge[0], edge[1], edge[2], nexus[0], nexus[1], nexus[2]);

    // --- weight combine + prep (0=W1top 1=W1bot 2=WupdT 3=comb 4=Wsp 5=WnxT 6=WnxB) ---
    combine_w<<<129, 128>>>(W_msg2, W_upd + 128 * 128, b_msg2);
    prep_w<<<224, 256>>>(W_msg1, W_msg1 + 128 * 128, W_upd, pwcomb,
                         W_sp, W_nx, W_nx + 128 * 128);

    // --- encoder ---
    encoder_k<<<gE, T>>>(x[0], x[1], x[2], W_enc, b_enc, h16_0);

    for (int it = 0; it < 3; it++) {
        gemm_dual<<<gG3, T, DU_TOTAL>>>(h16_0, PSTRIDE, 0, 1, pA, pB, NHIT);
        planar_agg<<<gW3, T>>>(b_msg1);
        gemm_mma<<<gG3, T, SM_TOTAL>>>(h16_0, pmr, PSTRIDE, 2, 2, 0, b_upd, pb2c,
                                       pdeg, NHIT, h16_0, h16_1, NHIT, EPI_RESRELU_DEG);
        nexus_fwd<<<gW1, T>>>(h16_1);
        gemm_mma<<<gG1, T, SM_TOTAL>>>(pspsum, nullptr, 0, 4, 1, 0, b_sp, nullptr,
                                       nullptr, 0, nullptr, psp, NSP, EPI_RELU);
        nexus_back<<<gW3, T>>>();
        gemm_mma<<<gG3, T, SM_TOTAL>>>(h16_1, pback, PSTRIDE, 5, 2, 0, b_nx, nullptr,
                                       nullptr, 0, h16_1, h16_0, NHIT, EPI_RESRELU);
    }

    decoder_k<<<gW3, T>>>(h16_0, W_sem, b_sem, (float*)d_out);
}

// round 17
// speedup vs baseline: 1.7600x; 1.0718x over previous
#include <cuda_runtime.h>
#include <cuda_fp16.h>
#include <cstdint>

#define NHIT 30000
#define NEDGE 90000
#define NSP 30000
#define HD 128
#define NCLASS 5
#define PSTRIDE (NHIT * HD)

// ---------------- device scratch ----------------
__device__ __half g_h16[2][3][NHIT * HD];       // fp16 hidden state (ping-pong)
__device__ __half g_A[3][NHIT * HD];
__device__ __half g_B[3][NHIT * HD];
__device__ __half g_mr[3][NHIT * HD];
__device__ __half g_spsum[NSP * HD];
__device__ __half g_sp[NSP * HD];
__device__ __half g_back[3][NHIT * HD];
__device__ float g_wcomb[HD * HD];              // W_msg2 @ W_upd_bottom
__device__ float g_b2c[HD];                     // b_msg2 @ W_upd_bottom

// prepped weights: 7 chunks x 2 k-stages x (128n x 64k fp16, swizzled)
__device__ uint4 g_wbuf[7][2][1024];

__device__ int g_deg[3][NHIT];
__device__ int g_cf[3][NSP];
__device__ int g_cb[3][NHIT];
__device__ int g_offE[3][NHIT + 1];
__device__ int g_offF[3][NSP + 1];
__device__ int g_offB[3][NHIT + 1];
__device__ int g_csrE[3][NEDGE];
__device__ int g_csrF[3][NSP];
__device__ int g_csrB[3][NSP];
__device__ int g_curE[3][NHIT];
__device__ int g_curF[3][NSP];
__device__ int g_curB[3][NHIT];

enum { EPI_RELU = 1, EPI_RESRELU = 2, EPI_RESRELU_DEG = 4 };

// ---------------- helpers ----------------
__device__ __forceinline__ uint32_t s2u(const void* p) {
    return (uint32_t)__cvta_generic_to_shared(p);
}
__device__ __forceinline__ uint32_t pack2h(float a, float b) {
    __half2 t = __floats2half2_rn(a, b);
    return *reinterpret_cast<uint32_t*>(&t);
}
__device__ __forceinline__ uint32_t swz(int row, int k) {
    return (uint32_t)(row * 128 + ((((k >> 3) ^ row) & 7) << 4) + (k & 7) * 2);
}
__device__ __forceinline__ void unp8(const uint4& v, float* f) {
    float2 t;
    t = __half22float2(*reinterpret_cast<const __half2*>(&v.x)); f[0] = t.x; f[1] = t.y;
    t = __half22float2(*reinterpret_cast<const __half2*>(&v.y)); f[2] = t.x; f[3] = t.y;
    t = __half22float2(*reinterpret_cast<const __half2*>(&v.z)); f[4] = t.x; f[5] = t.y;
    t = __half22float2(*reinterpret_cast<const __half2*>(&v.w)); f[6] = t.x; f[7] = t.y;
}
__device__ __forceinline__ uint4 pck8(const float* f) {
    uint4 o;
    *reinterpret_cast<__half2*>(&o.x) = __floats2half2_rn(f[0], f[1]);
    *reinterpret_cast<__half2*>(&o.y) = __floats2half2_rn(f[2], f[3]);
    *reinterpret_cast<__half2*>(&o.z) = __floats2half2_rn(f[4], f[5]);
    *reinterpret_cast<__half2*>(&o.w) = __floats2half2_rn(f[6], f[7]);
    return o;
}
__device__ __forceinline__ void ldsm4(uint32_t* r, uint32_t addr) {
    asm volatile("ldmatrix.sync.aligned.m8n8.x4.shared.b16 {%0,%1,%2,%3}, [%4];"
                 : "=r"(r[0]), "=r"(r[1]), "=r"(r[2]), "=r"(r[3]) : "r"(addr));
}
__device__ __forceinline__ void mma16816(float* c, const uint32_t* a, uint32_t b0, uint32_t b1) {
    asm volatile(
        "mma.sync.aligned.m16n8k16.row.col.f32.f16.f16.f32 "
        "{%0,%1,%2,%3}, {%4,%5,%6,%7}, {%8,%9}, {%0,%1,%2,%3};"
        : "+f"(c[0]), "+f"(c[1]), "+f"(c[2]), "+f"(c[3])
        : "r"(a[0]), "r"(a[1]), "r"(a[2]), "r"(a[3]), "r"(b0), "r"(b1));
}
__device__ __forceinline__ void cpa8(uint32_t dst, const void* src) {
    asm volatile("cp.async.ca.shared.global [%0], [%1], 8;" :: "r"(dst), "l"(src));
}
__device__ __forceinline__ void cpa16(uint32_t dst, const void* src) {
    asm volatile("cp.async.cg.shared.global [%0], [%1], 16;" :: "r"(dst), "l"(src));
}
#define CP_COMMIT() asm volatile("cp.async.commit_group;")
#define CP_WAIT1()  asm volatile("cp.async.wait_group 1;")
#define CP_WAIT0()  asm volatile("cp.async.wait_group 0;")

// gemm_mma: 2 pipeline buffers x [A 16K | B 16K]
#define PB_A 0
#define PB_B 16384
#define PB_SZ 32768
#define SM_TOTAL 65536
// gemm_dual: A (both halves) 32K + 2 B-buffers x 16K
#define DU_A 0
#define DU_B 32768
#define DU_BSZ 16384
#define DU_TOTAL 65536

// ---------------- weight combine ----------------
__global__ void combine_w(const float* __restrict__ W2, const float* __restrict__ Wub,
                          const float* __restrict__ b2) {
    int n = threadIdx.x;
    int k = blockIdx.x;
    if (k < 128) {
        float s = 0.f;
        #pragma unroll 8
        for (int j = 0; j < 128; j++) s = fmaf(W2[k * 128 + j], Wub[j * 128 + n], s);
        g_wcomb[k * 128 + n] = s;
    } else {
        float s = 0.f;
        #pragma unroll 8
        for (int j = 0; j < 128; j++) s = fmaf(b2[j], Wub[j * 128 + n], s);
        g_b2c[n] = s;
    }
}

// ---------------- weight prep (hi only) ----------------
__global__ void prep_w(const float* w0, const float* w1, const float* w2,
                       const float* w3, const float* w4, const float* w5,
                       const float* w6) {
    int id = blockIdx.x * blockDim.x + threadIdx.x;
    if (id >= 7 * 8192) return;
    int c = id >> 13;
    int rem = id & 8191;
    int s = rem >> 12;
    int rem2 = rem & 4095;
    int n = rem2 >> 5;
    int kp = (rem2 & 31) * 2;
    const float* Wc = (c == 0) ? w0 : (c == 1) ? w1 : (c == 2) ? w2 : (c == 3) ? w3
                    : (c == 4) ? w4 : (c == 5) ? w5 : w6;
    float v0 = Wc[(s * 64 + kp) * 128 + n];
    float v1 = Wc[(s * 64 + kp + 1) * 128 + n];
    *reinterpret_cast<uint32_t*>((char*)&g_wbuf[c][s][0] + swz(n, kp)) = pack2h(v0, v1);
}

// ---------------- HMMA 1-pass GEMM, cp.async double-buffered ----------------
__global__ __launch_bounds__(256, 2) void gemm_mma(
    const __half* __restrict__ Ah0, const __half* __restrict__ Ah1,
    int sA, int wc0, int nchunks,
    const float* __restrict__ bias, const float* __restrict__ bias2,
    const int* __restrict__ mask, int sMask,
    const __half* __restrict__ resid,
    __half* __restrict__ outh, int M, int epi)
{
    extern __shared__ char smem[];
    uint32_t sb = s2u(smem);
    int tid = threadIdx.x;
    int wid = tid >> 5, lane = tid & 31;
    int mwarp = wid & 3, nwarp = wid >> 2;
    int row0 = blockIdx.x * 128;
    int pl = blockIdx.y;
    const __half* Ah0p = Ah0 + (size_t)pl * sA;
    const __half* Ah1p = Ah1 ? (Ah1 + (size_t)pl * sA) : nullptr;
    const __half* residp = resid ? (resid + (size_t)pl * sA) : nullptr;
    const int* maskp = mask ? (mask + (size_t)pl * sMask) : nullptr;

    float C[2][8][4];
    #pragma unroll
    for (int mt = 0; mt < 2; mt++)
        #pragma unroll
        for (int nt = 0; nt < 8; nt++)
            #pragma unroll
            for (int q = 0; q < 4; q++) C[mt][nt][q] = 0.f;

    int a_row_in16 = (lane & 7) + ((lane >> 3) & 1) * 8;
    int a_kb = (lane >> 4) & 1;
    int b_row_in16 = (lane & 7) + ((lane >> 4) & 1) * 8;
    int b_kb = (lane >> 3) & 1;

    int nst = nchunks * 2;

    auto prefetch = [&](int s) {
        int ch = s >> 1, kh = s & 1;
        const __half* src = ch ? Ah1p : Ah0p;
        uint32_t bb = sb + (uint32_t)((s & 1) * PB_SZ);
        #pragma unroll
        for (int l = 0; l < 8; l++) {
            int i = l * 256 + tid;
            int r = i >> 4, c4 = (i & 15) * 4;
            int row = row0 + r; if (row >= M) row = M - 1;
            cpa8(bb + PB_A + swz(r, c4), &src[(size_t)row * 128 + kh * 64 + c4]);
        }
        const uint4* bh = &g_wbuf[wc0 + ch][kh][0];
        #pragma unroll
        for (int l = 0; l < 4; l++) {
            int i = l * 256 + tid;
            cpa16(bb + PB_B + (uint32_t)i * 16, bh + i);
        }
        CP_COMMIT();
    };

    prefetch(0);
    for (int s = 0; s < nst; s++) {
        if (s + 1 < nst) { prefetch(s + 1); CP_WAIT1(); }
        else             { CP_WAIT0(); }
        __syncthreads();
        uint32_t ab = sb + (uint32_t)((s & 1) * PB_SZ);

        #pragma unroll
        for (int k16 = 0; k16 < 4; k16++) {
            uint32_t a[2][4];
            #pragma unroll
            for (int mt = 0; mt < 2; mt++) {
                int row = mwarp * 32 + mt * 16 + a_row_in16;
                uint32_t o = (uint32_t)(row * 128 + ((((k16 * 2 + a_kb) ^ row) & 7) << 4));
                ldsm4(a[mt], ab + PB_A + o);
            }
            #pragma unroll
            for (int ntp = 0; ntp < 4; ntp++) {
                int nrow = nwarp * 64 + ntp * 16 + b_row_in16;
                uint32_t o = (uint32_t)(nrow * 128 + ((((k16 * 2 + b_kb) ^ nrow) & 7) << 4));
                uint32_t bhi[4];
                ldsm4(bhi, ab + PB_B + o);
                #pragma unroll
                for (int half = 0; half < 2; half++) {
                    int nt = ntp * 2 + half;
                    #pragma unroll
                    for (int mt = 0; mt < 2; mt++)
                        mma16816(C[mt][nt], a[mt], bhi[half * 2], bhi[half * 2 + 1]);
                }
            }
        }
        __syncthreads();
    }

    int qrow = lane >> 2;
    int qcol = (lane & 3) * 2;
    #pragma unroll
    for (int mt = 0; mt < 2; mt++) {
        #pragma unroll
        for (int half = 0; half < 2; half++) {
            int row = row0 + mwarp * 32 + mt * 16 + qrow + half * 8;
            if (row >= M) continue;
            bool dg = (epi == EPI_RESRELU_DEG) ? (maskp[row] > 0) : false;
            #pragma unroll
            for (int nt = 0; nt < 8; nt++) {
                int col = nwarp * 64 + nt * 8 + qcol;
                float v0 = C[mt][nt][half * 2 + 0];
                float v1 = C[mt][nt][half * 2 + 1];
                float o0, o1;
                if (epi == EPI_RELU) {
                    o0 = fmaxf(v0 + bias[col], 0.f);
                    o1 = fmaxf(v1 + bias[col + 1], 0.f);
                } else {
                    float e0 = v0 + bias[col], e1 = v1 + bias[col + 1];
                    if (epi == EPI_RESRELU_DEG && dg) { e0 += bias2[col]; e1 += bias2[col + 1]; }
                    float2 rr = __half22float2(
                        *reinterpret_cast<const __half2*>(&residp[(size_t)row * 128 + col]));
                    o0 = rr.x + fmaxf(e0, 0.f);
                    o1 = rr.y + fmaxf(e1, 0.f);
                }
                *reinterpret_cast<__half2*>(&outh[(size_t)pl * sA + (size_t)row * 128 + col]) =
                    __floats2half2_rn(o0, o1);
            }
        }
    }
}

// ---------------- dual-output GEMM, 1-pass, cp.async pipelined B ----------------
__global__ __launch_bounds__(256, 2) void gemm_dual(
    const __half* __restrict__ A, int sA, int wc0, int wc1,
    __half* __restrict__ out0, __half* __restrict__ out1, int M)
{
    extern __shared__ char smem[];
    uint32_t sb = s2u(smem);
    int tid = threadIdx.x;
    int wid = tid >> 5, lane = tid & 31;
    int mwarp = wid & 3, nwarp = wid >> 2;
    int row0 = blockIdx.x * 128;
    int pl = blockIdx.y;
    const __half* Ap = A + (size_t)pl * sA;
    __half* o0 = out0 + (size_t)pl * sA;
    __half* o1 = out1 + (size_t)pl * sA;

    int a_row_in16 = (lane & 7) + ((lane >> 3) & 1) * 8;
    int a_kb = (lane >> 4) & 1;
    int b_row_in16 = (lane & 7) + ((lane >> 4) & 1) * 8;
    int b_kb = (lane >> 3) & 1;
    int qrow = lane >> 2;
    int qcol = (lane & 3) * 2;

    auto prefetchB = [&](int s) {
        int w = s >> 1, kh = s & 1;
        int wc = w ? wc1 : wc0;
        uint32_t bb = sb + DU_B + (uint32_t)((s & 1) * DU_BSZ);
        const uint4* bh = &g_wbuf[wc][kh][0];
        #pragma unroll
        for (int l = 0; l < 4; l++) {
            int i = l * 256 + tid;
            cpa16(bb + (uint32_t)i * 16, bh + i);
        }
        CP_COMMIT();
    };

    #pragma unroll
    for (int l = 0; l < 16; l++) {
        int i = l * 256 + tid;
        int r = i >> 5, c4 = (i & 31) * 4;
        int sh = c4 >> 6, k = c4 & 63;
        int row = row0 + r; if (row >= M) row = M - 1;
        cpa8(sb + DU_A + sh * 16384 + swz(r, k), &Ap[(size_t)row * 128 + c4]);
    }
    prefetchB(0);

    float C[2][8][4];
    for (int s = 0; s < 4; s++) {
        if (s + 1 < 4) { prefetchB(s + 1); CP_WAIT1(); }
        else           { CP_WAIT0(); }
        __syncthreads();

        if ((s & 1) == 0) {
            #pragma unroll
            for (int mt = 0; mt < 2; mt++)
                #pragma unroll
                for (int nt = 0; nt < 8; nt++)
                    #pragma unroll
                    for (int q = 0; q < 4; q++) C[mt][nt][q] = 0.f;
        }

        uint32_t abase = sb + DU_A + (uint32_t)((s & 1) * 16384);
        uint32_t bbase = sb + DU_B + (uint32_t)((s & 1) * DU_BSZ);
        #pragma unroll
        for (int k16 = 0; k16 < 4; k16++) {
            uint32_t a[2][4];
            #pragma unroll
            for (int mt = 0; mt < 2; mt++) {
                int row = mwarp * 32 + mt * 16 + a_row_in16;
                uint32_t o = (uint32_t)(row * 128 + ((((k16 * 2 + a_kb) ^ row) & 7) << 4));
                ldsm4(a[mt], abase + o);
            }
            #pragma unroll
            for (int ntp = 0; ntp < 4; ntp++) {
                int nrow = nwarp * 64 + ntp * 16 + b_row_in16;
                uint32_t o = (uint32_t)(nrow * 128 + ((((k16 * 2 + b_kb) ^ nrow) & 7) << 4));
                uint32_t bhi[4];
                ldsm4(bhi, bbase + o);
                #pragma unroll
                for (int half = 0; half < 2; half++) {
                    int nt = ntp * 2 + half;
                    #pragma unroll
                    for (int mt = 0; mt < 2; mt++)
                        mma16816(C[mt][nt], a[mt], bhi[half * 2], bhi[half * 2 + 1]);
                }
            }
        }
        __syncthreads();

        if (s & 1) {
            __half* op = (s >> 1) ? o1 : o0;
            #pragma unroll
            for (int mt = 0; mt < 2; mt++) {
                #pragma unroll
                for (int half = 0; half < 2; half++) {
                    int row = row0 + mwarp * 32 + mt * 16 + qrow + half * 8;
                    if (row >= M) continue;
                    #pragma unroll
                    for (int nt = 0; nt < 8; nt++) {
                        int col = nwarp * 64 + nt * 8 + qcol;
                        *reinterpret_cast<__half2*>(&op[(size_t)row * 128 + col]) =
                            __floats2half2_rn(C[mt][nt][half * 2], C[mt][nt][half * 2 + 1]);
                    }
                }
            }
        }
    }
}

// ---------------- CSR build ----------------
__global__ void zero_counts() {
    int i = blockIdx.x * blockDim.x + threadIdx.x;
    if (i < NHIT) {
        #pragma unroll
        for (int p = 0; p < 3; p++) { g_deg[p][i] = 0; g_cb[p][i] = 0; }
    }
    if (i < NSP) {
        #pragma unroll
        for (int p = 0; p < 3; p++) g_cf[p][i] = 0;
    }
}

__global__ void count_all(const int* __restrict__ e0, const int* __restrict__ e1,
                          const int* __restrict__ e2, const int* __restrict__ n0,
                          const int* __restrict__ n1, const int* __restrict__ n2) {
    int p = blockIdx.y;
    const int* e = (p == 0) ? e0 : (p == 1) ? e1 : e2;
    const int* nx = (p == 0) ? n0 : (p == 1) ? n1 : n2;
    int i = blockIdx.x * blockDim.x + threadIdx.x;
    if (i < NEDGE) atomicAdd(&g_deg[p][e[NEDGE + i]], 1);
    if (i < NSP) {
        atomicAdd(&g_cf[p][nx[NSP + i]], 1);
        atomicAdd(&g_cb[p][nx[i]], 1);
    }
}

__global__ void scan_excl_all() {
    int sel = blockIdx.x / 3, p = blockIdx.x % 3;
    const int* in; int* out; int* cur; int n;
    if (sel == 0)      { in = g_deg[p]; out = g_offE[p]; cur = g_curE[p]; n = NHIT; }
    else if (sel == 1) { in = g_cf[p];  out = g_offF[p]; cur = g_curF[p]; n = NSP; }
    else               { in = g_cb[p];  out = g_offB[p]; cur = g_curB[p]; n = NHIT; }
    __shared__ int wsum[32];
    __shared__ int carry;
    int tid = threadIdx.x;
    if (tid == 0) carry = 0;
    __syncthreads();
    for (int base = 0; base < n; base += 1024) {
        int i = base + tid;
        int v = (i < n) ? in[i] : 0;
        int x = v;
        #pragma unroll
        for (int d = 1; d < 32; d <<= 1) {
            int y = __shfl_up_sync(0xffffffffu, x, d);
            if ((tid & 31) >= d) x += y;
        }
        if ((tid & 31) == 31) wsum[tid >> 5] = x;
        __syncthreads();
        if (tid < 32) {
            int s = wsum[tid];
            #pragma unroll
            for (int d = 1; d < 32; d <<= 1) {
                int y = __shfl_up_sync(0xffffffffu, s, d);
                if (tid >= d) s += y;
            }
            wsum[tid] = s;
        }
        __syncthreads();
        int woff = (tid >= 32) ? wsum[(tid >> 5) - 1] : 0;
        int incl = carry + woff + x;
        if (i < n) { out[i] = incl - v; cur[i] = incl - v; }
        __syncthreads();
        if (tid == 1023) carry = incl;
        __syncthreads();
    }
    if (tid == 0) out[n] = carry;
}

__global__ void fill_all(const int* __restrict__ e0, const int* __restrict__ e1,
                         const int* __restrict__ e2, const int* __restrict__ n0,
                         const int* __restrict__ n1, const int* __restrict__ n2) {
    int p = blockIdx.y;
    const int* e = (p == 0) ? e0 : (p == 1) ? e1 : e2;
    const int* nx = (p == 0) ? n0 : (p == 1) ? n1 : n2;
    int i = blockIdx.x * blockDim.x + threadIdx.x;
    if (i < NEDGE) {
        int dst = e[NEDGE + i];
        g_csrE[p][atomicAdd(&g_curE[p][dst], 1)] = e[i];
    }
    if (i < NSP) {
        int s = nx[NSP + i];
        g_csrF[p][atomicAdd(&g_curF[p][s], 1)] = nx[i];
        int h = nx[i];
        g_csrB[p][atomicAdd(&g_curB[p][h], 1)] = nx[NSP + i];
    }
}

// ---------------- encoder (fp16 state) ----------------
__global__ void encoder_k(const float* __restrict__ x0, const float* __restrict__ x1,
                          const float* __restrict__ x2, const float* __restrict__ W,
                          const float* __restrict__ b, __half* __restrict__ h16base) {
    int p = blockIdx.y;
    const float* x = (p == 0) ? x0 : (p == 1) ? x1 : x2;
    int idx = blockIdx.x * blockDim.x + threadIdx.x;
    if (idx >= NHIT * HD) return;
    int n = idx >> 7, j = idx & 127;
    float acc = b[j];
    #pragma unroll
    for (int k = 0; k < 4; k++) acc = fmaf(x[n * 4 + k], W[k * HD + j], acc);
    acc = fmaxf(acc, 0.f);
    h16base[(size_t)p * PSTRIDE + idx] = __float2half(acc);
}

// ---------------- planar edge aggregation (half-warp per node, uint4) ----------------
__global__ void planar_agg(const float* __restrict__ b1) {
    int p = blockIdx.y;
    int gt = blockIdx.x * blockDim.x + threadIdx.x;
    int n = gt >> 4;
    if (n >= NHIT) return;
    int c8 = (gt & 15) * 8;
    float af[8], bf[8];
    unp8(*reinterpret_cast<const uint4*>(&g_A[p][(size_t)n * HD + c8]), af);
    float4 bb0 = *reinterpret_cast<const float4*>(&b1[c8]);
    float4 bb1 = *reinterpret_cast<const float4*>(&b1[c8 + 4]);
    bf[0] = bb0.x; bf[1] = bb0.y; bf[2] = bb0.z; bf[3] = bb0.w;
    bf[4] = bb1.x; bf[5] = bb1.y; bf[6] = bb1.z; bf[7] = bb1.w;
    int s = g_offE[p][n], e = g_offE[p][n + 1];
    float acc0[8], acc1[8];
    #pragma unroll
    for (int q = 0; q < 8; q++) { acc0[q] = 0.f; acc1[q] = 0.f; }
    int i = s;
    for (; i + 2 <= e; i += 2) {
        int s0 = g_csrE[p][i], s1 = g_csrE[p][i + 1];
        float f0[8], f1[8];
        unp8(*reinterpret_cast<const uint4*>(&g_B[p][(size_t)s0 * HD + c8]), f0);
        unp8(*reinterpret_cast<const uint4*>(&g_B[p][(size_t)s1 * HD + c8]), f1);
        #pragma unroll
        for (int q = 0; q < 8; q++) {
            acc0[q] += fmaxf(af[q] + f0[q] + bf[q], 0.f);
            acc1[q] += fmaxf(af[q] + f1[q] + bf[q], 0.f);
        }
    }
    if (i < e) {
        int s0 = g_csrE[p][i];
        float f0[8];
        unp8(*reinterpret_cast<const uint4*>(&g_B[p][(size_t)s0 * HD + c8]), f0);
        #pragma unroll
        for (int q = 0; q < 8; q++) acc0[q] += fmaxf(af[q] + f0[q] + bf[q], 0.f);
    }
    float inv = (e > s) ? 1.f / (float)(e - s) : 0.f;
    float o[8];
    #pragma unroll
    for (int q = 0; q < 8; q++) o[q] = (acc0[q] + acc1[q]) * inv;
    *reinterpret_cast<uint4*>(&g_mr[p][(size_t)n * HD + c8]) = pck8(o);
}

// ---------------- nexus forward (half-warp per spacepoint, uint4) ----------------
__global__ void nexus_fwd(const __half* __restrict__ h16base) {
    int gt = blockIdx.x * blockDim.x + threadIdx.x;
    int s = gt >> 4;
    if (s >= NSP) return;
    int c8 = (gt & 15) * 8;
    float tot[8];
    #pragma unroll
    for (int q = 0; q < 8; q++) tot[q] = 0.f;
    #pragma unroll
    for (int p = 0; p < 3; p++) {
        const __half* h = h16base + (size_t)p * PSTRIDE;
        int st = g_offF[p][s], en = g_offF[p][s + 1];
        float acc0[8], acc1[8];
        #pragma unroll
        for (int q = 0; q < 8; q++) { acc0[q] = 0.f; acc1[q] = 0.f; }
        int i = st;
        for (; i + 2 <= en; i += 2) {
            int h0i = g_csrF[p][i], h1i = g_csrF[p][i + 1];
            float f0[8], f1[8];
            unp8(*reinterpret_cast<const uint4*>(&h[(size_t)h0i * HD + c8]), f0);
            unp8(*reinterpret_cast<const uint4*>(&h[(size_t)h1i * HD + c8]), f1);
            #pragma unroll
            for (int q = 0; q < 8; q++) { acc0[q] += f0[q]; acc1[q] += f1[q]; }
        }
        if (i < en) {
            int h0i = g_csrF[p][i];
            float f0[8];
            unp8(*reinterpret_cast<const uint4*>(&h[(size_t)h0i * HD + c8]), f0);
            #pragma unroll
            for (int q = 0; q < 8; q++) acc0[q] += f0[q];
        }
        if (en > st) {
            float inv = 1.f / (float)(en - st);
            #pragma unroll
            for (int q = 0; q < 8; q++) tot[q] += (acc0[q] + acc1[q]) * inv;
        }
    }
    *reinterpret_cast<uint4*>(&g_spsum[(size_t)s * HD + c8]) = pck8(tot);
}

// ---------------- nexus backward (half-warp per node, uint4) ----------------
__global__ void nexus_back() {
    int p = blockIdx.y;
    int gt = blockIdx.x * blockDim.x + threadIdx.x;
    int n = gt >> 4;
    if (n >= NHIT) return;
    int c8 = (gt & 15) * 8;
    int st = g_offB[p][n], en = g_offB[p][n + 1];
    float acc0[8], acc1[8];
    #pragma unroll
    for (int q = 0; q < 8; q++) { acc0[q] = 0.f; acc1[q] = 0.f; }
    int i = st;
    for (; i + 2 <= en; i += 2) {
        int s0 = g_csrB[p][i], s1 = g_csrB[p][i + 1];
        float f0[8], f1[8];
        unp8(*reinterpret_cast<const uint4*>(&g_sp[(size_t)s0 * HD + c8]), f0);
        unp8(*reinterpret_cast<const uint4*>(&g_sp[(size_t)s1 * HD + c8]), f1);
        #pragma unroll
        for (int q = 0; q < 8; q++) { acc0[q] += f0[q]; acc1[q] += f1[q]; }
    }
    if (i < en) {
        int s0 = g_csrB[p][i];
        float f0[8];
        unp8(*reinterpret_cast<const uint4*>(&g_sp[(size_t)s0 * HD + c8]), f0);
        #pragma unroll
        for (int q = 0; q < 8; q++) acc0[q] += f0[q];
    }
    float inv = (en > st) ? 1.f / (float)(en - st) : 0.f;
    float o[8];
    #pragma unroll
    for (int q = 0; q < 8; q++) o[q] = (acc0[q] + acc1[q]) * inv;
    *reinterpret_cast<uint4*>(&g_back[p][(size_t)n * HD + c8]) = pck8(o);
}

// ---------------- decoder (fp16 state in, fp32 out) ----------------
__global__ void decoder_k(const __half* __restrict__ hbase, const float* __restrict__ Wsem,
                          const float* __restrict__ bsem, float* __restrict__ out) {
    int p = blockIdx.y;
    const __half* h = hbase + (size_t)p * PSTRIDE;
    float* o = out + (size_t)p * NHIT * NCLASS;
    int warp = (blockIdx.x * blockDim.x + threadIdx.x) >> 5;
    if (warp >= NHIT) return;
    int lane = threadIdx.x & 31;
    int n = warp;
    float hv[4];
    #pragma unroll
    for (int t = 0; t < 4; t++) hv[t] = __half2float(h[(size_t)n * HD + lane + t * 32]);
    #pragma unroll
    for (int c = 0; c < NCLASS; c++) {
        float s = 0.f;
        #pragma unroll
        for (int t = 0; t < 4; t++) s = fmaf(hv[t], Wsem[(lane + t * 32) * NCLASS + c], s);
        #pragma unroll
        for (int d = 16; d > 0; d >>= 1) s += __shfl_down_sync(0xffffffffu, s, d);
        if (lane == 0) o[n * NCLASS + c] = s + bsem[c];
    }
}

// ---------------- host ----------------
extern "C" void kernel_launch(void* const* d_in, const int* in_sizes, int n_in,
                              void* d_out, int out_size) {
    int xi[3], ei[3], ni[3];
    if (in_sizes[1] == 2 * NEDGE) {
        for (int p = 0; p < 3; p++) { xi[p] = 3 * p; ei[p] = 3 * p + 1; ni[p] = 3 * p + 2; }
    } else {
        for (int p = 0; p < 3; p++) { xi[p] = p; ei[p] = 3 + p; ni[p] = 6 + p; }
    }
    const float* x[3]; const int* edge[3]; const int* nexus[3];
    for (int p = 0; p < 3; p++) {
        x[p] = (const float*)d_in[xi[p]];
        edge[p] = (const int*)d_in[ei[p]];
        nexus[p] = (const int*)d_in[ni[p]];
    }
    const float* W_enc  = (const float*)d_in[9];
    const float* b_enc  = (const float*)d_in[10];
    const float* W_msg1 = (const float*)d_in[11];
    const float* b_msg1 = (const float*)d_in[12];
    const float* W_msg2 = (const float*)d_in[13];
    const float* b_msg2 = (const float*)d_in[14];
    const float* W_upd  = (const float*)d_in[15];
    const float* b_upd  = (const float*)d_in[16];
    const float* W_sp   = (const float*)d_in[17];
    const float* b_sp   = (const float*)d_in[18];
    const float* W_nx   = (const float*)d_in[19];
    const float* b_nx   = (const float*)d_in[20];
    const float* W_sem  = (const float*)d_in[21];
    const float* b_sem  = (const float*)d_in[22];

    float *pwcomb, *pb2c; int* pdeg;
    __half *ph16, *pA, *pB, *pmr, *pspsum, *psp, *pback;
    cudaGetSymbolAddress((void**)&ph16, g_h16);
    cudaGetSymbolAddress((void**)&pA, g_A);
    cudaGetSymbolAddress((void**)&pB, g_B);
    cudaGetSymbolAddress((void**)&pmr, g_mr);
    cudaGetSymbolAddress((void**)&pspsum, g_spsum);
    cudaGetSymbolAddress((void**)&psp, g_sp);
    cudaGetSymbolAddress((void**)&pback, g_back);
    cudaGetSymbolAddress((void**)&pwcomb, g_wcomb);
    cudaGetSymbolAddress((void**)&pb2c, g_b2c);
    cudaGetSymbolAddress((void**)&pdeg, g_deg);

    cudaFuncSetAttribute(gemm_mma, cudaFuncAttributeMaxDynamicSharedMemorySize, SM_TOTAL);
    cudaFuncSetAttribute(gemm_dual, cudaFuncAttributeMaxDynamicSharedMemorySize, DU_TOTAL);

    __half* h16_0 = ph16;
    __half* h16_1 = ph16 + (size_t)3 * PSTRIDE;

    const int T = 256;
    dim3 gG3((NHIT + 127) / 128, 3);
    dim3 gG1((NSP + 127) / 128, 1);
    dim3 gH3((NHIT * 16 + T - 1) / T, 3);   // half-warp-per-node gathers
    int gH1 = (NSP * 16 + T - 1) / T;
    dim3 gW3((NHIT * 32 + T - 1) / T, 3);   // decoder (warp per node)
    dim3 gE((NHIT * HD + T - 1) / T, 3);

    // --- CSR build ---
    zero_counts<<<(NHIT + T - 1) / T, T>>>();
    dim3 gCnt((NEDGE + T - 1) / T, 3);
    count_all<<<gCnt, T>>>(edge[0], edge[1], edge[2], nexus[0], nexus[1], nexus[2]);
    scan_excl_all<<<9, 1024>>>();
    fill_all<<<gCnt, T>>>(edge[0], edge[1], edge[2], nexus[0], nexus[1], nexus[2]);

    // --- weight combine + prep (0=W1top 1=W1bot 2=WupdT 3=comb 4=Wsp 5=WnxT 6=WnxB) ---
    combine_w<<<129, 128>>>(W_msg2, W_upd + 128 * 128, b_msg2);
    prep_w<<<224, 256>>>(W_msg1, W_msg1 + 128 * 128, W_upd, pwcomb,
                         W_sp, W_nx, W_nx + 128 * 128);

    // --- encoder ---
    encoder_k<<<gE, T>>>(x[0], x[1], x[2], W_enc, b_enc, h16_0);

    for (int it = 0; it < 3; it++) {
        gemm_dual<<<gG3, T, DU_TOTAL>>>(h16_0, PSTRIDE, 0, 1, pA, pB, NHIT);
        planar_agg<<<gH3, T>>>(b_msg1);
        gemm_mma<<<gG3, T, SM_TOTAL>>>(h16_0, pmr, PSTRIDE, 2, 2, b_upd, pb2c,
                                       pdeg, NHIT, h16_0, h16_1, NHIT, EPI_RESRELU_DEG);
        nexus_fwd<<<gH1, T>>>(h16_1);
        gemm_mma<<<gG1, T, SM_TOTAL>>>(pspsum, nullptr, 0, 4, 1, b_sp, nullptr,
                                       nullptr, 0, nullptr, psp, NSP, EPI_RELU);
        nexus_back<<<gH3, T>>>();
        gemm_mma<<<gG3, T, SM_TOTAL>>>(h16_1, pback, PSTRIDE, 5, 2, b_nx, nullptr,
                                       nullptr, 0, h16_1, h16_0, NHIT, EPI_RESRELU);
    }

    decoder_k<<<gW3, T>>>(h16_0, W_sem, b_sem, (float*)d_out);
}